// round 7
// baseline (speedup 1.0000x reference)
#include <cuda_runtime.h>
#include <math.h>

#define NWAY 5
#define BB 4
#define CC 64
#define HWN 25
#define MS 125      // K_SHOT * h * w
#define MU 2500     // u * h * w
#define QQ 75
#define COLS 625    // NWAY * MS
#define MTOT 2625   // MS + MU
#define COLP 640    // padded cols for transposed support
#define MUP 2560    // padded m for transposed unlabeled
#define QROWS 1875  // 75 q * 25 rows (packed)
#define QROWP 1920  // padded to 15*128
#define CATP 2688   // padded cat columns (21*128)

// ---------------- scratch (static device allocations only) ----------------
__device__ float g_sup_t[BB*CC*COLP];            // [b][c][col] transposed support (pad zeroed)
__device__ float g_unl_t[BB*CC*MUP];             // [b][c][m]   transposed unlabeled (pad zeroed)
__device__ float g_unl_n[BB*MU*CC];              // [b][m][c]   row-major normalized unlabeled
__device__ float g_q_t[BB*CC*QROWP];             // [b][c][q*25+mq] transposed query (pads zero)
__device__ float g_cat_t[BB*NWAY*CC*CATP];       // [bw][c][j] = [sup(125) | compacted unl(cw)]
__device__ unsigned long long g_rowbest[BB*MU];  // per (b,m): packed (val,col) argmax
__device__ unsigned long long g_colbest[BB*COLS];// per (b,col): packed (val,m) argmax
__device__ unsigned long long g_rowq[BB*QROWP*NWAY]; // per (b,row,w): packed best over cols
__device__ int g_sel[BB*NWAY*MU];                // compacted m-indices per (b,way)
__device__ int g_count[BB*NWAY];
__device__ int g_L[1];

// monotone float ordering map (handles negatives exactly)
__device__ __forceinline__ unsigned fmap(float f){
    unsigned b=__float_as_uint(f);
    return (b&0x80000000u)? ~b : (b|0x80000000u);
}
__device__ __forceinline__ float funmap(unsigned u){
    return (u&0x80000000u)? __uint_as_float(u^0x80000000u) : __uint_as_float(~u);
}
// max-value, min-index-on-tie key (matches jnp first-occurrence argmax)
__device__ __forceinline__ unsigned long long packkey(float v, unsigned idx){
    return (((unsigned long long)fmap(v))<<32) | (unsigned long long)(0xFFFFFFFFu - idx);
}
// packed 2xFP32 FMA (Blackwell f32x2)
__device__ __forceinline__ void fma2(unsigned long long& acc, unsigned long long a, unsigned long long b){
    asm("fma.rn.f32x2 %0, %1, %2, %0;" : "+l"(acc) : "l"(a), "l"(b));
}
__device__ __forceinline__ unsigned long long splat2(float x){
    unsigned long long r;
    asm("mov.b64 %0, {%1, %1};" : "=l"(r) : "r"(__float_as_uint(x)));
    return r;
}
__device__ __forceinline__ void unpack2(unsigned long long v, float& lo, float& hi){
    unsigned a,b;
    asm("mov.b64 {%0, %1}, %2;" : "=r"(a), "=r"(b) : "l"(v));
    lo=__uint_as_float(a); hi=__uint_as_float(b);
}

// ---------------- K0: prep = init + all normalizations ----------------
__global__ void __launch_bounds__(256) k_prep(const float* __restrict__ sup,
                                              const float* __restrict__ unl,
                                              const float* __restrict__ qx,
                                              float* __restrict__ out, int out_size){
    int s = blockIdx.x;
    int tid = threadIdx.x;
    if (s >= 800){
        int i = (s-800)*256 + tid;
        const int stride = 16*256;
        for (int t=i;t<BB*MU;t+=stride) g_rowbest[t]=0ULL;
        for (int t=i;t<BB*COLS;t+=stride) g_colbest[t]=0ULL;
        for (int t=i;t<BB*QROWP*NWAY;t+=stride) g_rowq[t]=0ULL;
        for (int t=i;t<BB*CC*(COLP-COLS);t+=stride){
            int bc=t/(COLP-COLS), p=t%(COLP-COLS);
            g_sup_t[(size_t)bc*COLP+COLS+p]=0.f;
        }
        for (int t=i;t<BB*CC*(MUP-MU);t+=stride){
            int bc=t/(MUP-MU), p=t%(MUP-MU);
            g_unl_t[(size_t)bc*MUP+MU+p]=0.f;
        }
        // pad rows 1875..1919 of g_q_t
        for (int t=i;t<BB*CC*(QROWP-QROWS);t+=stride){
            int bc=t/(QROWP-QROWS), p=t%(QROWP-QROWS);
            g_q_t[(size_t)bc*QROWP+QROWS+p]=0.f;
        }
        if (i==0) g_L[0]=0;
        for (int t=i;t<out_size;t+=stride) out[t]=0.f;
        return;
    }
    __shared__ __align__(16) float tile[1600];
    __shared__ float inv[HWN];
    const float* in;
    if (s<100)      in = sup + (size_t)s*1600;
    else if (s<500) in = unl + (size_t)(s-100)*1600;
    else            in = qx  + (size_t)(s-500)*1600;
    {
        const float4* in4=(const float4*)in;
        float4* t4=(float4*)tile;
        for (int t=tid;t<400;t+=256) t4[t]=in4[t];
    }
    __syncthreads();
    if (tid<HWN){
        float a=0.f;
        for (int c=0;c<CC;++c){ float v=tile[c*HWN+tid]; a=fmaf(v,v,a); }
        inv[tid]=1.0f/fmaxf(sqrtf(a),1e-12f);
    }
    __syncthreads();
    if (s<100){
        int b=s/25, sk=s%25, w=sk/5, k=sk%5;
        int colbase=w*MS+k*25;
        float* outt=g_sup_t+(size_t)b*CC*COLP+colbase;
        float* outc=g_cat_t+(size_t)(b*NWAY+w)*CC*CATP + k*25;
        for (int o=tid;o<1600;o+=256){
            int c=o/HWN,hw=o%HWN;
            float v=tile[o]*inv[hw];
            outt[(size_t)c*COLP+hw]=v;
            outc[(size_t)c*CATP+hw]=v;
        }
    } else if (s<500){
        int t2=s-100; int b=t2/100,u=t2%100;
        float* outt=g_unl_t+(size_t)b*CC*MUP+u*25;
        float* outp=g_unl_n+(size_t)(b*MU+u*25)*CC;
        for (int o=tid;o<1600;o+=256){ int c=o/HWN,hw=o%HWN; outt[(size_t)c*MUP+hw]=tile[o]*inv[hw]; }
        for (int o=tid;o<1600;o+=256){ int hw=o>>6,c=o&63; outp[o]=tile[c*HWN+hw]*inv[hw]; }
    } else {
        int t2=s-500; int b=t2/QQ, q=t2%QQ;
        float* outt=g_q_t+(size_t)b*CC*QROWP + q*25;
        for (int o=tid;o<1600;o+=256){ int c=o/HWN,hw=o%HWN; outt[(size_t)c*QROWP+hw]=tile[o]*inv[hw]; }
    }
}

// ---------------- K1: u2s GEMM (f32x2) + packed row/col argmax ----------------
__global__ void __launch_bounds__(128,3) k_u2s(){
    __shared__ float4 s4[2048];                  // [c][32 f4] = 128 cols (32KB)
    __shared__ float4 u4[2048];                  // [c][32 f4] = 128 m   (32KB)
    __shared__ unsigned long long sm_col[128];
    int mt=blockIdx.x, cp=blockIdx.y, b=blockIdx.z;
    int tid=threadIdx.x, lane=tid&31;
    int ci=tid&7, mi=tid>>3;

    const float4* gs4=(const float4*)g_sup_t + (size_t)b*(CC*COLP/4) + cp*32;
    #pragma unroll
    for (int t=0;t<16;++t){
        int idx=tid+t*128; int c=idx>>5, x=idx&31;
        s4[idx]=gs4[(size_t)c*(COLP/4)+x];
    }
    const float4* gu4=(const float4*)g_unl_t + (size_t)b*(CC*MUP/4) + mt*32;
    #pragma unroll
    for (int t=0;t<16;++t){
        int idx=tid+t*128; int c=idx>>5, x=idx&31;
        u4[idx]=gu4[(size_t)c*(MUP/4)+x];
    }
    sm_col[tid]=0ULL;
    __syncthreads();

    unsigned long long rk[8];
    #pragma unroll
    for (int sdx=0;sdx<8;++sdx) rk[sdx]=0ULL;

    #pragma unroll 1
    for (int h=0; h<2; ++h){
        unsigned long long acc[8][4];
        #pragma unroll
        for (int j=0;j<8;++j)
            #pragma unroll
            for (int k2=0;k2<4;++k2) acc[j][k2]=0ULL;

        #pragma unroll 2
        for (int c=0;c<64;++c){
            float4 a0=s4[c*32+h*16+ci];
            float4 a1=s4[c*32+h*16+8+ci];
            ulonglong2 bb0=*(const ulonglong2*)&u4[c*32+mi];
            ulonglong2 bb1=*(const ulonglong2*)&u4[c*32+16+mi];
            unsigned long long pb0=bb0.x, pb1=bb0.y, pb2=bb1.x, pb3=bb1.y;
            float av[8]={a0.x,a0.y,a0.z,a0.w,a1.x,a1.y,a1.z,a1.w};
            #pragma unroll
            for (int j=0;j<8;++j){
                unsigned long long sa=splat2(av[j]);
                fma2(acc[j][0],sa,pb0);
                fma2(acc[j][1],sa,pb1);
                fma2(acc[j][2],sa,pb2);
                fma2(acc[j][3],sa,pb3);
            }
        }
        #pragma unroll
        for (int j=0;j<8;++j){
            int colj = cp*128 + h*64 + ((j<4)? ci*4+j : 32+ci*4+(j-4));
            bool vc = colj < COLS;
            unsigned long long ck=0ULL;
            #pragma unroll
            for (int k2=0;k2<4;++k2){
                float lo,hi; unpack2(acc[j][k2],lo,hi);
                int mloc = (k2<2)? mi*4+2*k2 : 64+mi*4+2*(k2-2);
                int mglo = mt*128+mloc, mghi = mglo+1;
                if (vc){
                    unsigned long long kl=packkey(lo,(unsigned)colj);
                    unsigned long long kh=packkey(hi,(unsigned)colj);
                    if (kl>rk[2*k2])   rk[2*k2]=kl;
                    if (kh>rk[2*k2+1]) rk[2*k2+1]=kh;
                    if (mglo<MU){ unsigned long long c1=packkey(lo,(unsigned)mglo); if (c1>ck) ck=c1; }
                    if (mghi<MU){ unsigned long long c2=packkey(hi,(unsigned)mghi); if (c2>ck) ck=c2; }
                }
            }
            #pragma unroll
            for (int off=8;off<=16;off<<=1){
                unsigned long long o=__shfl_xor_sync(0xffffffffu,ck,off);
                if (o>ck) ck=o;
            }
            if (lane<8 && ck){
                int local = h*64 + ((j<4)? lane*4+j : 32+lane*4+(j-4));
                atomicMax(&sm_col[local], ck);
            }
        }
    }
    #pragma unroll
    for (int sdx=0;sdx<8;++sdx){
        unsigned long long v=rk[sdx];
        #pragma unroll
        for (int off=1;off<=4;off<<=1){
            unsigned long long o=__shfl_xor_sync(0xffffffffu,v,off);
            if (o>v) v=o;
        }
        if ((lane&7)==0 && v){
            int mloc = (sdx<4)? mi*4+sdx : 64+mi*4+(sdx-4);
            int mg = mt*128+mloc;
            if (mg<MU) atomicMax(&g_rowbest[(size_t)b*MU+mg], v);
        }
    }
    __syncthreads();
    if ((cp*128+tid)<COLS && sm_col[tid])
        atomicMax(&g_colbest[(size_t)b*COLS+cp*128+tid], sm_col[tid]);
}

// ---------------- K2: umask + stable stream compaction + L ----------------
__global__ void k_compact(){
    int bw = blockIdx.x; int b = bw/NWAY, w = bw%NWAY;
    int tid = threadIdx.x, lane = tid&31, wid = tid>>5;
    __shared__ int wsum[8], woff[8], sbase;
    if (tid==0) sbase=0;
    __syncthreads();
    for (int chunk=0; chunk<10; ++chunk){
        int m = chunk*256 + tid;
        bool flag = false;
        if (m < MU){
            unsigned long long rb = g_rowbest[b*MU+m];
            unsigned col = 0xFFFFFFFFu - (unsigned)(rb & 0xFFFFFFFFu);
            if ((int)(col/MS) == w){
                unsigned long long cb = g_colbest[b*COLS+col];
                unsigned mm = 0xFFFFFFFFu - (unsigned)(cb & 0xFFFFFFFFu);
                flag = (mm == (unsigned)m);
            }
        }
        unsigned bal = __ballot_sync(0xffffffffu, flag);
        if (lane==0) wsum[wid] = __popc(bal);
        __syncthreads();
        if (tid==0){
            int run=sbase;
            for (int i=0;i<8;++i){ woff[i]=run; run+=wsum[i]; }
            sbase=run;
        }
        __syncthreads();
        if (flag){
            int pos = woff[wid] + __popc(bal & ((1u<<lane)-1u));
            g_sel[(b*NWAY+w)*MU + pos] = m;
        }
        __syncthreads();
    }
    if (tid==0){
        g_count[b*NWAY+w] = sbase;
        atomicMax(&g_L[0], sbase);
    }
}

// ---------------- K3: inverted gather — coalesced reads, scattered stores ---
// warp handles 8 compacted columns; lanes cover the 64 channels via float2.
__global__ void __launch_bounds__(256) k_gather(){
    int bw = blockIdx.x, jt = blockIdx.y;
    int b = bw/NWAY;
    int cw = g_count[bw];
    int tid=threadIdx.x, lane=tid&31, wp=tid>>5;
    int j0 = jt*64 + wp*8;
    if (j0 >= cw) return;
    const int* __restrict__ sel = g_sel + (size_t)bw*MU;
    float* __restrict__ cat = g_cat_t + (size_t)bw*CC*CATP + MS;
    #pragma unroll
    for (int t=0;t<8;++t){
        int j=j0+t;
        if (j<cw){
            int m = __ldg(&sel[j]);  // uniform per warp -> broadcast
            const float2* src = (const float2*)(g_unl_n + (size_t)(b*MU+m)*CC);
            float2 v = src[lane];
            cat[(size_t)(2*lane)*CATP + j]   = v.x;
            cat[(size_t)(2*lane+1)*CATP + j] = v.y;
        }
    }
}

// ---------------- K4: query GEMM (f32x2) + row-best epilogue ----------------
__global__ void __launch_bounds__(128,3) k_qsim(){
    int ct=blockIdx.x, qt=blockIdx.y, bw=blockIdx.z;
    int b=bw/NWAY, w=bw%NWAY;
    int cw=g_count[bw]; int wl=MS+cw;
    if (ct*128 >= wl) return;
    __shared__ float4 a4[2048];                 // q-rows: [c][32 f4] = 128 rows (32KB)
    __shared__ float4 v4[2048];                 // cols:   [c][32 f4] = 128 cols (32KB)
    int tid=threadIdx.x, lane=tid&31;
    int ci=tid&7, mi=tid>>3;

    const float4* ga=(const float4*)g_q_t + (size_t)b*(CC*QROWP/4) + qt*32;
    #pragma unroll
    for (int t=0;t<16;++t){
        int idx=tid+t*128; int c=idx>>5, x=idx&31;
        a4[idx]=ga[(size_t)c*(QROWP/4)+x];
    }
    const float4* gv=(const float4*)g_cat_t + (size_t)bw*(CC*CATP/4) + ct*32;
    #pragma unroll
    for (int t=0;t<16;++t){
        int idx=tid+t*128; int c=idx>>5, x=idx&31;
        v4[idx]=gv[(size_t)c*(CATP/4)+x];
    }
    __syncthreads();

    unsigned long long rk[8];
    #pragma unroll
    for (int sdx=0;sdx<8;++sdx) rk[sdx]=0ULL;

    #pragma unroll 1
    for (int h=0; h<2; ++h){
        unsigned long long acc[8][4];
        #pragma unroll
        for (int j=0;j<8;++j)
            #pragma unroll
            for (int k2=0;k2<4;++k2) acc[j][k2]=0ULL;

        #pragma unroll 2
        for (int c=0;c<64;++c){
            float4 a0=v4[c*32+h*16+ci];
            float4 a1=v4[c*32+h*16+8+ci];
            ulonglong2 bb0=*(const ulonglong2*)&a4[c*32+mi];
            ulonglong2 bb1=*(const ulonglong2*)&a4[c*32+16+mi];
            unsigned long long pb0=bb0.x, pb1=bb0.y, pb2=bb1.x, pb3=bb1.y;
            float av[8]={a0.x,a0.y,a0.z,a0.w,a1.x,a1.y,a1.z,a1.w};
            #pragma unroll
            for (int j=0;j<8;++j){
                unsigned long long sa=splat2(av[j]);
                fma2(acc[j][0],sa,pb0);
                fma2(acc[j][1],sa,pb1);
                fma2(acc[j][2],sa,pb2);
                fma2(acc[j][3],sa,pb3);
            }
        }
        #pragma unroll
        for (int j=0;j<8;++j){
            int coll = h*64 + ((j<4)? ci*4+j : 32+ci*4+(j-4));
            int jg = ct*128 + coll;
            if (jg < wl){
                unsigned gcol = (unsigned)(w*MTOT + jg);
                #pragma unroll
                for (int k2=0;k2<4;++k2){
                    float lo,hi; unpack2(acc[j][k2],lo,hi);
                    unsigned long long kl=packkey(lo,gcol);
                    unsigned long long kh=packkey(hi,gcol);
                    if (kl>rk[2*k2])   rk[2*k2]=kl;
                    if (kh>rk[2*k2+1]) rk[2*k2+1]=kh;
                }
            }
        }
    }
    #pragma unroll
    for (int sdx=0;sdx<8;++sdx){
        unsigned long long v=rk[sdx];
        #pragma unroll
        for (int off=1;off<=4;off<<=1){
            unsigned long long o=__shfl_xor_sync(0xffffffffu,v,off);
            if (o>v) v=o;
        }
        if ((lane&7)==0 && v){
            int mloc = (sdx<4)? mi*4+sdx : 64+mi*4+(sdx-4);
            int r = qt*128+mloc;
            if (r<QROWS)
                atomicMax(&g_rowq[((size_t)b*QROWP + r)*NWAY + w], v);
        }
    }
}

// ---------------- K5: finish = recompute col-argmax + mutual mask + CE ------
__global__ void __launch_bounds__(256) k_fin(const int* __restrict__ qy,
                                             float* __restrict__ out){
    int q=blockIdx.x, b=blockIdx.y;
    int tid=threadIdx.x, lane=tid&31, wp=tid>>5;
    __shared__ float rmx_s[NWAY][32];
    __shared__ unsigned gcol_s[32];
    __shared__ float mask_s[32];
    __shared__ int cnt_s[NWAY+1];
    if (tid<NWAY) cnt_s[tid]=g_count[b*NWAY+tid];
    if (tid==NWAY) cnt_s[NWAY]=g_L[0];
    if (tid<32) mask_s[tid]=0.f;
    __syncthreads();
    // stage 1: per-row (mq) way-maxes and global best column
    if (wp==0 && lane<HWN){
        unsigned long long qb=0ULL;
        #pragma unroll
        for (int w=0;w<NWAY;++w){
            unsigned long long r = g_rowq[((size_t)b*QROWP + q*25 + lane)*NWAY + w];
            int cww=cnt_s[w];
            if (cww < cnt_s[NWAY]){
                // first all-zero pad column of this way: raw cos = 0.0, col id MS+cww
                unsigned long long pk = packkey(0.0f,(unsigned)(w*MTOT+MS+cww));
                if (pk>r) r=pk;
            }
            rmx_s[w][lane]=fmaf(funmap((unsigned)(r>>32)),0.5f,0.5f);
            if (r>qb) qb=r;
        }
        gcol_s[lane]=0xFFFFFFFFu - (unsigned)(qb & 0xFFFFFFFFu);
    }
    __syncthreads();
    // stage 2: per winning column, recompute argmax over mq (bitwise-identical chain)
    for (int t=wp; t<HWN; t+=8){
        unsigned gcol=gcol_s[t];
        int w_=(int)(gcol/MTOT), j_=(int)(gcol%MTOT);
        int amq=0;
        if (j_ < MS + cnt_s[w_]){
            float acc=0.f;
            const float* qp = g_q_t + (size_t)b*CC*QROWP + q*25 + lane;
            const float* cp = g_cat_t + (size_t)(b*NWAY+w_)*CC*CATP + j_;
            if (lane<HWN){
                #pragma unroll
                for (int c=0;c<CC;++c)
                    acc=fmaf(qp[(size_t)c*QROWP], cp[(size_t)c*CATP], acc);
            }
            unsigned long long k = (lane<HWN)? packkey(acc,(unsigned)lane) : 0ULL;
            #pragma unroll
            for (int off=16;off>=1;off>>=1){
                unsigned long long o=__shfl_xor_sync(0xffffffffu,k,off);
                if (o>k) k=o;
            }
            amq = (int)(0xFFFFFFFFu - (unsigned)(k & 0xFFFFFFFFu));
        }
        if (lane==0) mask_s[t] = (amq==t)?1.f:0.f;
    }
    __syncthreads();
    // stage 3: qv + cross-entropy
    if (wp==0){
        float qv[NWAY];
        #pragma unroll
        for (int w=0;w<NWAY;++w){
            float t = (lane<HWN) ? rmx_s[w][lane]*mask_s[lane] : 0.f;
            #pragma unroll
            for (int off=16;off>=1;off>>=1) t += __shfl_xor_sync(0xffffffffu,t,off);
            qv[w]=t;
        }
        if (lane==0){
            int y = qy[b*QQ+q];
            float mx=qv[0];
            #pragma unroll
            for (int w=1;w<NWAY;++w) mx=fmaxf(mx,qv[w]);
            float se=0.f;
            #pragma unroll
            for (int w=0;w<NWAY;++w) se += expf(qv[w]-mx);
            float li = mx + logf(se) - qv[y];
            atomicAdd(out, li*(1.0f/(float)(BB*QQ)));
        }
    }
}

// ---------------- launch ----------------
extern "C" void kernel_launch(void* const* d_in, const int* in_sizes, int n_in,
                              void* d_out, int out_size) {
    const float* sup = nullptr;
    const float* qx  = nullptr;
    const float* ux  = nullptr;
    const int*   qy  = nullptr;
    for (int i=0;i<n_in;++i){
        switch (in_sizes[i]){
            case 160000: sup = (const float*)d_in[i]; break; // support_xf
            case 480000: qx  = (const float*)d_in[i]; break; // query_xf
            case 640000: ux  = (const float*)d_in[i]; break; // unlabeled_xf
            case 300:    qy  = (const int*)d_in[i];   break; // query_y
            default: break;                                  // support_y unused
        }
    }
    float* out = (float*)d_out;
    k_prep<<<816,256>>>(sup, ux, qx, out, out_size);
    k_u2s<<<dim3(20,5,BB),128>>>();
    k_compact<<<BB*NWAY,256>>>();
    k_gather<<<dim3(BB*NWAY,40),256>>>();
    k_qsim<<<dim3(21,15,BB*NWAY),128>>>();
    k_fin<<<dim3(QQ,BB),256>>>(qy, out);
}

// round 8
// speedup vs baseline: 1.0389x; 1.0389x over previous
#include <cuda_runtime.h>
#include <math.h>

#define NWAY 5
#define BB 4
#define CC 64
#define HWN 25
#define MS 125      // K_SHOT * h * w
#define MU 2500     // u * h * w
#define QQ 75
#define COLS 625    // NWAY * MS
#define MTOT 2625   // MS + MU
#define COLP 640    // padded cols for transposed support
#define MUP 2560    // padded m for transposed unlabeled
#define QROWS 1875  // 75 q * 25 rows (packed)
#define QROWP 1920  // padded to 15*128
#define CATP 2688   // padded cat columns (21*128)

// ---------------- scratch (static device allocations only) ----------------
__device__ float g_sup_t[BB*CC*COLP];            // [b][c][col] transposed support (pad zeroed)
__device__ float g_unl_t[BB*CC*MUP];             // [b][c][m]   transposed unlabeled (pad zeroed)
__device__ float g_unl_n[BB*MU*CC];              // [b][m][c]   row-major normalized unlabeled
__device__ float g_q_t[BB*CC*QROWP];             // [b][c][q*25+mq] transposed query (pads zero)
__device__ float g_cat_t[BB*NWAY*CC*CATP];       // [bw][c][j] = [sup(125) | compacted unl(cw)]
__device__ unsigned long long g_rowbest[BB*MU];  // per (b,m): packed (val,col) argmax
__device__ unsigned long long g_colbest[BB*COLS];// per (b,col): packed (val,m) argmax
__device__ unsigned long long g_rowq[BB*QROWP*NWAY]; // per (b,row,w): packed best over cols
__device__ int g_sel[BB*NWAY*MU];                // compacted m-indices per (b,way)
__device__ int g_count[BB*NWAY];
__device__ int g_L[1];

// monotone float ordering map (handles negatives exactly)
__device__ __forceinline__ unsigned fmap(float f){
    unsigned b=__float_as_uint(f);
    return (b&0x80000000u)? ~b : (b|0x80000000u);
}
__device__ __forceinline__ float funmap(unsigned u){
    return (u&0x80000000u)? __uint_as_float(u^0x80000000u) : __uint_as_float(~u);
}
// max-value, min-index-on-tie key (matches jnp first-occurrence argmax)
__device__ __forceinline__ unsigned long long packkey(float v, unsigned idx){
    return (((unsigned long long)fmap(v))<<32) | (unsigned long long)(0xFFFFFFFFu - idx);
}
// packed 2xFP32 FMA (Blackwell f32x2)
__device__ __forceinline__ void fma2(unsigned long long& acc, unsigned long long a, unsigned long long b){
    asm("fma.rn.f32x2 %0, %1, %2, %0;" : "+l"(acc) : "l"(a), "l"(b));
}
__device__ __forceinline__ unsigned long long splat2(float x){
    unsigned long long r;
    asm("mov.b64 %0, {%1, %1};" : "=l"(r) : "r"(__float_as_uint(x)));
    return r;
}
__device__ __forceinline__ void unpack2(unsigned long long v, float& lo, float& hi){
    unsigned a,b;
    asm("mov.b64 {%0, %1}, %2;" : "=r"(a), "=r"(b) : "l"(v));
    lo=__uint_as_float(a); hi=__uint_as_float(b);
}

// ---------------- K0: prep = init + all normalizations ----------------
__global__ void __launch_bounds__(256) k_prep(const float* __restrict__ sup,
                                              const float* __restrict__ unl,
                                              const float* __restrict__ qx,
                                              float* __restrict__ out, int out_size){
    int s = blockIdx.x;
    int tid = threadIdx.x;
    if (s >= 800){
        int i = (s-800)*256 + tid;
        const int stride = 16*256;
        for (int t=i;t<BB*MU;t+=stride) g_rowbest[t]=0ULL;
        for (int t=i;t<BB*COLS;t+=stride) g_colbest[t]=0ULL;
        for (int t=i;t<BB*QROWP*NWAY;t+=stride) g_rowq[t]=0ULL;
        for (int t=i;t<BB*CC*(COLP-COLS);t+=stride){
            int bc=t/(COLP-COLS), p=t%(COLP-COLS);
            g_sup_t[(size_t)bc*COLP+COLS+p]=0.f;
        }
        for (int t=i;t<BB*CC*(MUP-MU);t+=stride){
            int bc=t/(MUP-MU), p=t%(MUP-MU);
            g_unl_t[(size_t)bc*MUP+MU+p]=0.f;
        }
        // pad rows 1875..1919 of g_q_t
        for (int t=i;t<BB*CC*(QROWP-QROWS);t+=stride){
            int bc=t/(QROWP-QROWS), p=t%(QROWP-QROWS);
            g_q_t[(size_t)bc*QROWP+QROWS+p]=0.f;
        }
        if (i==0) g_L[0]=0;
        for (int t=i;t<out_size;t+=stride) out[t]=0.f;
        return;
    }
    __shared__ __align__(16) float tile[1600];
    __shared__ float inv[HWN];
    const float* in;
    if (s<100)      in = sup + (size_t)s*1600;
    else if (s<500) in = unl + (size_t)(s-100)*1600;
    else            in = qx  + (size_t)(s-500)*1600;
    {
        const float4* in4=(const float4*)in;
        float4* t4=(float4*)tile;
        for (int t=tid;t<400;t+=256) t4[t]=in4[t];
    }
    __syncthreads();
    if (tid<HWN){
        float a=0.f;
        for (int c=0;c<CC;++c){ float v=tile[c*HWN+tid]; a=fmaf(v,v,a); }
        inv[tid]=1.0f/fmaxf(sqrtf(a),1e-12f);
    }
    __syncthreads();
    if (s<100){
        int b=s/25, sk=s%25, w=sk/5, k=sk%5;
        int colbase=w*MS+k*25;
        float* outt=g_sup_t+(size_t)b*CC*COLP+colbase;
        float* outc=g_cat_t+(size_t)(b*NWAY+w)*CC*CATP + k*25;
        for (int o=tid;o<1600;o+=256){
            int c=o/HWN,hw=o%HWN;
            float v=tile[o]*inv[hw];
            outt[(size_t)c*COLP+hw]=v;
            outc[(size_t)c*CATP+hw]=v;
        }
    } else if (s<500){
        int t2=s-100; int b=t2/100,u=t2%100;
        float* outt=g_unl_t+(size_t)b*CC*MUP+u*25;
        float* outp=g_unl_n+(size_t)(b*MU+u*25)*CC;
        for (int o=tid;o<1600;o+=256){ int c=o/HWN,hw=o%HWN; outt[(size_t)c*MUP+hw]=tile[o]*inv[hw]; }
        for (int o=tid;o<1600;o+=256){ int hw=o>>6,c=o&63; outp[o]=tile[c*HWN+hw]*inv[hw]; }
    } else {
        int t2=s-500; int b=t2/QQ, q=t2%QQ;
        float* outt=g_q_t+(size_t)b*CC*QROWP + q*25;
        for (int o=tid;o<1600;o+=256){ int c=o/HWN,hw=o%HWN; outt[(size_t)c*QROWP+hw]=tile[o]*inv[hw]; }
    }
}

// ---------------- K1: u2s GEMM (f32x2) + packed row/col argmax ----------------
__global__ void __launch_bounds__(128,3) k_u2s(){
    __shared__ float4 s4[2048];                  // [c][32 f4] = 128 cols (32KB)
    __shared__ float4 u4[2048];                  // [c][32 f4] = 128 m   (32KB)
    __shared__ unsigned long long sm_col[128];
    int mt=blockIdx.x, cp=blockIdx.y, b=blockIdx.z;
    int tid=threadIdx.x, lane=tid&31;
    int ci=tid&7, mi=tid>>3;

    const float4* gs4=(const float4*)g_sup_t + (size_t)b*(CC*COLP/4) + cp*32;
    #pragma unroll
    for (int t=0;t<16;++t){
        int idx=tid+t*128; int c=idx>>5, x=idx&31;
        s4[idx]=gs4[(size_t)c*(COLP/4)+x];
    }
    const float4* gu4=(const float4*)g_unl_t + (size_t)b*(CC*MUP/4) + mt*32;
    #pragma unroll
    for (int t=0;t<16;++t){
        int idx=tid+t*128; int c=idx>>5, x=idx&31;
        u4[idx]=gu4[(size_t)c*(MUP/4)+x];
    }
    sm_col[tid]=0ULL;
    __syncthreads();

    unsigned long long rk[8];
    #pragma unroll
    for (int sdx=0;sdx<8;++sdx) rk[sdx]=0ULL;

    #pragma unroll 1
    for (int h=0; h<2; ++h){
        unsigned long long acc[8][4];
        #pragma unroll
        for (int j=0;j<8;++j)
            #pragma unroll
            for (int k2=0;k2<4;++k2) acc[j][k2]=0ULL;

        #pragma unroll 2
        for (int c=0;c<64;++c){
            float4 a0=s4[c*32+h*16+ci];
            float4 a1=s4[c*32+h*16+8+ci];
            ulonglong2 bb0=*(const ulonglong2*)&u4[c*32+mi];
            ulonglong2 bb1=*(const ulonglong2*)&u4[c*32+16+mi];
            unsigned long long pb0=bb0.x, pb1=bb0.y, pb2=bb1.x, pb3=bb1.y;
            float av[8]={a0.x,a0.y,a0.z,a0.w,a1.x,a1.y,a1.z,a1.w};
            #pragma unroll
            for (int j=0;j<8;++j){
                unsigned long long sa=splat2(av[j]);
                fma2(acc[j][0],sa,pb0);
                fma2(acc[j][1],sa,pb1);
                fma2(acc[j][2],sa,pb2);
                fma2(acc[j][3],sa,pb3);
            }
        }
        #pragma unroll
        for (int j=0;j<8;++j){
            int colj = cp*128 + h*64 + ((j<4)? ci*4+j : 32+ci*4+(j-4));
            bool vc = colj < COLS;
            unsigned long long ck=0ULL;
            #pragma unroll
            for (int k2=0;k2<4;++k2){
                float lo,hi; unpack2(acc[j][k2],lo,hi);
                int mloc = (k2<2)? mi*4+2*k2 : 64+mi*4+2*(k2-2);
                int mglo = mt*128+mloc, mghi = mglo+1;
                if (vc){
                    unsigned long long kl=packkey(lo,(unsigned)colj);
                    unsigned long long kh=packkey(hi,(unsigned)colj);
                    if (kl>rk[2*k2])   rk[2*k2]=kl;
                    if (kh>rk[2*k2+1]) rk[2*k2+1]=kh;
                    if (mglo<MU){ unsigned long long c1=packkey(lo,(unsigned)mglo); if (c1>ck) ck=c1; }
                    if (mghi<MU){ unsigned long long c2=packkey(hi,(unsigned)mghi); if (c2>ck) ck=c2; }
                }
            }
            #pragma unroll
            for (int off=8;off<=16;off<<=1){
                unsigned long long o=__shfl_xor_sync(0xffffffffu,ck,off);
                if (o>ck) ck=o;
            }
            if (lane<8 && ck){
                int local = h*64 + ((j<4)? lane*4+j : 32+lane*4+(j-4));
                atomicMax(&sm_col[local], ck);
            }
        }
    }
    #pragma unroll
    for (int sdx=0;sdx<8;++sdx){
        unsigned long long v=rk[sdx];
        #pragma unroll
        for (int off=1;off<=4;off<<=1){
            unsigned long long o=__shfl_xor_sync(0xffffffffu,v,off);
            if (o>v) v=o;
        }
        if ((lane&7)==0 && v){
            int mloc = (sdx<4)? mi*4+sdx : 64+mi*4+(sdx-4);
            int mg = mt*128+mloc;
            if (mg<MU) atomicMax(&g_rowbest[(size_t)b*MU+mg], v);
        }
    }
    __syncthreads();
    if ((cp*128+tid)<COLS && sm_col[tid])
        atomicMax(&g_colbest[(size_t)b*COLS+cp*128+tid], sm_col[tid]);
}

// ---------------- K2: umask + stable stream compaction + L ----------------
__global__ void k_compact(){
    int bw = blockIdx.x; int b = bw/NWAY, w = bw%NWAY;
    int tid = threadIdx.x, lane = tid&31, wid = tid>>5;
    __shared__ int wsum[8], woff[8], sbase;
    if (tid==0) sbase=0;
    __syncthreads();
    for (int chunk=0; chunk<10; ++chunk){
        int m = chunk*256 + tid;
        bool flag = false;
        if (m < MU){
            unsigned long long rb = g_rowbest[b*MU+m];
            unsigned col = 0xFFFFFFFFu - (unsigned)(rb & 0xFFFFFFFFu);
            if ((int)(col/MS) == w){
                unsigned long long cb = g_colbest[b*COLS+col];
                unsigned mm = 0xFFFFFFFFu - (unsigned)(cb & 0xFFFFFFFFu);
                flag = (mm == (unsigned)m);
            }
        }
        unsigned bal = __ballot_sync(0xffffffffu, flag);
        if (lane==0) wsum[wid] = __popc(bal);
        __syncthreads();
        if (tid==0){
            int run=sbase;
            for (int i=0;i<8;++i){ woff[i]=run; run+=wsum[i]; }
            sbase=run;
        }
        __syncthreads();
        if (flag){
            int pos = woff[wid] + __popc(bal & ((1u<<lane)-1u));
            g_sel[(b*NWAY+w)*MU + pos] = m;
        }
        __syncthreads();
    }
    if (tid==0){
        g_count[b*NWAY+w] = sbase;
        atomicMax(&g_L[0], sbase);
    }
}

// ---------------- K3: gather via smem transpose — both sides coalesced ------
// Block = (bw, 64-column tile). Warp reads selected rows as float2 (coalesced),
// deposits into smem [c][j]; then all threads write tile rows out contiguous in j.
__global__ void __launch_bounds__(256) k_gather(){
    int bw = blockIdx.x, jt = blockIdx.y;
    int b = bw/NWAY;
    int cw = g_count[bw];
    int jbase = jt*64;
    if (jbase >= cw) return;
    __shared__ float tile[CC][65];
    int tid=threadIdx.x, lane=tid&31, wp=tid>>5;
    int nj = min(64, cw - jbase);
    const int* __restrict__ sel = g_sel + (size_t)bw*MU + jbase;
    for (int t=wp; t<nj; t+=8){
        int m = __ldg(&sel[t]);  // uniform per warp -> broadcast
        const float2* src = (const float2*)(g_unl_n + (size_t)(b*MU+m)*CC);
        float2 v = src[lane];    // 256B contiguous per warp
        tile[2*lane][t]   = v.x;
        tile[2*lane+1][t] = v.y;
    }
    __syncthreads();
    float* __restrict__ cat = g_cat_t + (size_t)bw*CC*CATP + MS + jbase;
    for (int o=tid; o<CC*64; o+=256){
        int c=o>>6, j=o&63;
        if (j<nj) cat[(size_t)c*CATP + j] = tile[c][j];   // coalesced along j
    }
}

// ---------------- K4: query GEMM (f32x2) + row-best epilogue ----------------
__global__ void __launch_bounds__(128,3) k_qsim(){
    int ct=blockIdx.x, qt=blockIdx.y, bw=blockIdx.z;
    int b=bw/NWAY, w=bw%NWAY;
    int cw=g_count[bw]; int wl=MS+cw;
    if (ct*128 >= wl) return;
    __shared__ float4 a4[2048];                 // q-rows: [c][32 f4] = 128 rows (32KB)
    __shared__ float4 v4[2048];                 // cols:   [c][32 f4] = 128 cols (32KB)
    int tid=threadIdx.x, lane=tid&31;
    int ci=tid&7, mi=tid>>3;

    const float4* ga=(const float4*)g_q_t + (size_t)b*(CC*QROWP/4) + qt*32;
    #pragma unroll
    for (int t=0;t<16;++t){
        int idx=tid+t*128; int c=idx>>5, x=idx&31;
        a4[idx]=ga[(size_t)c*(QROWP/4)+x];
    }
    const float4* gv=(const float4*)g_cat_t + (size_t)bw*(CC*CATP/4) + ct*32;
    #pragma unroll
    for (int t=0;t<16;++t){
        int idx=tid+t*128; int c=idx>>5, x=idx&31;
        v4[idx]=gv[(size_t)c*(CATP/4)+x];
    }
    __syncthreads();

    unsigned long long rk[8];
    #pragma unroll
    for (int sdx=0;sdx<8;++sdx) rk[sdx]=0ULL;

    #pragma unroll 1
    for (int h=0; h<2; ++h){
        unsigned long long acc[8][4];
        #pragma unroll
        for (int j=0;j<8;++j)
            #pragma unroll
            for (int k2=0;k2<4;++k2) acc[j][k2]=0ULL;

        #pragma unroll 2
        for (int c=0;c<64;++c){
            float4 a0=v4[c*32+h*16+ci];
            float4 a1=v4[c*32+h*16+8+ci];
            ulonglong2 bb0=*(const ulonglong2*)&a4[c*32+mi];
            ulonglong2 bb1=*(const ulonglong2*)&a4[c*32+16+mi];
            unsigned long long pb0=bb0.x, pb1=bb0.y, pb2=bb1.x, pb3=bb1.y;
            float av[8]={a0.x,a0.y,a0.z,a0.w,a1.x,a1.y,a1.z,a1.w};
            #pragma unroll
            for (int j=0;j<8;++j){
                unsigned long long sa=splat2(av[j]);
                fma2(acc[j][0],sa,pb0);
                fma2(acc[j][1],sa,pb1);
                fma2(acc[j][2],sa,pb2);
                fma2(acc[j][3],sa,pb3);
            }
        }
        #pragma unroll
        for (int j=0;j<8;++j){
            int coll = h*64 + ((j<4)? ci*4+j : 32+ci*4+(j-4));
            int jg = ct*128 + coll;
            if (jg < wl){
                unsigned gcol = (unsigned)(w*MTOT + jg);
                #pragma unroll
                for (int k2=0;k2<4;++k2){
                    float lo,hi; unpack2(acc[j][k2],lo,hi);
                    unsigned long long kl=packkey(lo,gcol);
                    unsigned long long kh=packkey(hi,gcol);
                    if (kl>rk[2*k2])   rk[2*k2]=kl;
                    if (kh>rk[2*k2+1]) rk[2*k2+1]=kh;
                }
            }
        }
    }
    #pragma unroll
    for (int sdx=0;sdx<8;++sdx){
        unsigned long long v=rk[sdx];
        #pragma unroll
        for (int off=1;off<=4;off<<=1){
            unsigned long long o=__shfl_xor_sync(0xffffffffu,v,off);
            if (o>v) v=o;
        }
        if ((lane&7)==0 && v){
            int mloc = (sdx<4)? mi*4+sdx : 64+mi*4+(sdx-4);
            int r = qt*128+mloc;
            if (r<QROWS)
                atomicMax(&g_rowq[((size_t)b*QROWP + r)*NWAY + w], v);
        }
    }
}

// ---------------- K5: finish = recompute col-argmax + mutual mask + CE ------
__global__ void __launch_bounds__(256) k_fin(const int* __restrict__ qy,
                                             float* __restrict__ out){
    int q=blockIdx.x, b=blockIdx.y;
    int tid=threadIdx.x, lane=tid&31, wp=tid>>5;
    __shared__ float rmx_s[NWAY][32];
    __shared__ unsigned gcol_s[32];
    __shared__ float mask_s[32];
    __shared__ int cnt_s[NWAY+1];
    if (tid<NWAY) cnt_s[tid]=g_count[b*NWAY+tid];
    if (tid==NWAY) cnt_s[NWAY]=g_L[0];
    if (tid<32) mask_s[tid]=0.f;
    __syncthreads();
    // stage 1: per-row (mq) way-maxes and global best column
    if (wp==0 && lane<HWN){
        unsigned long long qb=0ULL;
        #pragma unroll
        for (int w=0;w<NWAY;++w){
            unsigned long long r = g_rowq[((size_t)b*QROWP + q*25 + lane)*NWAY + w];
            int cww=cnt_s[w];
            if (cww < cnt_s[NWAY]){
                // first all-zero pad column of this way: raw cos = 0.0, col id MS+cww
                unsigned long long pk = packkey(0.0f,(unsigned)(w*MTOT+MS+cww));
                if (pk>r) r=pk;
            }
            rmx_s[w][lane]=fmaf(funmap((unsigned)(r>>32)),0.5f,0.5f);
            if (r>qb) qb=r;
        }
        gcol_s[lane]=0xFFFFFFFFu - (unsigned)(qb & 0xFFFFFFFFu);
    }
    __syncthreads();
    // stage 2: per winning column, recompute argmax over mq (bitwise-identical chain)
    for (int t=wp; t<HWN; t+=8){
        unsigned gcol=gcol_s[t];
        int w_=(int)(gcol/MTOT), j_=(int)(gcol%MTOT);
        int amq=0;
        if (j_ < MS + cnt_s[w_]){
            float acc=0.f;
            const float* qp = g_q_t + (size_t)b*CC*QROWP + q*25 + lane;
            const float* cp = g_cat_t + (size_t)(b*NWAY+w_)*CC*CATP + j_;
            if (lane<HWN){
                #pragma unroll
                for (int c=0;c<CC;++c)
                    acc=fmaf(qp[(size_t)c*QROWP], cp[(size_t)c*CATP], acc);
            }
            unsigned long long k = (lane<HWN)? packkey(acc,(unsigned)lane) : 0ULL;
            #pragma unroll
            for (int off=16;off>=1;off>>=1){
                unsigned long long o=__shfl_xor_sync(0xffffffffu,k,off);
                if (o>k) k=o;
            }
            amq = (int)(0xFFFFFFFFu - (unsigned)(k & 0xFFFFFFFFu));
        }
        if (lane==0) mask_s[t] = (amq==t)?1.f:0.f;
    }
    __syncthreads();
    // stage 3: qv + cross-entropy
    if (wp==0){
        float qv[NWAY];
        #pragma unroll
        for (int w=0;w<NWAY;++w){
            float t = (lane<HWN) ? rmx_s[w][lane]*mask_s[lane] : 0.f;
            #pragma unroll
            for (int off=16;off>=1;off>>=1) t += __shfl_xor_sync(0xffffffffu,t,off);
            qv[w]=t;
        }
        if (lane==0){
            int y = qy[b*QQ+q];
            float mx=qv[0];
            #pragma unroll
            for (int w=1;w<NWAY;++w) mx=fmaxf(mx,qv[w]);
            float se=0.f;
            #pragma unroll
            for (int w=0;w<NWAY;++w) se += expf(qv[w]-mx);
            float li = mx + logf(se) - qv[y];
            atomicAdd(out, li*(1.0f/(float)(BB*QQ)));
        }
    }
}

// ---------------- launch ----------------
extern "C" void kernel_launch(void* const* d_in, const int* in_sizes, int n_in,
                              void* d_out, int out_size) {
    const float* sup = nullptr;
    const float* qx  = nullptr;
    const float* ux  = nullptr;
    const int*   qy  = nullptr;
    for (int i=0;i<n_in;++i){
        switch (in_sizes[i]){
            case 160000: sup = (const float*)d_in[i]; break; // support_xf
            case 480000: qx  = (const float*)d_in[i]; break; // query_xf
            case 640000: ux  = (const float*)d_in[i]; break; // unlabeled_xf
            case 300:    qy  = (const int*)d_in[i];   break; // query_y
            default: break;                                  // support_y unused
        }
    }
    float* out = (float*)d_out;
    k_prep<<<816,256>>>(sup, ux, qx, out, out_size);
    k_u2s<<<dim3(20,5,BB),128>>>();
    k_compact<<<BB*NWAY,256>>>();
    k_gather<<<dim3(BB*NWAY,40),256>>>();
    k_qsim<<<dim3(21,15,BB*NWAY),128>>>();
    k_fin<<<dim3(QQ,BB),256>>>(qy, out);
}

// round 9
// speedup vs baseline: 1.0580x; 1.0185x over previous
#include <cuda_runtime.h>
#include <math.h>

#define NWAY 5
#define BB 4
#define CC 64
#define HWN 25
#define MS 125      // K_SHOT * h * w
#define MU 2500     // u * h * w
#define QQ 75
#define COLS 625    // NWAY * MS
#define MTOT 2625   // MS + MU
#define COLP 640    // padded cols for transposed support
#define MUP 2560    // padded m for transposed unlabeled
#define QROWS 1875  // 75 q * 25 rows (packed)
#define QROWP 1920  // padded to 15*128
#define CATP 2688   // padded cat columns (21*128)

// ---------------- scratch (static device allocations only) ----------------
__device__ float g_sup_t[BB*CC*COLP];            // [b][c][col] transposed support (pad zeroed)
__device__ float g_unl_t[BB*CC*MUP];             // [b][c][m]   transposed unlabeled (pad zeroed)
__device__ float g_unl_n[BB*MU*CC];              // [b][m][c]   row-major normalized unlabeled
__device__ float g_q_t[BB*CC*QROWP];             // [b][c][q*25+mq] transposed query (pads zero)
__device__ float g_cat_t[BB*NWAY*CC*CATP];       // [bw][c][j] = [sup(125) | compacted unl(cw)]
__device__ unsigned long long g_rowbest[BB*MU];  // per (b,m): packed (val,col) argmax
__device__ unsigned long long g_colbest[BB*COLS];// per (b,col): packed (val,m) argmax
__device__ unsigned long long g_rowq[BB*QROWP*NWAY]; // per (b,row,w): packed best over cols
__device__ int g_count[BB*NWAY];
__device__ int g_L[1];

// monotone float ordering map (handles negatives exactly)
__device__ __forceinline__ unsigned fmap(float f){
    unsigned b=__float_as_uint(f);
    return (b&0x80000000u)? ~b : (b|0x80000000u);
}
__device__ __forceinline__ float funmap(unsigned u){
    return (u&0x80000000u)? __uint_as_float(u^0x80000000u) : __uint_as_float(~u);
}
// max-value, min-index-on-tie key (matches jnp first-occurrence argmax)
__device__ __forceinline__ unsigned long long packkey(float v, unsigned idx){
    return (((unsigned long long)fmap(v))<<32) | (unsigned long long)(0xFFFFFFFFu - idx);
}
// packed 2xFP32 FMA (Blackwell f32x2)
__device__ __forceinline__ void fma2(unsigned long long& acc, unsigned long long a, unsigned long long b){
    asm("fma.rn.f32x2 %0, %1, %2, %0;" : "+l"(acc) : "l"(a), "l"(b));
}
__device__ __forceinline__ unsigned long long splat2(float x){
    unsigned long long r;
    asm("mov.b64 %0, {%1, %1};" : "=l"(r) : "r"(__float_as_uint(x)));
    return r;
}
__device__ __forceinline__ void unpack2(unsigned long long v, float& lo, float& hi){
    unsigned a,b;
    asm("mov.b64 {%0, %1}, %2;" : "=r"(a), "=r"(b) : "l"(v));
    lo=__uint_as_float(a); hi=__uint_as_float(b);
}

// ---------------- K0: prep = init + all normalizations ----------------
__global__ void __launch_bounds__(256) k_prep(const float* __restrict__ sup,
                                              const float* __restrict__ unl,
                                              const float* __restrict__ qx,
                                              float* __restrict__ out, int out_size){
    int s = blockIdx.x;
    int tid = threadIdx.x;
    if (s >= 800){
        int i = (s-800)*256 + tid;
        const int stride = 16*256;
        for (int t=i;t<BB*MU;t+=stride) g_rowbest[t]=0ULL;
        for (int t=i;t<BB*COLS;t+=stride) g_colbest[t]=0ULL;
        for (int t=i;t<BB*QROWP*NWAY;t+=stride) g_rowq[t]=0ULL;
        for (int t=i;t<BB*CC*(COLP-COLS);t+=stride){
            int bc=t/(COLP-COLS), p=t%(COLP-COLS);
            g_sup_t[(size_t)bc*COLP+COLS+p]=0.f;
        }
        for (int t=i;t<BB*CC*(MUP-MU);t+=stride){
            int bc=t/(MUP-MU), p=t%(MUP-MU);
            g_unl_t[(size_t)bc*MUP+MU+p]=0.f;
        }
        // pad rows 1875..1919 of g_q_t
        for (int t=i;t<BB*CC*(QROWP-QROWS);t+=stride){
            int bc=t/(QROWP-QROWS), p=t%(QROWP-QROWS);
            g_q_t[(size_t)bc*QROWP+QROWS+p]=0.f;
        }
        if (i==0) g_L[0]=0;
        for (int t=i;t<out_size;t+=stride) out[t]=0.f;
        return;
    }
    __shared__ __align__(16) float tile[1600];
    __shared__ float inv[HWN];
    const float* in;
    if (s<100)      in = sup + (size_t)s*1600;
    else if (s<500) in = unl + (size_t)(s-100)*1600;
    else            in = qx  + (size_t)(s-500)*1600;
    {
        const float4* in4=(const float4*)in;
        float4* t4=(float4*)tile;
        for (int t=tid;t<400;t+=256) t4[t]=in4[t];
    }
    __syncthreads();
    if (tid<HWN){
        float a=0.f;
        for (int c=0;c<CC;++c){ float v=tile[c*HWN+tid]; a=fmaf(v,v,a); }
        inv[tid]=1.0f/fmaxf(sqrtf(a),1e-12f);
    }
    __syncthreads();
    if (s<100){
        int b=s/25, sk=s%25, w=sk/5, k=sk%5;
        int colbase=w*MS+k*25;
        float* outt=g_sup_t+(size_t)b*CC*COLP+colbase;
        float* outc=g_cat_t+(size_t)(b*NWAY+w)*CC*CATP + k*25;
        for (int o=tid;o<1600;o+=256){
            int c=o/HWN,hw=o%HWN;
            float v=tile[o]*inv[hw];
            outt[(size_t)c*COLP+hw]=v;
            outc[(size_t)c*CATP+hw]=v;
        }
    } else if (s<500){
        int t2=s-100; int b=t2/100,u=t2%100;
        float* outt=g_unl_t+(size_t)b*CC*MUP+u*25;
        float* outp=g_unl_n+(size_t)(b*MU+u*25)*CC;
        for (int o=tid;o<1600;o+=256){ int c=o/HWN,hw=o%HWN; outt[(size_t)c*MUP+hw]=tile[o]*inv[hw]; }
        for (int o=tid;o<1600;o+=256){ int hw=o>>6,c=o&63; outp[o]=tile[c*HWN+hw]*inv[hw]; }
    } else {
        int t2=s-500; int b=t2/QQ, q=t2%QQ;
        float* outt=g_q_t+(size_t)b*CC*QROWP + q*25;
        for (int o=tid;o<1600;o+=256){ int c=o/HWN,hw=o%HWN; outt[(size_t)c*QROWP+hw]=tile[o]*inv[hw]; }
    }
}

// ---------------- K1: u2s GEMM (f32x2) + packed row/col argmax ----------------
__global__ void __launch_bounds__(128,3) k_u2s(){
    __shared__ float4 s4[2048];                  // [c][32 f4] = 128 cols (32KB)
    __shared__ float4 u4[2048];                  // [c][32 f4] = 128 m   (32KB)
    __shared__ unsigned long long sm_col[128];
    int mt=blockIdx.x, cp=blockIdx.y, b=blockIdx.z;
    int tid=threadIdx.x, lane=tid&31;
    int ci=tid&7, mi=tid>>3;

    const float4* gs4=(const float4*)g_sup_t + (size_t)b*(CC*COLP/4) + cp*32;
    #pragma unroll
    for (int t=0;t<16;++t){
        int idx=tid+t*128; int c=idx>>5, x=idx&31;
        s4[idx]=gs4[(size_t)c*(COLP/4)+x];
    }
    const float4* gu4=(const float4*)g_unl_t + (size_t)b*(CC*MUP/4) + mt*32;
    #pragma unroll
    for (int t=0;t<16;++t){
        int idx=tid+t*128; int c=idx>>5, x=idx&31;
        u4[idx]=gu4[(size_t)c*(MUP/4)+x];
    }
    sm_col[tid]=0ULL;
    __syncthreads();

    unsigned long long rk[8];
    #pragma unroll
    for (int sdx=0;sdx<8;++sdx) rk[sdx]=0ULL;

    #pragma unroll 1
    for (int h=0; h<2; ++h){
        unsigned long long acc[8][4];
        #pragma unroll
        for (int j=0;j<8;++j)
            #pragma unroll
            for (int k2=0;k2<4;++k2) acc[j][k2]=0ULL;

        #pragma unroll 2
        for (int c=0;c<64;++c){
            float4 a0=s4[c*32+h*16+ci];
            float4 a1=s4[c*32+h*16+8+ci];
            ulonglong2 bb0=*(const ulonglong2*)&u4[c*32+mi];
            ulonglong2 bb1=*(const ulonglong2*)&u4[c*32+16+mi];
            unsigned long long pb0=bb0.x, pb1=bb0.y, pb2=bb1.x, pb3=bb1.y;
            float av[8]={a0.x,a0.y,a0.z,a0.w,a1.x,a1.y,a1.z,a1.w};
            #pragma unroll
            for (int j=0;j<8;++j){
                unsigned long long sa=splat2(av[j]);
                fma2(acc[j][0],sa,pb0);
                fma2(acc[j][1],sa,pb1);
                fma2(acc[j][2],sa,pb2);
                fma2(acc[j][3],sa,pb3);
            }
        }
        #pragma unroll
        for (int j=0;j<8;++j){
            int colj = cp*128 + h*64 + ((j<4)? ci*4+j : 32+ci*4+(j-4));
            bool vc = colj < COLS;
            unsigned long long ck=0ULL;
            #pragma unroll
            for (int k2=0;k2<4;++k2){
                float lo,hi; unpack2(acc[j][k2],lo,hi);
                int mloc = (k2<2)? mi*4+2*k2 : 64+mi*4+2*(k2-2);
                int mglo = mt*128+mloc, mghi = mglo+1;
                if (vc){
                    unsigned long long kl=packkey(lo,(unsigned)colj);
                    unsigned long long kh=packkey(hi,(unsigned)colj);
                    if (kl>rk[2*k2])   rk[2*k2]=kl;
                    if (kh>rk[2*k2+1]) rk[2*k2+1]=kh;
                    if (mglo<MU){ unsigned long long c1=packkey(lo,(unsigned)mglo); if (c1>ck) ck=c1; }
                    if (mghi<MU){ unsigned long long c2=packkey(hi,(unsigned)mghi); if (c2>ck) ck=c2; }
                }
            }
            #pragma unroll
            for (int off=8;off<=16;off<<=1){
                unsigned long long o=__shfl_xor_sync(0xffffffffu,ck,off);
                if (o>ck) ck=o;
            }
            if (lane<8 && ck){
                int local = h*64 + ((j<4)? lane*4+j : 32+lane*4+(j-4));
                atomicMax(&sm_col[local], ck);
            }
        }
    }
    #pragma unroll
    for (int sdx=0;sdx<8;++sdx){
        unsigned long long v=rk[sdx];
        #pragma unroll
        for (int off=1;off<=4;off<<=1){
            unsigned long long o=__shfl_xor_sync(0xffffffffu,v,off);
            if (o>v) v=o;
        }
        if ((lane&7)==0 && v){
            int mloc = (sdx<4)? mi*4+sdx : 64+mi*4+(sdx-4);
            int mg = mt*128+mloc;
            if (mg<MU) atomicMax(&g_rowbest[(size_t)b*MU+mg], v);
        }
    }
    __syncthreads();
    if ((cp*128+tid)<COLS && sm_col[tid])
        atomicMax(&g_colbest[(size_t)b*COLS+cp*128+tid], sm_col[tid]);
}

// ---------------- K2: fused compact + gather (per bw block) -----------------
// Phase 1: stable stream compaction into smem sel list (same order as before).
// Phase 2: smem-transpose gather g_unl_n rows -> g_cat_t columns, both coalesced.
__global__ void __launch_bounds__(512) k_cg(){
    int bw = blockIdx.x; int b = bw/NWAY, w = bw%NWAY;
    int tid = threadIdx.x, lane = tid&31, wid = tid>>5;   // 16 warps
    __shared__ int sel_s[640];                            // cw <= 625
    __shared__ int wsum[16], woff[16], sbase;
    __shared__ float tile[CC][65];
    if (tid==0) sbase=0;
    __syncthreads();
    for (int chunk=0; chunk<5; ++chunk){
        int m = chunk*512 + tid;
        bool flag = false;
        if (m < MU){
            unsigned long long rb = g_rowbest[b*MU+m];
            unsigned col = 0xFFFFFFFFu - (unsigned)(rb & 0xFFFFFFFFu);
            if ((int)(col/MS) == w){
                unsigned long long cb = g_colbest[b*COLS+col];
                unsigned mm = 0xFFFFFFFFu - (unsigned)(cb & 0xFFFFFFFFu);
                flag = (mm == (unsigned)m);
            }
        }
        unsigned bal = __ballot_sync(0xffffffffu, flag);
        if (lane==0) wsum[wid] = __popc(bal);
        __syncthreads();
        if (tid==0){
            int run=sbase;
            #pragma unroll
            for (int i=0;i<16;++i){ woff[i]=run; run+=wsum[i]; }
            sbase=run;
        }
        __syncthreads();
        if (flag){
            int pos = woff[wid] + __popc(bal & ((1u<<lane)-1u));
            sel_s[pos] = m;
        }
        __syncthreads();
    }
    int cw = sbase;
    if (tid==0){
        g_count[bw] = cw;
        atomicMax(&g_L[0], cw);
    }
    // Phase 2: gather
    const float* __restrict__ unl = g_unl_n + (size_t)b*MU*CC;
    float* __restrict__ cat = g_cat_t + (size_t)bw*CC*CATP + MS;
    for (int jb=0; jb<cw; jb+=64){
        int nj = min(64, cw-jb);
        for (int t=wid; t<nj; t+=16){
            int m = sel_s[jb+t];                             // broadcast per warp
            float2 v = ((const float2*)(unl + (size_t)m*CC))[lane];  // 256B coalesced
            tile[2*lane][t]   = v.x;
            tile[2*lane+1][t] = v.y;
        }
        __syncthreads();
        for (int o=tid; o<CC*64; o+=512){
            int c=o>>6, j=o&63;
            if (j<nj) cat[(size_t)c*CATP + jb + j] = tile[c][j];   // coalesced along j
        }
        __syncthreads();
    }
}

// ---------------- K3: query GEMM (f32x2) + row-best epilogue ----------------
__global__ void __launch_bounds__(128,3) k_qsim(){
    int ct=blockIdx.x, qt=blockIdx.y, bw=blockIdx.z;
    int b=bw/NWAY, w=bw%NWAY;
    int cw=g_count[bw]; int wl=MS+cw;
    if (ct*128 >= wl) return;
    __shared__ float4 a4[2048];                 // q-rows: [c][32 f4] = 128 rows (32KB)
    __shared__ float4 v4[2048];                 // cols:   [c][32 f4] = 128 cols (32KB)
    int tid=threadIdx.x, lane=tid&31;
    int ci=tid&7, mi=tid>>3;

    const float4* ga=(const float4*)g_q_t + (size_t)b*(CC*QROWP/4) + qt*32;
    #pragma unroll
    for (int t=0;t<16;++t){
        int idx=tid+t*128; int c=idx>>5, x=idx&31;
        a4[idx]=ga[(size_t)c*(QROWP/4)+x];
    }
    const float4* gv=(const float4*)g_cat_t + (size_t)bw*(CC*CATP/4) + ct*32;
    #pragma unroll
    for (int t=0;t<16;++t){
        int idx=tid+t*128; int c=idx>>5, x=idx&31;
        v4[idx]=gv[(size_t)c*(CATP/4)+x];
    }
    __syncthreads();

    unsigned long long rk[8];
    #pragma unroll
    for (int sdx=0;sdx<8;++sdx) rk[sdx]=0ULL;

    #pragma unroll 1
    for (int h=0; h<2; ++h){
        unsigned long long acc[8][4];
        #pragma unroll
        for (int j=0;j<8;++j)
            #pragma unroll
            for (int k2=0;k2<4;++k2) acc[j][k2]=0ULL;

        #pragma unroll 2
        for (int c=0;c<64;++c){
            float4 a0=v4[c*32+h*16+ci];
            float4 a1=v4[c*32+h*16+8+ci];
            ulonglong2 bb0=*(const ulonglong2*)&a4[c*32+mi];
            ulonglong2 bb1=*(const ulonglong2*)&a4[c*32+16+mi];
            unsigned long long pb0=bb0.x, pb1=bb0.y, pb2=bb1.x, pb3=bb1.y;
            float av[8]={a0.x,a0.y,a0.z,a0.w,a1.x,a1.y,a1.z,a1.w};
            #pragma unroll
            for (int j=0;j<8;++j){
                unsigned long long sa=splat2(av[j]);
                fma2(acc[j][0],sa,pb0);
                fma2(acc[j][1],sa,pb1);
                fma2(acc[j][2],sa,pb2);
                fma2(acc[j][3],sa,pb3);
            }
        }
        #pragma unroll
        for (int j=0;j<8;++j){
            int coll = h*64 + ((j<4)? ci*4+j : 32+ci*4+(j-4));
            int jg = ct*128 + coll;
            if (jg < wl){
                unsigned gcol = (unsigned)(w*MTOT + jg);
                #pragma unroll
                for (int k2=0;k2<4;++k2){
                    float lo,hi; unpack2(acc[j][k2],lo,hi);
                    unsigned long long kl=packkey(lo,gcol);
                    unsigned long long kh=packkey(hi,gcol);
                    if (kl>rk[2*k2])   rk[2*k2]=kl;
                    if (kh>rk[2*k2+1]) rk[2*k2+1]=kh;
                }
            }
        }
    }
    #pragma unroll
    for (int sdx=0;sdx<8;++sdx){
        unsigned long long v=rk[sdx];
        #pragma unroll
        for (int off=1;off<=4;off<<=1){
            unsigned long long o=__shfl_xor_sync(0xffffffffu,v,off);
            if (o>v) v=o;
        }
        if ((lane&7)==0 && v){
            int mloc = (sdx<4)? mi*4+sdx : 64+mi*4+(sdx-4);
            int r = qt*128+mloc;
            if (r<QROWS)
                atomicMax(&g_rowq[((size_t)b*QROWP + r)*NWAY + w], v);
        }
    }
}

// ---------------- K4: finish = recompute col-argmax + mutual mask + CE ------
__global__ void __launch_bounds__(256) k_fin(const int* __restrict__ qy,
                                             float* __restrict__ out){
    int q=blockIdx.x, b=blockIdx.y;
    int tid=threadIdx.x, lane=tid&31, wp=tid>>5;
    __shared__ float rmx_s[NWAY][32];
    __shared__ unsigned gcol_s[32];
    __shared__ float mask_s[32];
    __shared__ int cnt_s[NWAY+1];
    if (tid<NWAY) cnt_s[tid]=g_count[b*NWAY+tid];
    if (tid==NWAY) cnt_s[NWAY]=g_L[0];
    if (tid<32) mask_s[tid]=0.f;
    __syncthreads();
    // stage 1: per-row (mq) way-maxes and global best column
    if (wp==0 && lane<HWN){
        unsigned long long qb=0ULL;
        #pragma unroll
        for (int w=0;w<NWAY;++w){
            unsigned long long r = g_rowq[((size_t)b*QROWP + q*25 + lane)*NWAY + w];
            int cww=cnt_s[w];
            if (cww < cnt_s[NWAY]){
                // first all-zero pad column of this way: raw cos = 0.0, col id MS+cww
                unsigned long long pk = packkey(0.0f,(unsigned)(w*MTOT+MS+cww));
                if (pk>r) r=pk;
            }
            rmx_s[w][lane]=fmaf(funmap((unsigned)(r>>32)),0.5f,0.5f);
            if (r>qb) qb=r;
        }
        gcol_s[lane]=0xFFFFFFFFu - (unsigned)(qb & 0xFFFFFFFFu);
    }
    __syncthreads();
    // stage 2: per winning column, recompute argmax over mq (bitwise-identical chain)
    for (int t=wp; t<HWN; t+=8){
        unsigned gcol=gcol_s[t];
        int w_=(int)(gcol/MTOT), j_=(int)(gcol%MTOT);
        int amq=0;
        if (j_ < MS + cnt_s[w_]){
            float acc=0.f;
            const float* qp = g_q_t + (size_t)b*CC*QROWP + q*25 + lane;
            const float* cp = g_cat_t + (size_t)(b*NWAY+w_)*CC*CATP + j_;
            if (lane<HWN){
                #pragma unroll
                for (int c=0;c<CC;++c)
                    acc=fmaf(qp[(size_t)c*QROWP], cp[(size_t)c*CATP], acc);
            }
            unsigned long long k = (lane<HWN)? packkey(acc,(unsigned)lane) : 0ULL;
            #pragma unroll
            for (int off=16;off>=1;off>>=1){
                unsigned long long o=__shfl_xor_sync(0xffffffffu,k,off);
                if (o>k) k=o;
            }
            amq = (int)(0xFFFFFFFFu - (unsigned)(k & 0xFFFFFFFFu));
        }
        if (lane==0) mask_s[t] = (amq==t)?1.f:0.f;
    }
    __syncthreads();
    // stage 3: qv + cross-entropy
    if (wp==0){
        float qv[NWAY];
        #pragma unroll
        for (int w=0;w<NWAY;++w){
            float t = (lane<HWN) ? rmx_s[w][lane]*mask_s[lane] : 0.f;
            #pragma unroll
            for (int off=16;off>=1;off>>=1) t += __shfl_xor_sync(0xffffffffu,t,off);
            qv[w]=t;
        }
        if (lane==0){
            int y = qy[b*QQ+q];
            float mx=qv[0];
            #pragma unroll
            for (int w=1;w<NWAY;++w) mx=fmaxf(mx,qv[w]);
            float se=0.f;
            #pragma unroll
            for (int w=0;w<NWAY;++w) se += expf(qv[w]-mx);
            float li = mx + logf(se) - qv[y];
            atomicAdd(out, li*(1.0f/(float)(BB*QQ)));
        }
    }
}

// ---------------- launch ----------------
extern "C" void kernel_launch(void* const* d_in, const int* in_sizes, int n_in,
                              void* d_out, int out_size) {
    const float* sup = nullptr;
    const float* qx  = nullptr;
    const float* ux  = nullptr;
    const int*   qy  = nullptr;
    for (int i=0;i<n_in;++i){
        switch (in_sizes[i]){
            case 160000: sup = (const float*)d_in[i]; break; // support_xf
            case 480000: qx  = (const float*)d_in[i]; break; // query_xf
            case 640000: ux  = (const float*)d_in[i]; break; // unlabeled_xf
            case 300:    qy  = (const int*)d_in[i];   break; // query_y
            default: break;                                  // support_y unused
        }
    }
    float* out = (float*)d_out;
    k_prep<<<816,256>>>(sup, ux, qx, out, out_size);
    k_u2s<<<dim3(20,5,BB),128>>>();
    k_cg<<<BB*NWAY,512>>>();
    k_qsim<<<dim3(21,15,BB*NWAY),128>>>();
    k_fin<<<dim3(QQ,BB),256>>>(qy, out);
}

// round 10
// speedup vs baseline: 1.0608x; 1.0026x over previous
#include <cuda_runtime.h>
#include <math.h>

#define NWAY 5
#define BB 4
#define CC 64
#define HWN 25
#define MS 125      // K_SHOT * h * w
#define MU 2500     // u * h * w
#define QQ 75
#define COLS 625    // NWAY * MS
#define MTOT 2625   // MS + MU
#define COLP 640    // padded cols for transposed support
#define MUP 2560    // padded m for transposed unlabeled
#define QROWS 1875  // 75 q * 25 rows (packed)
#define QROWP 1920  // padded to 15*128
#define CATP 2688   // padded cat columns (21*128)

// ---------------- scratch (static device allocations only) ----------------
__device__ float g_sup_t[BB*CC*COLP];            // [b][c][col] transposed support (pad zeroed)
__device__ float g_unl_t[BB*CC*MUP];             // [b][c][m]   transposed unlabeled (pad zeroed)
__device__ float g_unl_n[BB*MU*CC];              // [b][m][c]   row-major normalized unlabeled
__device__ float g_q_t[BB*CC*QROWP];             // [b][c][q*25+mq] transposed query (pads zero)
__device__ float g_cat_t[BB*NWAY*CC*CATP];       // [bw][c][j] = [sup(125) | compacted unl(cw)]
__device__ unsigned long long g_rowbest[BB*MU];  // per (b,m): packed (val,col) argmax
__device__ unsigned long long g_colbest[BB*COLS];// per (b,col): packed (val,m) argmax
__device__ unsigned long long g_rowq[BB*QROWP*NWAY]; // per (b,row,w): packed best over cols
__device__ int g_count[BB*NWAY];
__device__ int g_L[1];

// monotone float ordering map (handles negatives exactly)
__device__ __forceinline__ unsigned fmap(float f){
    unsigned b=__float_as_uint(f);
    return (b&0x80000000u)? ~b : (b|0x80000000u);
}
__device__ __forceinline__ float funmap(unsigned u){
    return (u&0x80000000u)? __uint_as_float(u^0x80000000u) : __uint_as_float(~u);
}
// max-value, min-index-on-tie key (matches jnp first-occurrence argmax)
__device__ __forceinline__ unsigned long long packkey(float v, unsigned idx){
    return (((unsigned long long)fmap(v))<<32) | (unsigned long long)(0xFFFFFFFFu - idx);
}
// packed 2xFP32 FMA (Blackwell f32x2)
__device__ __forceinline__ void fma2(unsigned long long& acc, unsigned long long a, unsigned long long b){
    asm("fma.rn.f32x2 %0, %1, %2, %0;" : "+l"(acc) : "l"(a), "l"(b));
}
__device__ __forceinline__ unsigned long long splat2(float x){
    unsigned long long r;
    asm("mov.b64 %0, {%1, %1};" : "=l"(r) : "r"(__float_as_uint(x)));
    return r;
}
__device__ __forceinline__ void unpack2(unsigned long long v, float& lo, float& hi){
    unsigned a,b;
    asm("mov.b64 {%0, %1}, %2;" : "=r"(a), "=r"(b) : "l"(v));
    lo=__uint_as_float(a); hi=__uint_as_float(b);
}

// ---------------- K0: prep = init + all normalizations ----------------
__global__ void __launch_bounds__(256) k_prep(const float* __restrict__ sup,
                                              const float* __restrict__ unl,
                                              const float* __restrict__ qx,
                                              float* __restrict__ out, int out_size){
    int s = blockIdx.x;
    int tid = threadIdx.x;
    if (s >= 800){
        int i = (s-800)*256 + tid;
        const int stride = 16*256;
        for (int t=i;t<BB*MU;t+=stride) g_rowbest[t]=0ULL;
        for (int t=i;t<BB*COLS;t+=stride) g_colbest[t]=0ULL;
        for (int t=i;t<BB*QROWP*NWAY;t+=stride) g_rowq[t]=0ULL;
        for (int t=i;t<BB*CC*(COLP-COLS);t+=stride){
            int bc=t/(COLP-COLS), p=t%(COLP-COLS);
            g_sup_t[(size_t)bc*COLP+COLS+p]=0.f;
        }
        for (int t=i;t<BB*CC*(MUP-MU);t+=stride){
            int bc=t/(MUP-MU), p=t%(MUP-MU);
            g_unl_t[(size_t)bc*MUP+MU+p]=0.f;
        }
        // pad rows 1875..1919 of g_q_t
        for (int t=i;t<BB*CC*(QROWP-QROWS);t+=stride){
            int bc=t/(QROWP-QROWS), p=t%(QROWP-QROWS);
            g_q_t[(size_t)bc*QROWP+QROWS+p]=0.f;
        }
        if (i==0) g_L[0]=0;
        for (int t=i;t<out_size;t+=stride) out[t]=0.f;
        return;
    }
    __shared__ __align__(16) float tile[1600];
    __shared__ float inv[HWN];
    const float* in;
    if (s<100)      in = sup + (size_t)s*1600;
    else if (s<500) in = unl + (size_t)(s-100)*1600;
    else            in = qx  + (size_t)(s-500)*1600;
    {
        const float4* in4=(const float4*)in;
        float4* t4=(float4*)tile;
        for (int t=tid;t<400;t+=256) t4[t]=in4[t];
    }
    __syncthreads();
    if (tid<HWN){
        float a=0.f;
        for (int c=0;c<CC;++c){ float v=tile[c*HWN+tid]; a=fmaf(v,v,a); }
        inv[tid]=1.0f/fmaxf(sqrtf(a),1e-12f);
    }
    __syncthreads();
    if (s<100){
        int b=s/25, sk=s%25, w=sk/5, k=sk%5;
        int colbase=w*MS+k*25;
        float* outt=g_sup_t+(size_t)b*CC*COLP+colbase;
        float* outc=g_cat_t+(size_t)(b*NWAY+w)*CC*CATP + k*25;
        for (int o=tid;o<1600;o+=256){
            int c=o/HWN,hw=o%HWN;
            float v=tile[o]*inv[hw];
            outt[(size_t)c*COLP+hw]=v;
            outc[(size_t)c*CATP+hw]=v;
        }
    } else if (s<500){
        int t2=s-100; int b=t2/100,u=t2%100;
        float* outt=g_unl_t+(size_t)b*CC*MUP+u*25;
        float* outp=g_unl_n+(size_t)(b*MU+u*25)*CC;
        for (int o=tid;o<1600;o+=256){ int c=o/HWN,hw=o%HWN; outt[(size_t)c*MUP+hw]=tile[o]*inv[hw]; }
        for (int o=tid;o<1600;o+=256){ int hw=o>>6,c=o&63; outp[o]=tile[c*HWN+hw]*inv[hw]; }
    } else {
        int t2=s-500; int b=t2/QQ, q=t2%QQ;
        float* outt=g_q_t+(size_t)b*CC*QROWP + q*25;
        for (int o=tid;o<1600;o+=256){ int c=o/HWN,hw=o%HWN; outt[(size_t)c*QROWP+hw]=tile[o]*inv[hw]; }
    }
}

// ---------------- K1: u2s GEMM (f32x2) + packed row/col argmax ----------------
__global__ void __launch_bounds__(128,3) k_u2s(){
    __shared__ float4 s4[2048];                  // [c][32 f4] = 128 cols (32KB)
    __shared__ float4 u4[2048];                  // [c][32 f4] = 128 m   (32KB)
    __shared__ unsigned long long sm_col[128];
    int mt=blockIdx.x, cp=blockIdx.y, b=blockIdx.z;
    int tid=threadIdx.x, lane=tid&31;
    int ci=tid&7, mi=tid>>3;

    const float4* gs4=(const float4*)g_sup_t + (size_t)b*(CC*COLP/4) + cp*32;
    #pragma unroll
    for (int t=0;t<16;++t){
        int idx=tid+t*128; int c=idx>>5, x=idx&31;
        s4[idx]=gs4[(size_t)c*(COLP/4)+x];
    }
    const float4* gu4=(const float4*)g_unl_t + (size_t)b*(CC*MUP/4) + mt*32;
    #pragma unroll
    for (int t=0;t<16;++t){
        int idx=tid+t*128; int c=idx>>5, x=idx&31;
        u4[idx]=gu4[(size_t)c*(MUP/4)+x];
    }
    sm_col[tid]=0ULL;
    __syncthreads();

    unsigned long long rk[8];
    #pragma unroll
    for (int sdx=0;sdx<8;++sdx) rk[sdx]=0ULL;

    #pragma unroll 1
    for (int h=0; h<2; ++h){
        unsigned long long acc[8][4];
        #pragma unroll
        for (int j=0;j<8;++j)
            #pragma unroll
            for (int k2=0;k2<4;++k2) acc[j][k2]=0ULL;

        #pragma unroll 2
        for (int c=0;c<64;++c){
            float4 a0=s4[c*32+h*16+ci];
            float4 a1=s4[c*32+h*16+8+ci];
            ulonglong2 bb0=*(const ulonglong2*)&u4[c*32+mi];
            ulonglong2 bb1=*(const ulonglong2*)&u4[c*32+16+mi];
            unsigned long long pb0=bb0.x, pb1=bb0.y, pb2=bb1.x, pb3=bb1.y;
            float av[8]={a0.x,a0.y,a0.z,a0.w,a1.x,a1.y,a1.z,a1.w};
            #pragma unroll
            for (int j=0;j<8;++j){
                unsigned long long sa=splat2(av[j]);
                fma2(acc[j][0],sa,pb0);
                fma2(acc[j][1],sa,pb1);
                fma2(acc[j][2],sa,pb2);
                fma2(acc[j][3],sa,pb3);
            }
        }
        #pragma unroll
        for (int j=0;j<8;++j){
            int colj = cp*128 + h*64 + ((j<4)? ci*4+j : 32+ci*4+(j-4));
            bool vc = colj < COLS;
            unsigned long long ck=0ULL;
            #pragma unroll
            for (int k2=0;k2<4;++k2){
                float lo,hi; unpack2(acc[j][k2],lo,hi);
                int mloc = (k2<2)? mi*4+2*k2 : 64+mi*4+2*(k2-2);
                int mglo = mt*128+mloc, mghi = mglo+1;
                if (vc){
                    unsigned long long kl=packkey(lo,(unsigned)colj);
                    unsigned long long kh=packkey(hi,(unsigned)colj);
                    if (kl>rk[2*k2])   rk[2*k2]=kl;
                    if (kh>rk[2*k2+1]) rk[2*k2+1]=kh;
                    if (mglo<MU){ unsigned long long c1=packkey(lo,(unsigned)mglo); if (c1>ck) ck=c1; }
                    if (mghi<MU){ unsigned long long c2=packkey(hi,(unsigned)mghi); if (c2>ck) ck=c2; }
                }
            }
            #pragma unroll
            for (int off=8;off<=16;off<<=1){
                unsigned long long o=__shfl_xor_sync(0xffffffffu,ck,off);
                if (o>ck) ck=o;
            }
            if (lane<8 && ck){
                int local = h*64 + ((j<4)? lane*4+j : 32+lane*4+(j-4));
                atomicMax(&sm_col[local], ck);
            }
        }
    }
    #pragma unroll
    for (int sdx=0;sdx<8;++sdx){
        unsigned long long v=rk[sdx];
        #pragma unroll
        for (int off=1;off<=4;off<<=1){
            unsigned long long o=__shfl_xor_sync(0xffffffffu,v,off);
            if (o>v) v=o;
        }
        if ((lane&7)==0 && v){
            int mloc = (sdx<4)? mi*4+sdx : 64+mi*4+(sdx-4);
            int mg = mt*128+mloc;
            if (mg<MU) atomicMax(&g_rowbest[(size_t)b*MU+mg], v);
        }
    }
    __syncthreads();
    if ((cp*128+tid)<COLS && sm_col[tid])
        atomicMax(&g_colbest[(size_t)b*COLS+cp*128+tid], sm_col[tid]);
}

// ---------------- K2: fused compact + gather (per bw block) -----------------
__global__ void __launch_bounds__(512) k_cg(){
    int bw = blockIdx.x; int b = bw/NWAY, w = bw%NWAY;
    int tid = threadIdx.x, lane = tid&31, wid = tid>>5;   // 16 warps
    __shared__ int sel_s[640];                            // cw <= 625
    __shared__ int wsum[16], woff[16], sbase;
    __shared__ float tile[CC][65];
    if (tid==0) sbase=0;
    __syncthreads();
    for (int chunk=0; chunk<5; ++chunk){
        int m = chunk*512 + tid;
        bool flag = false;
        if (m < MU){
            unsigned long long rb = g_rowbest[b*MU+m];
            unsigned col = 0xFFFFFFFFu - (unsigned)(rb & 0xFFFFFFFFu);
            if ((int)(col/MS) == w){
                unsigned long long cb = g_colbest[b*COLS+col];
                unsigned mm = 0xFFFFFFFFu - (unsigned)(cb & 0xFFFFFFFFu);
                flag = (mm == (unsigned)m);
            }
        }
        unsigned bal = __ballot_sync(0xffffffffu, flag);
        if (lane==0) wsum[wid] = __popc(bal);
        __syncthreads();
        if (tid==0){
            int run=sbase;
            #pragma unroll
            for (int i=0;i<16;++i){ woff[i]=run; run+=wsum[i]; }
            sbase=run;
        }
        __syncthreads();
        if (flag){
            int pos = woff[wid] + __popc(bal & ((1u<<lane)-1u));
            sel_s[pos] = m;
        }
        __syncthreads();
    }
    int cw = sbase;
    if (tid==0){
        g_count[bw] = cw;
        atomicMax(&g_L[0], cw);
    }
    // Phase 2: gather
    const float* __restrict__ unl = g_unl_n + (size_t)b*MU*CC;
    float* __restrict__ cat = g_cat_t + (size_t)bw*CC*CATP + MS;
    for (int jb=0; jb<cw; jb+=64){
        int nj = min(64, cw-jb);
        for (int t=wid; t<nj; t+=16){
            int m = sel_s[jb+t];                             // broadcast per warp
            float2 v = ((const float2*)(unl + (size_t)m*CC))[lane];  // 256B coalesced
            tile[2*lane][t]   = v.x;
            tile[2*lane+1][t] = v.y;
        }
        __syncthreads();
        for (int o=tid; o<CC*64; o+=512){
            int c=o>>6, j=o&63;
            if (j<nj) cat[(size_t)c*CATP + jb + j] = tile[c][j];   // coalesced along j
        }
        __syncthreads();
    }
}

// ---------------- K3: query GEMM (f32x2), 256 threads, streaming epilogue ----
// Tile 128 rows x 128 cols. Warp = 32 lanes spanning all 128 cols (4 each);
// warp id mi in [0,8) owns rows mi*16 .. mi*16+15 (8 f32x2 pairs).
__global__ void __launch_bounds__(256,2) k_qsim(){
    int ct=blockIdx.x, qt=blockIdx.y, bw=blockIdx.z;
    int b=bw/NWAY, w=bw%NWAY;
    int cw=g_count[bw]; int wl=MS+cw;
    if (ct*128 >= wl) return;
    __shared__ float4 a4[2048];                 // q-rows: [c][32 f4] = 128 rows (32KB)
    __shared__ float4 v4[2048];                 // cols:   [c][32 f4] = 128 cols (32KB)
    int tid=threadIdx.x, lane=tid&31, mi=tid>>5;

    const float4* ga=(const float4*)g_q_t + (size_t)b*(CC*QROWP/4) + qt*32;
    #pragma unroll
    for (int t=0;t<8;++t){
        int idx=tid+t*256; int c=idx>>5, x=idx&31;
        a4[idx]=ga[(size_t)c*(QROWP/4)+x];
    }
    const float4* gv=(const float4*)g_cat_t + (size_t)bw*(CC*CATP/4) + ct*32;
    #pragma unroll
    for (int t=0;t<8;++t){
        int idx=tid+t*256; int c=idx>>5, x=idx&31;
        v4[idx]=gv[(size_t)c*(CATP/4)+x];
    }
    __syncthreads();

    // accumulators: 4 cols (lane*4+j) x 8 row-pairs (rows mi*16+2t, +1)
    unsigned long long acc[4][8];
    #pragma unroll
    for (int j=0;j<4;++j)
        #pragma unroll
        for (int t=0;t<8;++t) acc[j][t]=0ULL;

    #pragma unroll 2
    for (int c=0;c<64;++c){
        float4 a = v4[c*32 + lane];                       // 4 col values
        ulonglong2 bb0=*(const ulonglong2*)&a4[c*32 + mi*4];
        ulonglong2 bb1=*(const ulonglong2*)&a4[c*32 + mi*4 + 1];
        ulonglong2 bb2=*(const ulonglong2*)&a4[c*32 + mi*4 + 2];
        ulonglong2 bb3=*(const ulonglong2*)&a4[c*32 + mi*4 + 3];
        unsigned long long pb[8]={bb0.x,bb0.y,bb1.x,bb1.y,bb2.x,bb2.y,bb3.x,bb3.y};
        float av[4]={a.x,a.y,a.z,a.w};
        #pragma unroll
        for (int j=0;j<4;++j){
            unsigned long long sa=splat2(av[j]);
            #pragma unroll
            for (int t=0;t<8;++t) fma2(acc[j][t],sa,pb[t]);
        }
    }

    // streaming epilogue: per row-pair, max over this thread's 4 cols,
    // then full-warp shfl (covers all 128 cols), lane0 atomics.
    int col0 = ct*128 + lane*4;
    #pragma unroll
    for (int t=0;t<8;++t){
        unsigned long long kl=0ULL, kh=0ULL;
        #pragma unroll
        for (int j=0;j<4;++j){
            int jg = col0 + j;
            if (jg < wl){
                float lo,hi; unpack2(acc[j][t],lo,hi);
                unsigned gcol = (unsigned)(w*MTOT + jg);
                unsigned long long a1=packkey(lo,gcol);
                unsigned long long a2=packkey(hi,gcol);
                if (a1>kl) kl=a1;
                if (a2>kh) kh=a2;
            }
        }
        #pragma unroll
        for (int off=16;off>=1;off>>=1){
            unsigned long long o1=__shfl_xor_sync(0xffffffffu,kl,off);
            unsigned long long o2=__shfl_xor_sync(0xffffffffu,kh,off);
            if (o1>kl) kl=o1;
            if (o2>kh) kh=o2;
        }
        if (lane==0){
            int r0 = qt*128 + mi*16 + 2*t;
            if (r0<QROWS && kl) atomicMax(&g_rowq[((size_t)b*QROWP + r0)*NWAY + w], kl);
            if (r0+1<QROWS && kh) atomicMax(&g_rowq[((size_t)b*QROWP + r0+1)*NWAY + w], kh);
        }
    }
}

// ---------------- K4: finish = recompute col-argmax + mutual mask + CE ------
__global__ void __launch_bounds__(256) k_fin(const int* __restrict__ qy,
                                             float* __restrict__ out){
    int q=blockIdx.x, b=blockIdx.y;
    int tid=threadIdx.x, lane=tid&31, wp=tid>>5;
    __shared__ float rmx_s[NWAY][32];
    __shared__ unsigned gcol_s[32];
    __shared__ float mask_s[32];
    __shared__ int cnt_s[NWAY+1];
    if (tid<NWAY) cnt_s[tid]=g_count[b*NWAY+tid];
    if (tid==NWAY) cnt_s[NWAY]=g_L[0];
    if (tid<32) mask_s[tid]=0.f;
    __syncthreads();
    // stage 1: per-row (mq) way-maxes and global best column
    if (wp==0 && lane<HWN){
        unsigned long long qb=0ULL;
        #pragma unroll
        for (int w=0;w<NWAY;++w){
            unsigned long long r = g_rowq[((size_t)b*QROWP + q*25 + lane)*NWAY + w];
            int cww=cnt_s[w];
            if (cww < cnt_s[NWAY]){
                // first all-zero pad column of this way: raw cos = 0.0, col id MS+cww
                unsigned long long pk = packkey(0.0f,(unsigned)(w*MTOT+MS+cww));
                if (pk>r) r=pk;
            }
            rmx_s[w][lane]=fmaf(funmap((unsigned)(r>>32)),0.5f,0.5f);
            if (r>qb) qb=r;
        }
        gcol_s[lane]=0xFFFFFFFFu - (unsigned)(qb & 0xFFFFFFFFu);
    }
    __syncthreads();
    // stage 2: per winning column, recompute argmax over mq (bitwise-identical chain)
    for (int t=wp; t<HWN; t+=8){
        unsigned gcol=gcol_s[t];
        int w_=(int)(gcol/MTOT), j_=(int)(gcol%MTOT);
        int amq=0;
        if (j_ < MS + cnt_s[w_]){
            float acc=0.f;
            const float* qp = g_q_t + (size_t)b*CC*QROWP + q*25 + lane;
            const float* cp = g_cat_t + (size_t)(b*NWAY+w_)*CC*CATP + j_;
            if (lane<HWN){
                #pragma unroll
                for (int c=0;c<CC;++c)
                    acc=fmaf(qp[(size_t)c*QROWP], cp[(size_t)c*CATP], acc);
            }
            unsigned long long k = (lane<HWN)? packkey(acc,(unsigned)lane) : 0ULL;
            #pragma unroll
            for (int off=16;off>=1;off>>=1){
                unsigned long long o=__shfl_xor_sync(0xffffffffu,k,off);
                if (o>k) k=o;
            }
            amq = (int)(0xFFFFFFFFu - (unsigned)(k & 0xFFFFFFFFu));
        }
        if (lane==0) mask_s[t] = (amq==t)?1.f:0.f;
    }
    __syncthreads();
    // stage 3: qv + cross-entropy
    if (wp==0){
        float qv[NWAY];
        #pragma unroll
        for (int w=0;w<NWAY;++w){
            float t = (lane<HWN) ? rmx_s[w][lane]*mask_s[lane] : 0.f;
            #pragma unroll
            for (int off=16;off>=1;off>>=1) t += __shfl_xor_sync(0xffffffffu,t,off);
            qv[w]=t;
        }
        if (lane==0){
            int y = qy[b*QQ+q];
            float mx=qv[0];
            #pragma unroll
            for (int w=1;w<NWAY;++w) mx=fmaxf(mx,qv[w]);
            float se=0.f;
            #pragma unroll
            for (int w=0;w<NWAY;++w) se += expf(qv[w]-mx);
            float li = mx + logf(se) - qv[y];
            atomicAdd(out, li*(1.0f/(float)(BB*QQ)));
        }
    }
}

// ---------------- launch ----------------
extern "C" void kernel_launch(void* const* d_in, const int* in_sizes, int n_in,
                              void* d_out, int out_size) {
    const float* sup = nullptr;
    const float* qx  = nullptr;
    const float* ux  = nullptr;
    const int*   qy  = nullptr;
    for (int i=0;i<n_in;++i){
        switch (in_sizes[i]){
            case 160000: sup = (const float*)d_in[i]; break; // support_xf
            case 480000: qx  = (const float*)d_in[i]; break; // query_xf
            case 640000: ux  = (const float*)d_in[i]; break; // unlabeled_xf
            case 300:    qy  = (const int*)d_in[i];   break; // query_y
            default: break;                                  // support_y unused
        }
    }
    float* out = (float*)d_out;
    k_prep<<<816,256>>>(sup, ux, qx, out, out_size);
    k_u2s<<<dim3(20,5,BB),128>>>();
    k_cg<<<BB*NWAY,512>>>();
    k_qsim<<<dim3(21,15,BB*NWAY),256>>>();
    k_fin<<<dim3(QQ,BB),256>>>(qy, out);
}

// round 11
// speedup vs baseline: 1.1356x; 1.0704x over previous
#include <cuda_runtime.h>
#include <math.h>

#define NWAY 5
#define BB 4
#define CC 64
#define HWN 25
#define MS 125      // K_SHOT * h * w
#define MU 2500     // u * h * w
#define QQ 75
#define COLS 625    // NWAY * MS
#define MTOT 2625   // MS + MU
#define COLP 640    // padded cols for transposed support
#define MUP 2560    // padded m for transposed unlabeled
#define QROWS 1875  // 75 q * 25 rows (packed)
#define QROWP 1920  // padded to 15*128
#define CATP 2688   // padded cat columns (21*128)

// ---------------- scratch (static device allocations only) ----------------
__device__ float g_sup_t[BB*CC*COLP];            // [b][c][col] transposed support (pad zeroed)
__device__ float g_unl_t[BB*CC*MUP];             // [b][c][m]   transposed unlabeled (pad zeroed)
__device__ float g_unl_n[BB*MU*CC];              // [b][m][c]   row-major normalized unlabeled
__device__ float g_q_t[BB*CC*QROWP];             // [b][c][q*25+mq] transposed query (pads zero)
__device__ float g_cat_t[BB*NWAY*CC*CATP];       // [bw][c][j] = [sup(125) | compacted unl(cw)]
__device__ unsigned long long g_rowbest[BB*MU];  // per (b,m): packed (val,col) argmax
__device__ unsigned long long g_colbest[BB*COLS];// per (b,col): packed (val,m) argmax
__device__ unsigned long long g_rowq[BB*QROWP*NWAY]; // per (b,row,w): packed best over cols
__device__ int g_count[BB*NWAY];
__device__ int g_L[1];

// monotone float ordering map (handles negatives exactly)
__device__ __forceinline__ unsigned fmap(float f){
    unsigned b=__float_as_uint(f);
    return (b&0x80000000u)? ~b : (b|0x80000000u);
}
__device__ __forceinline__ float funmap(unsigned u){
    return (u&0x80000000u)? __uint_as_float(u^0x80000000u) : __uint_as_float(~u);
}
// max-value, min-index-on-tie key (matches jnp first-occurrence argmax)
__device__ __forceinline__ unsigned long long packkey(float v, unsigned idx){
    return (((unsigned long long)fmap(v))<<32) | (unsigned long long)(0xFFFFFFFFu - idx);
}
// packed 2xFP32 FMA (Blackwell f32x2)
__device__ __forceinline__ void fma2(unsigned long long& acc, unsigned long long a, unsigned long long b){
    asm("fma.rn.f32x2 %0, %1, %2, %0;" : "+l"(acc) : "l"(a), "l"(b));
}
__device__ __forceinline__ unsigned long long splat2(float x){
    unsigned long long r;
    asm("mov.b64 %0, {%1, %1};" : "=l"(r) : "r"(__float_as_uint(x)));
    return r;
}
__device__ __forceinline__ void unpack2(unsigned long long v, float& lo, float& hi){
    unsigned a,b;
    asm("mov.b64 {%0, %1}, %2;" : "=r"(a), "=r"(b) : "l"(v));
    lo=__uint_as_float(a); hi=__uint_as_float(b);
}

// ---------------- K0: prep = init + all normalizations ----------------
__global__ void __launch_bounds__(256) k_prep(const float* __restrict__ sup,
                                              const float* __restrict__ unl,
                                              const float* __restrict__ qx,
                                              float* __restrict__ out, int out_size){
    int s = blockIdx.x;
    int tid = threadIdx.x;
    if (s >= 800){
        int i = (s-800)*256 + tid;
        const int stride = 16*256;
        for (int t=i;t<BB*MU;t+=stride) g_rowbest[t]=0ULL;
        for (int t=i;t<BB*COLS;t+=stride) g_colbest[t]=0ULL;
        for (int t=i;t<BB*QROWP*NWAY;t+=stride) g_rowq[t]=0ULL;
        for (int t=i;t<BB*CC*(COLP-COLS);t+=stride){
            int bc=t/(COLP-COLS), p=t%(COLP-COLS);
            g_sup_t[(size_t)bc*COLP+COLS+p]=0.f;
        }
        for (int t=i;t<BB*CC*(MUP-MU);t+=stride){
            int bc=t/(MUP-MU), p=t%(MUP-MU);
            g_unl_t[(size_t)bc*MUP+MU+p]=0.f;
        }
        // pad rows 1875..1919 of g_q_t
        for (int t=i;t<BB*CC*(QROWP-QROWS);t+=stride){
            int bc=t/(QROWP-QROWS), p=t%(QROWP-QROWS);
            g_q_t[(size_t)bc*QROWP+QROWS+p]=0.f;
        }
        if (i==0) g_L[0]=0;
        for (int t=i;t<out_size;t+=stride) out[t]=0.f;
        return;
    }
    __shared__ __align__(16) float tile[1600];
    __shared__ float inv[HWN];
    const float* in;
    if (s<100)      in = sup + (size_t)s*1600;
    else if (s<500) in = unl + (size_t)(s-100)*1600;
    else            in = qx  + (size_t)(s-500)*1600;
    {
        const float4* in4=(const float4*)in;
        float4* t4=(float4*)tile;
        for (int t=tid;t<400;t+=256) t4[t]=in4[t];
    }
    __syncthreads();
    if (tid<HWN){
        float a=0.f;
        for (int c=0;c<CC;++c){ float v=tile[c*HWN+tid]; a=fmaf(v,v,a); }
        inv[tid]=1.0f/fmaxf(sqrtf(a),1e-12f);
    }
    __syncthreads();
    if (s<100){
        int b=s/25, sk=s%25, w=sk/5, k=sk%5;
        int colbase=w*MS+k*25;
        float* outt=g_sup_t+(size_t)b*CC*COLP+colbase;
        float* outc=g_cat_t+(size_t)(b*NWAY+w)*CC*CATP + k*25;
        for (int o=tid;o<1600;o+=256){
            int c=o/HWN,hw=o%HWN;
            float v=tile[o]*inv[hw];
            outt[(size_t)c*COLP+hw]=v;
            outc[(size_t)c*CATP+hw]=v;
        }
    } else if (s<500){
        int t2=s-100; int b=t2/100,u=t2%100;
        float* outt=g_unl_t+(size_t)b*CC*MUP+u*25;
        float* outp=g_unl_n+(size_t)(b*MU+u*25)*CC;
        for (int o=tid;o<1600;o+=256){ int c=o/HWN,hw=o%HWN; outt[(size_t)c*MUP+hw]=tile[o]*inv[hw]; }
        for (int o=tid;o<1600;o+=256){ int hw=o>>6,c=o&63; outp[o]=tile[c*HWN+hw]*inv[hw]; }
    } else {
        int t2=s-500; int b=t2/QQ, q=t2%QQ;
        float* outt=g_q_t+(size_t)b*CC*QROWP + q*25;
        for (int o=tid;o<1600;o+=256){ int c=o/HWN,hw=o%HWN; outt[(size_t)c*QROWP+hw]=tile[o]*inv[hw]; }
    }
}

// ---------------- K1: u2s GEMM (f32x2) + packed row/col argmax ----------------
__global__ void __launch_bounds__(128,3) k_u2s(){
    __shared__ float4 s4[2048];                  // [c][32 f4] = 128 cols (32KB)
    __shared__ float4 u4[2048];                  // [c][32 f4] = 128 m   (32KB)
    __shared__ unsigned long long sm_col[128];
    int mt=blockIdx.x, cp=blockIdx.y, b=blockIdx.z;
    int tid=threadIdx.x, lane=tid&31;
    int ci=tid&7, mi=tid>>3;

    const float4* gs4=(const float4*)g_sup_t + (size_t)b*(CC*COLP/4) + cp*32;
    #pragma unroll
    for (int t=0;t<16;++t){
        int idx=tid+t*128; int c=idx>>5, x=idx&31;
        s4[idx]=gs4[(size_t)c*(COLP/4)+x];
    }
    const float4* gu4=(const float4*)g_unl_t + (size_t)b*(CC*MUP/4) + mt*32;
    #pragma unroll
    for (int t=0;t<16;++t){
        int idx=tid+t*128; int c=idx>>5, x=idx&31;
        u4[idx]=gu4[(size_t)c*(MUP/4)+x];
    }
    sm_col[tid]=0ULL;
    __syncthreads();

    unsigned long long rk[8];
    #pragma unroll
    for (int sdx=0;sdx<8;++sdx) rk[sdx]=0ULL;

    #pragma unroll 1
    for (int h=0; h<2; ++h){
        unsigned long long acc[8][4];
        #pragma unroll
        for (int j=0;j<8;++j)
            #pragma unroll
            for (int k2=0;k2<4;++k2) acc[j][k2]=0ULL;

        #pragma unroll 2
        for (int c=0;c<64;++c){
            float4 a0=s4[c*32+h*16+ci];
            float4 a1=s4[c*32+h*16+8+ci];
            ulonglong2 bb0=*(const ulonglong2*)&u4[c*32+mi];
            ulonglong2 bb1=*(const ulonglong2*)&u4[c*32+16+mi];
            unsigned long long pb0=bb0.x, pb1=bb0.y, pb2=bb1.x, pb3=bb1.y;
            float av[8]={a0.x,a0.y,a0.z,a0.w,a1.x,a1.y,a1.z,a1.w};
            #pragma unroll
            for (int j=0;j<8;++j){
                unsigned long long sa=splat2(av[j]);
                fma2(acc[j][0],sa,pb0);
                fma2(acc[j][1],sa,pb1);
                fma2(acc[j][2],sa,pb2);
                fma2(acc[j][3],sa,pb3);
            }
        }
        #pragma unroll
        for (int j=0;j<8;++j){
            int colj = cp*128 + h*64 + ((j<4)? ci*4+j : 32+ci*4+(j-4));
            bool vc = colj < COLS;
            unsigned long long ck=0ULL;
            #pragma unroll
            for (int k2=0;k2<4;++k2){
                float lo,hi; unpack2(acc[j][k2],lo,hi);
                int mloc = (k2<2)? mi*4+2*k2 : 64+mi*4+2*(k2-2);
                int mglo = mt*128+mloc, mghi = mglo+1;
                if (vc){
                    unsigned long long kl=packkey(lo,(unsigned)colj);
                    unsigned long long kh=packkey(hi,(unsigned)colj);
                    if (kl>rk[2*k2])   rk[2*k2]=kl;
                    if (kh>rk[2*k2+1]) rk[2*k2+1]=kh;
                    if (mglo<MU){ unsigned long long c1=packkey(lo,(unsigned)mglo); if (c1>ck) ck=c1; }
                    if (mghi<MU){ unsigned long long c2=packkey(hi,(unsigned)mghi); if (c2>ck) ck=c2; }
                }
            }
            #pragma unroll
            for (int off=8;off<=16;off<<=1){
                unsigned long long o=__shfl_xor_sync(0xffffffffu,ck,off);
                if (o>ck) ck=o;
            }
            if (lane<8 && ck){
                int local = h*64 + ((j<4)? lane*4+j : 32+lane*4+(j-4));
                atomicMax(&sm_col[local], ck);
            }
        }
    }
    #pragma unroll
    for (int sdx=0;sdx<8;++sdx){
        unsigned long long v=rk[sdx];
        #pragma unroll
        for (int off=1;off<=4;off<<=1){
            unsigned long long o=__shfl_xor_sync(0xffffffffu,v,off);
            if (o>v) v=o;
        }
        if ((lane&7)==0 && v){
            int mloc = (sdx<4)? mi*4+sdx : 64+mi*4+(sdx-4);
            int mg = mt*128+mloc;
            if (mg<MU) atomicMax(&g_rowbest[(size_t)b*MU+mg], v);
        }
    }
    __syncthreads();
    if ((cp*128+tid)<COLS && sm_col[tid])
        atomicMax(&g_colbest[(size_t)b*COLS+cp*128+tid], sm_col[tid]);
}

// ---------------- K2: fused compact + gather (per bw block) -----------------
__global__ void __launch_bounds__(512) k_cg(){
    int bw = blockIdx.x; int b = bw/NWAY, w = bw%NWAY;
    int tid = threadIdx.x, lane = tid&31, wid = tid>>5;   // 16 warps
    __shared__ int sel_s[640];                            // cw <= 625
    __shared__ int wsum[16], woff[16], sbase;
    __shared__ float tile[CC][65];
    if (tid==0) sbase=0;
    __syncthreads();
    for (int chunk=0; chunk<5; ++chunk){
        int m = chunk*512 + tid;
        bool flag = false;
        if (m < MU){
            unsigned long long rb = g_rowbest[b*MU+m];
            unsigned col = 0xFFFFFFFFu - (unsigned)(rb & 0xFFFFFFFFu);
            if ((int)(col/MS) == w){
                unsigned long long cb = g_colbest[b*COLS+col];
                unsigned mm = 0xFFFFFFFFu - (unsigned)(cb & 0xFFFFFFFFu);
                flag = (mm == (unsigned)m);
            }
        }
        unsigned bal = __ballot_sync(0xffffffffu, flag);
        if (lane==0) wsum[wid] = __popc(bal);
        __syncthreads();
        if (tid==0){
            int run=sbase;
            #pragma unroll
            for (int i=0;i<16;++i){ woff[i]=run; run+=wsum[i]; }
            sbase=run;
        }
        __syncthreads();
        if (flag){
            int pos = woff[wid] + __popc(bal & ((1u<<lane)-1u));
            sel_s[pos] = m;
        }
        __syncthreads();
    }
    int cw = sbase;
    if (tid==0){
        g_count[bw] = cw;
        atomicMax(&g_L[0], cw);
    }
    // Phase 2: gather
    const float* __restrict__ unl = g_unl_n + (size_t)b*MU*CC;
    float* __restrict__ cat = g_cat_t + (size_t)bw*CC*CATP + MS;
    for (int jb=0; jb<cw; jb+=64){
        int nj = min(64, cw-jb);
        for (int t=wid; t<nj; t+=16){
            int m = sel_s[jb+t];                             // broadcast per warp
            float2 v = ((const float2*)(unl + (size_t)m*CC))[lane];  // 256B coalesced
            tile[2*lane][t]   = v.x;
            tile[2*lane+1][t] = v.y;
        }
        __syncthreads();
        for (int o=tid; o<CC*64; o+=512){
            int c=o>>6, j=o&63;
            if (j<nj) cat[(size_t)c*CATP + jb + j] = tile[c][j];   // coalesced along j
        }
        __syncthreads();
    }
}

// ---------------- K3: query GEMM (f32x2), persistent over ct tiles ----------
// Grid (15 qt, 20 bw), 256 threads. a4 (q-rows) loaded ONCE; block loops over
// all column tiles of its (qt,bw); row-max keys accumulate in registers across
// tiles; single shfl-reduce + atomics at the end.
__global__ void __launch_bounds__(256,2) k_qsim(){
    int qt=blockIdx.x, bw=blockIdx.y;
    int b=bw/NWAY, w=bw%NWAY;
    int cw=g_count[bw]; int wl=MS+cw;
    int nct=(wl+127)>>7;
    __shared__ float4 a4[2048];                 // q-rows: [c][32 f4] = 128 rows (32KB)
    __shared__ float4 v4[2048];                 // cols:   [c][32 f4] = 128 cols (32KB)
    int tid=threadIdx.x, lane=tid&31, mi=tid>>5;

    const float4* ga=(const float4*)g_q_t + (size_t)b*(CC*QROWP/4) + qt*32;
    #pragma unroll
    for (int t=0;t<8;++t){
        int idx=tid+t*256; int c=idx>>5, x=idx&31;
        a4[idx]=ga[(size_t)c*(QROWP/4)+x];
    }

    unsigned long long rkl[8], rkh[8];
    #pragma unroll
    for (int t=0;t<8;++t){ rkl[t]=0ULL; rkh[t]=0ULL; }

    for (int ct=0; ct<nct; ++ct){
        if (ct) __syncthreads();            // drain previous tile's v4 readers
        const float4* gv=(const float4*)g_cat_t + (size_t)bw*(CC*CATP/4) + ct*32;
        #pragma unroll
        for (int t=0;t<8;++t){
            int idx=tid+t*256; int c=idx>>5, x=idx&31;
            v4[idx]=gv[(size_t)c*(CATP/4)+x];
        }
        __syncthreads();                    // also covers a4 on first iteration

        unsigned long long acc[4][8];
        #pragma unroll
        for (int j=0;j<4;++j)
            #pragma unroll
            for (int t=0;t<8;++t) acc[j][t]=0ULL;

        #pragma unroll 2
        for (int c=0;c<64;++c){
            float4 a = v4[c*32 + lane];                       // 4 col values
            ulonglong2 bb0=*(const ulonglong2*)&a4[c*32 + mi*4];
            ulonglong2 bb1=*(const ulonglong2*)&a4[c*32 + mi*4 + 1];
            ulonglong2 bb2=*(const ulonglong2*)&a4[c*32 + mi*4 + 2];
            ulonglong2 bb3=*(const ulonglong2*)&a4[c*32 + mi*4 + 3];
            unsigned long long pb[8]={bb0.x,bb0.y,bb1.x,bb1.y,bb2.x,bb2.y,bb3.x,bb3.y};
            float av[4]={a.x,a.y,a.z,a.w};
            #pragma unroll
            for (int j=0;j<4;++j){
                unsigned long long sa=splat2(av[j]);
                #pragma unroll
                for (int t=0;t<8;++t) fma2(acc[j][t],sa,pb[t]);
            }
        }

        // accumulate per-thread col-max keys across tiles (no shfl here)
        int col0 = ct*128 + lane*4;
        #pragma unroll
        for (int t=0;t<8;++t){
            #pragma unroll
            for (int j=0;j<4;++j){
                int jg = col0 + j;
                if (jg < wl){
                    float lo,hi; unpack2(acc[j][t],lo,hi);
                    unsigned gcol = (unsigned)(w*MTOT + jg);
                    unsigned long long a1=packkey(lo,gcol);
                    unsigned long long a2=packkey(hi,gcol);
                    if (a1>rkl[t]) rkl[t]=a1;
                    if (a2>rkh[t]) rkh[t]=a2;
                }
            }
        }
    }

    // final warp reduce over the 32 lanes (all columns) + atomics
    #pragma unroll
    for (int t=0;t<8;++t){
        unsigned long long kl=rkl[t], kh=rkh[t];
        #pragma unroll
        for (int off=16;off>=1;off>>=1){
            unsigned long long o1=__shfl_xor_sync(0xffffffffu,kl,off);
            unsigned long long o2=__shfl_xor_sync(0xffffffffu,kh,off);
            if (o1>kl) kl=o1;
            if (o2>kh) kh=o2;
        }
        if (lane==0){
            int r0 = qt*128 + mi*16 + 2*t;
            if (r0<QROWS && kl) atomicMax(&g_rowq[((size_t)b*QROWP + r0)*NWAY + w], kl);
            if (r0+1<QROWS && kh) atomicMax(&g_rowq[((size_t)b*QROWP + r0+1)*NWAY + w], kh);
        }
    }
}

// ---------------- K4: finish = recompute col-argmax + mutual mask + CE ------
__global__ void __launch_bounds__(256) k_fin(const int* __restrict__ qy,
                                             float* __restrict__ out){
    int q=blockIdx.x, b=blockIdx.y;
    int tid=threadIdx.x, lane=tid&31, wp=tid>>5;
    __shared__ float rmx_s[NWAY][32];
    __shared__ unsigned gcol_s[32];
    __shared__ float mask_s[32];
    __shared__ int cnt_s[NWAY+1];
    if (tid<NWAY) cnt_s[tid]=g_count[b*NWAY+tid];
    if (tid==NWAY) cnt_s[NWAY]=g_L[0];
    if (tid<32) mask_s[tid]=0.f;
    __syncthreads();
    // stage 1: per-row (mq) way-maxes and global best column
    if (wp==0 && lane<HWN){
        unsigned long long qb=0ULL;
        #pragma unroll
        for (int w=0;w<NWAY;++w){
            unsigned long long r = g_rowq[((size_t)b*QROWP + q*25 + lane)*NWAY + w];
            int cww=cnt_s[w];
            if (cww < cnt_s[NWAY]){
                // first all-zero pad column of this way: raw cos = 0.0, col id MS+cww
                unsigned long long pk = packkey(0.0f,(unsigned)(w*MTOT+MS+cww));
                if (pk>r) r=pk;
            }
            rmx_s[w][lane]=fmaf(funmap((unsigned)(r>>32)),0.5f,0.5f);
            if (r>qb) qb=r;
        }
        gcol_s[lane]=0xFFFFFFFFu - (unsigned)(qb & 0xFFFFFFFFu);
    }
    __syncthreads();
    // stage 2: per winning column, recompute argmax over mq (bitwise-identical chain)
    for (int t=wp; t<HWN; t+=8){
        unsigned gcol=gcol_s[t];
        int w_=(int)(gcol/MTOT), j_=(int)(gcol%MTOT);
        int amq=0;
        if (j_ < MS + cnt_s[w_]){
            float acc=0.f;
            const float* qp = g_q_t + (size_t)b*CC*QROWP + q*25 + lane;
            const float* cp = g_cat_t + (size_t)(b*NWAY+w_)*CC*CATP + j_;
            if (lane<HWN){
                #pragma unroll
                for (int c=0;c<CC;++c)
                    acc=fmaf(qp[(size_t)c*QROWP], cp[(size_t)c*CATP], acc);
            }
            unsigned long long k = (lane<HWN)? packkey(acc,(unsigned)lane) : 0ULL;
            #pragma unroll
            for (int off=16;off>=1;off>>=1){
                unsigned long long o=__shfl_xor_sync(0xffffffffu,k,off);
                if (o>k) k=o;
            }
            amq = (int)(0xFFFFFFFFu - (unsigned)(k & 0xFFFFFFFFu));
        }
        if (lane==0) mask_s[t] = (amq==t)?1.f:0.f;
    }
    __syncthreads();
    // stage 3: qv + cross-entropy
    if (wp==0){
        float qv[NWAY];
        #pragma unroll
        for (int w=0;w<NWAY;++w){
            float t = (lane<HWN) ? rmx_s[w][lane]*mask_s[lane] : 0.f;
            #pragma unroll
            for (int off=16;off>=1;off>>=1) t += __shfl_xor_sync(0xffffffffu,t,off);
            qv[w]=t;
        }
        if (lane==0){
            int y = qy[b*QQ+q];
            float mx=qv[0];
            #pragma unroll
            for (int w=1;w<NWAY;++w) mx=fmaxf(mx,qv[w]);
            float se=0.f;
            #pragma unroll
            for (int w=0;w<NWAY;++w) se += expf(qv[w]-mx);
            float li = mx + logf(se) - qv[y];
            atomicAdd(out, li*(1.0f/(float)(BB*QQ)));
        }
    }
}

// ---------------- launch ----------------
extern "C" void kernel_launch(void* const* d_in, const int* in_sizes, int n_in,
                              void* d_out, int out_size) {
    const float* sup = nullptr;
    const float* qx  = nullptr;
    const float* ux  = nullptr;
    const int*   qy  = nullptr;
    for (int i=0;i<n_in;++i){
        switch (in_sizes[i]){
            case 160000: sup = (const float*)d_in[i]; break; // support_xf
            case 480000: qx  = (const float*)d_in[i]; break; // query_xf
            case 640000: ux  = (const float*)d_in[i]; break; // unlabeled_xf
            case 300:    qy  = (const int*)d_in[i];   break; // query_y
            default: break;                                  // support_y unused
        }
    }
    float* out = (float*)d_out;
    k_prep<<<816,256>>>(sup, ux, qx, out, out_size);
    k_u2s<<<dim3(20,5,BB),128>>>();
    k_cg<<<BB*NWAY,512>>>();
    k_qsim<<<dim3(15,BB*NWAY),256>>>();
    k_fin<<<dim3(QQ,BB),256>>>(qy, out);
}

// round 12
// speedup vs baseline: 1.1372x; 1.0014x over previous
#include <cuda_runtime.h>
#include <math.h>

#define NWAY 5
#define BB 4
#define CC 64
#define HWN 25
#define MS 125      // K_SHOT * h * w
#define MU 2500     // u * h * w
#define QQ 75
#define COLS 625    // NWAY * MS
#define MTOT 2625   // MS + MU
#define COLP 640    // padded cols for transposed support
#define MUP 2560    // padded m for transposed unlabeled
#define QROWS 1875  // 75 q * 25 rows (packed)
#define QROWP 1920  // padded to 30*64
#define CATP 2688   // padded cat columns (21*128)

// ---------------- scratch (static device allocations only) ----------------
__device__ float g_sup_t[BB*CC*COLP];            // [b][c][col] transposed support (pad zeroed)
__device__ float g_unl_t[BB*CC*MUP];             // [b][c][m]   transposed unlabeled (pad zeroed)
__device__ float g_unl_n[BB*MU*CC];              // [b][m][c]   row-major normalized unlabeled
__device__ float g_q_t[BB*CC*QROWP];             // [b][c][q*25+mq] transposed query (pads zero)
__device__ float g_cat_t[BB*NWAY*CC*CATP];       // [bw][c][j] = [sup(125) | compacted unl(cw)]
__device__ unsigned long long g_rowbest[BB*MU];  // per (b,m): packed (val,col) argmax
__device__ unsigned long long g_colbest[BB*COLS];// per (b,col): packed (val,m) argmax
__device__ unsigned long long g_rowq[BB*QROWP*NWAY]; // per (b,row,w): packed best over cols
__device__ int g_count[BB*NWAY];
__device__ int g_L[1];

// monotone float ordering map (handles negatives exactly)
__device__ __forceinline__ unsigned fmap(float f){
    unsigned b=__float_as_uint(f);
    return (b&0x80000000u)? ~b : (b|0x80000000u);
}
__device__ __forceinline__ float funmap(unsigned u){
    return (u&0x80000000u)? __uint_as_float(u^0x80000000u) : __uint_as_float(~u);
}
// max-value, min-index-on-tie key (matches jnp first-occurrence argmax)
__device__ __forceinline__ unsigned long long packkey(float v, unsigned idx){
    return (((unsigned long long)fmap(v))<<32) | (unsigned long long)(0xFFFFFFFFu - idx);
}
// packed 2xFP32 FMA (Blackwell f32x2)
__device__ __forceinline__ void fma2(unsigned long long& acc, unsigned long long a, unsigned long long b){
    asm("fma.rn.f32x2 %0, %1, %2, %0;" : "+l"(acc) : "l"(a), "l"(b));
}
__device__ __forceinline__ unsigned long long splat2(float x){
    unsigned long long r;
    asm("mov.b64 %0, {%1, %1};" : "=l"(r) : "r"(__float_as_uint(x)));
    return r;
}
__device__ __forceinline__ void unpack2(unsigned long long v, float& lo, float& hi){
    unsigned a,b;
    asm("mov.b64 {%0, %1}, %2;" : "=r"(a), "=r"(b) : "l"(v));
    lo=__uint_as_float(a); hi=__uint_as_float(b);
}

// ---------------- K0: prep = init + all normalizations ----------------
__global__ void __launch_bounds__(256) k_prep(const float* __restrict__ sup,
                                              const float* __restrict__ unl,
                                              const float* __restrict__ qx,
                                              float* __restrict__ out, int out_size){
    int s = blockIdx.x;
    int tid = threadIdx.x;
    if (s >= 800){
        int i = (s-800)*256 + tid;
        const int stride = 16*256;
        for (int t=i;t<BB*MU;t+=stride) g_rowbest[t]=0ULL;
        for (int t=i;t<BB*COLS;t+=stride) g_colbest[t]=0ULL;
        for (int t=i;t<BB*QROWP*NWAY;t+=stride) g_rowq[t]=0ULL;
        for (int t=i;t<BB*CC*(COLP-COLS);t+=stride){
            int bc=t/(COLP-COLS), p=t%(COLP-COLS);
            g_sup_t[(size_t)bc*COLP+COLS+p]=0.f;
        }
        for (int t=i;t<BB*CC*(MUP-MU);t+=stride){
            int bc=t/(MUP-MU), p=t%(MUP-MU);
            g_unl_t[(size_t)bc*MUP+MU+p]=0.f;
        }
        // pad rows 1875..1919 of g_q_t
        for (int t=i;t<BB*CC*(QROWP-QROWS);t+=stride){
            int bc=t/(QROWP-QROWS), p=t%(QROWP-QROWS);
            g_q_t[(size_t)bc*QROWP+QROWS+p]=0.f;
        }
        if (i==0) g_L[0]=0;
        for (int t=i;t<out_size;t+=stride) out[t]=0.f;
        return;
    }
    __shared__ __align__(16) float tile[1600];
    __shared__ float inv[HWN];
    const float* in;
    if (s<100)      in = sup + (size_t)s*1600;
    else if (s<500) in = unl + (size_t)(s-100)*1600;
    else            in = qx  + (size_t)(s-500)*1600;
    {
        const float4* in4=(const float4*)in;
        float4* t4=(float4*)tile;
        for (int t=tid;t<400;t+=256) t4[t]=in4[t];
    }
    __syncthreads();
    if (tid<HWN){
        float a=0.f;
        for (int c=0;c<CC;++c){ float v=tile[c*HWN+tid]; a=fmaf(v,v,a); }
        inv[tid]=1.0f/fmaxf(sqrtf(a),1e-12f);
    }
    __syncthreads();
    if (s<100){
        int b=s/25, sk=s%25, w=sk/5, k=sk%5;
        int colbase=w*MS+k*25;
        float* outt=g_sup_t+(size_t)b*CC*COLP+colbase;
        float* outc=g_cat_t+(size_t)(b*NWAY+w)*CC*CATP + k*25;
        for (int o=tid;o<1600;o+=256){
            int c=o/HWN,hw=o%HWN;
            float v=tile[o]*inv[hw];
            outt[(size_t)c*COLP+hw]=v;
            outc[(size_t)c*CATP+hw]=v;
        }
    } else if (s<500){
        int t2=s-100; int b=t2/100,u=t2%100;
        float* outt=g_unl_t+(size_t)b*CC*MUP+u*25;
        float* outp=g_unl_n+(size_t)(b*MU+u*25)*CC;
        for (int o=tid;o<1600;o+=256){ int c=o/HWN,hw=o%HWN; outt[(size_t)c*MUP+hw]=tile[o]*inv[hw]; }
        for (int o=tid;o<1600;o+=256){ int hw=o>>6,c=o&63; outp[o]=tile[c*HWN+hw]*inv[hw]; }
    } else {
        int t2=s-500; int b=t2/QQ, q=t2%QQ;
        float* outt=g_q_t+(size_t)b*CC*QROWP + q*25;
        for (int o=tid;o<1600;o+=256){ int c=o/HWN,hw=o%HWN; outt[(size_t)c*QROWP+hw]=tile[o]*inv[hw]; }
    }
}

// ---------------- K1: u2s GEMM (f32x2) + packed row/col argmax ----------------
__global__ void __launch_bounds__(128,4) k_u2s(){
    __shared__ float4 s4[2048];                  // [c][32 f4] = 128 cols (32KB)
    __shared__ float4 u4[2048];                  // [c][32 f4] = 128 m   (32KB)
    __shared__ unsigned long long sm_col[128];
    int mt=blockIdx.x, cp=blockIdx.y, b=blockIdx.z;
    int tid=threadIdx.x, lane=tid&31;
    int ci=tid&7, mi=tid>>3;

    const float4* gs4=(const float4*)g_sup_t + (size_t)b*(CC*COLP/4) + cp*32;
    #pragma unroll
    for (int t=0;t<16;++t){
        int idx=tid+t*128; int c=idx>>5, x=idx&31;
        s4[idx]=gs4[(size_t)c*(COLP/4)+x];
    }
    const float4* gu4=(const float4*)g_unl_t + (size_t)b*(CC*MUP/4) + mt*32;
    #pragma unroll
    for (int t=0;t<16;++t){
        int idx=tid+t*128; int c=idx>>5, x=idx&31;
        u4[idx]=gu4[(size_t)c*(MUP/4)+x];
    }
    sm_col[tid]=0ULL;
    __syncthreads();

    unsigned long long rk[8];
    #pragma unroll
    for (int sdx=0;sdx<8;++sdx) rk[sdx]=0ULL;

    #pragma unroll 1
    for (int h=0; h<2; ++h){
        unsigned long long acc[8][4];
        #pragma unroll
        for (int j=0;j<8;++j)
            #pragma unroll
            for (int k2=0;k2<4;++k2) acc[j][k2]=0ULL;

        #pragma unroll 2
        for (int c=0;c<64;++c){
            float4 a0=s4[c*32+h*16+ci];
            float4 a1=s4[c*32+h*16+8+ci];
            ulonglong2 bb0=*(const ulonglong2*)&u4[c*32+mi];
            ulonglong2 bb1=*(const ulonglong2*)&u4[c*32+16+mi];
            unsigned long long pb0=bb0.x, pb1=bb0.y, pb2=bb1.x, pb3=bb1.y;
            float av[8]={a0.x,a0.y,a0.z,a0.w,a1.x,a1.y,a1.z,a1.w};
            #pragma unroll
            for (int j=0;j<8;++j){
                unsigned long long sa=splat2(av[j]);
                fma2(acc[j][0],sa,pb0);
                fma2(acc[j][1],sa,pb1);
                fma2(acc[j][2],sa,pb2);
                fma2(acc[j][3],sa,pb3);
            }
        }
        #pragma unroll
        for (int j=0;j<8;++j){
            int colj = cp*128 + h*64 + ((j<4)? ci*4+j : 32+ci*4+(j-4));
            bool vc = colj < COLS;
            unsigned long long ck=0ULL;
            #pragma unroll
            for (int k2=0;k2<4;++k2){
                float lo,hi; unpack2(acc[j][k2],lo,hi);
                int mloc = (k2<2)? mi*4+2*k2 : 64+mi*4+2*(k2-2);
                int mglo = mt*128+mloc, mghi = mglo+1;
                if (vc){
                    unsigned long long kl=packkey(lo,(unsigned)colj);
                    unsigned long long kh=packkey(hi,(unsigned)colj);
                    if (kl>rk[2*k2])   rk[2*k2]=kl;
                    if (kh>rk[2*k2+1]) rk[2*k2+1]=kh;
                    if (mglo<MU){ unsigned long long c1=packkey(lo,(unsigned)mglo); if (c1>ck) ck=c1; }
                    if (mghi<MU){ unsigned long long c2=packkey(hi,(unsigned)mghi); if (c2>ck) ck=c2; }
                }
            }
            #pragma unroll
            for (int off=8;off<=16;off<<=1){
                unsigned long long o=__shfl_xor_sync(0xffffffffu,ck,off);
                if (o>ck) ck=o;
            }
            if (lane<8 && ck){
                int local = h*64 + ((j<4)? lane*4+j : 32+lane*4+(j-4));
                atomicMax(&sm_col[local], ck);
            }
        }
    }
    #pragma unroll
    for (int sdx=0;sdx<8;++sdx){
        unsigned long long v=rk[sdx];
        #pragma unroll
        for (int off=1;off<=4;off<<=1){
            unsigned long long o=__shfl_xor_sync(0xffffffffu,v,off);
            if (o>v) v=o;
        }
        if ((lane&7)==0 && v){
            int mloc = (sdx<4)? mi*4+sdx : 64+mi*4+(sdx-4);
            int mg = mt*128+mloc;
            if (mg<MU) atomicMax(&g_rowbest[(size_t)b*MU+mg], v);
        }
    }
    __syncthreads();
    if ((cp*128+tid)<COLS && sm_col[tid])
        atomicMax(&g_colbest[(size_t)b*COLS+cp*128+tid], sm_col[tid]);
}

// ---------------- K2: fused compact + gather (per bw block) -----------------
__global__ void __launch_bounds__(512) k_cg(){
    int bw = blockIdx.x; int b = bw/NWAY, w = bw%NWAY;
    int tid = threadIdx.x, lane = tid&31, wid = tid>>5;   // 16 warps
    __shared__ int sel_s[640];                            // cw <= 625
    __shared__ int wsum[16], woff[16], sbase;
    __shared__ float tile[CC][65];
    if (tid==0) sbase=0;
    __syncthreads();
    for (int chunk=0; chunk<5; ++chunk){
        int m = chunk*512 + tid;
        bool flag = false;
        if (m < MU){
            unsigned long long rb = g_rowbest[b*MU+m];
            unsigned col = 0xFFFFFFFFu - (unsigned)(rb & 0xFFFFFFFFu);
            if ((int)(col/MS) == w){
                unsigned long long cb = g_colbest[b*COLS+col];
                unsigned mm = 0xFFFFFFFFu - (unsigned)(cb & 0xFFFFFFFFu);
                flag = (mm == (unsigned)m);
            }
        }
        unsigned bal = __ballot_sync(0xffffffffu, flag);
        if (lane==0) wsum[wid] = __popc(bal);
        __syncthreads();
        if (tid==0){
            int run=sbase;
            #pragma unroll
            for (int i=0;i<16;++i){ woff[i]=run; run+=wsum[i]; }
            sbase=run;
        }
        __syncthreads();
        if (flag){
            int pos = woff[wid] + __popc(bal & ((1u<<lane)-1u));
            sel_s[pos] = m;
        }
        __syncthreads();
    }
    int cw = sbase;
    if (tid==0){
        g_count[bw] = cw;
        atomicMax(&g_L[0], cw);
    }
    // Phase 2: gather
    const float* __restrict__ unl = g_unl_n + (size_t)b*MU*CC;
    float* __restrict__ cat = g_cat_t + (size_t)bw*CC*CATP + MS;
    for (int jb=0; jb<cw; jb+=64){
        int nj = min(64, cw-jb);
        for (int t=wid; t<nj; t+=16){
            int m = sel_s[jb+t];                             // broadcast per warp
            float2 v = ((const float2*)(unl + (size_t)m*CC))[lane];  // 256B coalesced
            tile[2*lane][t]   = v.x;
            tile[2*lane+1][t] = v.y;
        }
        __syncthreads();
        for (int o=tid; o<CC*64; o+=512){
            int c=o>>6, j=o&63;
            if (j<nj) cat[(size_t)c*CATP + jb + j] = tile[c][j];   // coalesced along j
        }
        __syncthreads();
    }
}

// ---------------- K3: query GEMM (f32x2), 64-row tiles, persistent over ct --
// Grid (30 qt, 20 bw), 256 threads, 3 blocks/SM. a4 (64 q-rows, 16KB) loaded
// once; loop over column tiles; row-max keys accumulate in regs across tiles.
__global__ void __launch_bounds__(256,3) k_qsim(){
    int qt=blockIdx.x, bw=blockIdx.y;
    int b=bw/NWAY, w=bw%NWAY;
    int cw=g_count[bw]; int wl=MS+cw;
    int nct=(wl+127)>>7;
    __shared__ float4 a4[1024];                 // q-rows: [c][16 f4] = 64 rows (16KB)
    __shared__ float4 v4[2048];                 // cols:   [c][32 f4] = 128 cols (32KB)
    int tid=threadIdx.x, lane=tid&31, mi=tid>>5;   // warp owns rows mi*8..mi*8+7

    const float4* ga=(const float4*)g_q_t + (size_t)b*(CC*QROWP/4) + qt*16;
    #pragma unroll
    for (int t=0;t<4;++t){
        int idx=tid+t*256; int c=idx>>4, x=idx&15;
        a4[idx]=ga[(size_t)c*(QROWP/4)+x];
    }

    unsigned long long rkl[4], rkh[4];
    #pragma unroll
    for (int t=0;t<4;++t){ rkl[t]=0ULL; rkh[t]=0ULL; }

    for (int ct=0; ct<nct; ++ct){
        if (ct) __syncthreads();            // drain previous tile's v4 readers
        const float4* gv=(const float4*)g_cat_t + (size_t)bw*(CC*CATP/4) + ct*32;
        #pragma unroll
        for (int t=0;t<8;++t){
            int idx=tid+t*256; int c=idx>>5, x=idx&31;
            v4[idx]=gv[(size_t)c*(CATP/4)+x];
        }
        __syncthreads();                    // also covers a4 on first iteration

        unsigned long long acc[4][4];
        #pragma unroll
        for (int j=0;j<4;++j)
            #pragma unroll
            for (int t=0;t<4;++t) acc[j][t]=0ULL;

        #pragma unroll 4
        for (int c=0;c<64;++c){
            float4 a = v4[c*32 + lane];                       // 4 col values
            ulonglong2 bb0=*(const ulonglong2*)&a4[c*16 + mi*2];      // rows mi*8..+3
            ulonglong2 bb1=*(const ulonglong2*)&a4[c*16 + mi*2 + 1];  // rows mi*8+4..+7
            unsigned long long pb[4]={bb0.x,bb0.y,bb1.x,bb1.y};
            float av[4]={a.x,a.y,a.z,a.w};
            #pragma unroll
            for (int j=0;j<4;++j){
                unsigned long long sa=splat2(av[j]);
                #pragma unroll
                for (int t=0;t<4;++t) fma2(acc[j][t],sa,pb[t]);
            }
        }

        // accumulate per-thread col-max keys across tiles (no shfl here)
        int col0 = ct*128 + lane*4;
        #pragma unroll
        for (int t=0;t<4;++t){
            #pragma unroll
            for (int j=0;j<4;++j){
                int jg = col0 + j;
                if (jg < wl){
                    float lo,hi; unpack2(acc[j][t],lo,hi);
                    unsigned gcol = (unsigned)(w*MTOT + jg);
                    unsigned long long a1=packkey(lo,gcol);
                    unsigned long long a2=packkey(hi,gcol);
                    if (a1>rkl[t]) rkl[t]=a1;
                    if (a2>rkh[t]) rkh[t]=a2;
                }
            }
        }
    }

    // final warp reduce over the 32 lanes (all columns) + atomics
    #pragma unroll
    for (int t=0;t<4;++t){
        unsigned long long kl=rkl[t], kh=rkh[t];
        #pragma unroll
        for (int off=16;off>=1;off>>=1){
            unsigned long long o1=__shfl_xor_sync(0xffffffffu,kl,off);
            unsigned long long o2=__shfl_xor_sync(0xffffffffu,kh,off);
            if (o1>kl) kl=o1;
            if (o2>kh) kh=o2;
        }
        if (lane==0){
            int r0 = qt*64 + mi*8 + 2*t;
            if (r0<QROWS && kl) atomicMax(&g_rowq[((size_t)b*QROWP + r0)*NWAY + w], kl);
            if (r0+1<QROWS && kh) atomicMax(&g_rowq[((size_t)b*QROWP + r0+1)*NWAY + w], kh);
        }
    }
}

// ---------------- K4: finish = recompute col-argmax + mutual mask + CE ------
__global__ void __launch_bounds__(256) k_fin(const int* __restrict__ qy,
                                             float* __restrict__ out){
    int q=blockIdx.x, b=blockIdx.y;
    int tid=threadIdx.x, lane=tid&31, wp=tid>>5;
    __shared__ float rmx_s[NWAY][32];
    __shared__ unsigned gcol_s[32];
    __shared__ float mask_s[32];
    __shared__ int cnt_s[NWAY+1];
    if (tid<NWAY) cnt_s[tid]=g_count[b*NWAY+tid];
    if (tid==NWAY) cnt_s[NWAY]=g_L[0];
    if (tid<32) mask_s[tid]=0.f;
    __syncthreads();
    // stage 1: per-row (mq) way-maxes and global best column
    if (wp==0 && lane<HWN){
        unsigned long long qb=0ULL;
        #pragma unroll
        for (int w=0;w<NWAY;++w){
            unsigned long long r = g_rowq[((size_t)b*QROWP + q*25 + lane)*NWAY + w];
            int cww=cnt_s[w];
            if (cww < cnt_s[NWAY]){
                // first all-zero pad column of this way: raw cos = 0.0, col id MS+cww
                unsigned long long pk = packkey(0.0f,(unsigned)(w*MTOT+MS+cww));
                if (pk>r) r=pk;
            }
            rmx_s[w][lane]=fmaf(funmap((unsigned)(r>>32)),0.5f,0.5f);
            if (r>qb) qb=r;
        }
        gcol_s[lane]=0xFFFFFFFFu - (unsigned)(qb & 0xFFFFFFFFu);
    }
    __syncthreads();
    // stage 2: per winning column, recompute argmax over mq (bitwise-identical chain)
    for (int t=wp; t<HWN; t+=8){
        unsigned gcol=gcol_s[t];
        int w_=(int)(gcol/MTOT), j_=(int)(gcol%MTOT);
        int amq=0;
        if (j_ < MS + cnt_s[w_]){
            float acc=0.f;
            const float* qp = g_q_t + (size_t)b*CC*QROWP + q*25 + lane;
            const float* cp = g_cat_t + (size_t)(b*NWAY+w_)*CC*CATP + j_;
            if (lane<HWN){
                #pragma unroll
                for (int c=0;c<CC;++c)
                    acc=fmaf(qp[(size_t)c*QROWP], cp[(size_t)c*CATP], acc);
            }
            unsigned long long k = (lane<HWN)? packkey(acc,(unsigned)lane) : 0ULL;
            #pragma unroll
            for (int off=16;off>=1;off>>=1){
                unsigned long long o=__shfl_xor_sync(0xffffffffu,k,off);
                if (o>k) k=o;
            }
            amq = (int)(0xFFFFFFFFu - (unsigned)(k & 0xFFFFFFFFu));
        }
        if (lane==0) mask_s[t] = (amq==t)?1.f:0.f;
    }
    __syncthreads();
    // stage 3: qv + cross-entropy
    if (wp==0){
        float qv[NWAY];
        #pragma unroll
        for (int w=0;w<NWAY;++w){
            float t = (lane<HWN) ? rmx_s[w][lane]*mask_s[lane] : 0.f;
            #pragma unroll
            for (int off=16;off>=1;off>>=1) t += __shfl_xor_sync(0xffffffffu,t,off);
            qv[w]=t;
        }
        if (lane==0){
            int y = qy[b*QQ+q];
            float mx=qv[0];
            #pragma unroll
            for (int w=1;w<NWAY;++w) mx=fmaxf(mx,qv[w]);
            float se=0.f;
            #pragma unroll
            for (int w=0;w<NWAY;++w) se += expf(qv[w]-mx);
            float li = mx + logf(se) - qv[y];
            atomicAdd(out, li*(1.0f/(float)(BB*QQ)));
        }
    }
}

// ---------------- launch ----------------
extern "C" void kernel_launch(void* const* d_in, const int* in_sizes, int n_in,
                              void* d_out, int out_size) {
    const float* sup = nullptr;
    const float* qx  = nullptr;
    const float* ux  = nullptr;
    const int*   qy  = nullptr;
    for (int i=0;i<n_in;++i){
        switch (in_sizes[i]){
            case 160000: sup = (const float*)d_in[i]; break; // support_xf
            case 480000: qx  = (const float*)d_in[i]; break; // query_xf
            case 640000: ux  = (const float*)d_in[i]; break; // unlabeled_xf
            case 300:    qy  = (const int*)d_in[i];   break; // query_y
            default: break;                                  // support_y unused
        }
    }
    float* out = (float*)d_out;
    k_prep<<<816,256>>>(sup, ux, qx, out, out_size);
    k_u2s<<<dim3(20,5,BB),128>>>();
    k_cg<<<BB*NWAY,512>>>();
    k_qsim<<<dim3(30,BB*NWAY),256>>>();
    k_fin<<<dim3(QQ,BB),256>>>(qy, out);
}

// round 13
// speedup vs baseline: 1.1864x; 1.0433x over previous
#include <cuda_runtime.h>
#include <math.h>

#define NWAY 5
#define BB 4
#define CC 64
#define HWN 25
#define MS 125      // K_SHOT * h * w
#define MU 2500     // u * h * w
#define QQ 75
#define COLS 625    // NWAY * MS
#define MTOT 2625   // MS + MU
#define COLP 640    // padded cols for transposed support
#define MUP 2560    // padded m for transposed unlabeled
#define QROWS 1875  // 75 q * 25 rows (packed)
#define QROWP 1920  // padded to 15*128
#define CATP 2688   // padded cat columns (21*128)

// ---------------- scratch (static device allocations only) ----------------
__device__ float g_sup_t[BB*CC*COLP];            // [b][c][col] transposed support (pad zeroed)
__device__ float g_unl_t[BB*CC*MUP];             // [b][c][m]   transposed unlabeled (pad zeroed)
__device__ float g_unl_n[BB*MU*CC];              // [b][m][c]   row-major normalized unlabeled
__device__ float g_q_t[BB*CC*QROWP];             // [b][c][q*25+mq] transposed query (pads zero)
__device__ float g_cat_t[BB*NWAY*CC*CATP];       // [bw][c][j] = [sup(125) | compacted unl(cw)]
__device__ unsigned long long g_rowbest[BB*MU];  // per (b,m): packed (val,col) argmax
__device__ unsigned long long g_colbest[BB*COLS];// per (b,col): packed (val,m) argmax
__device__ unsigned long long g_rowq[BB*QROWP*NWAY]; // per (b,row,w): packed best over cols
__device__ int g_count[BB*NWAY];
__device__ int g_L[1];

// monotone float ordering map (handles negatives exactly)
__device__ __forceinline__ unsigned fmap(float f){
    unsigned b=__float_as_uint(f);
    return (b&0x80000000u)? ~b : (b|0x80000000u);
}
__device__ __forceinline__ float funmap(unsigned u){
    return (u&0x80000000u)? __uint_as_float(u^0x80000000u) : __uint_as_float(~u);
}
// max-value, min-index-on-tie key (matches jnp first-occurrence argmax)
__device__ __forceinline__ unsigned long long packkey(float v, unsigned idx){
    return (((unsigned long long)fmap(v))<<32) | (unsigned long long)(0xFFFFFFFFu - idx);
}
// packed 2xFP32 FMA (Blackwell f32x2)
__device__ __forceinline__ void fma2(unsigned long long& acc, unsigned long long a, unsigned long long b){
    asm("fma.rn.f32x2 %0, %1, %2, %0;" : "+l"(acc) : "l"(a), "l"(b));
}
__device__ __forceinline__ unsigned long long splat2(float x){
    unsigned long long r;
    asm("mov.b64 %0, {%1, %1};" : "=l"(r) : "r"(__float_as_uint(x)));
    return r;
}
__device__ __forceinline__ void unpack2(unsigned long long v, float& lo, float& hi){
    unsigned a,b;
    asm("mov.b64 {%0, %1}, %2;" : "=r"(a), "=r"(b) : "l"(v));
    lo=__uint_as_float(a); hi=__uint_as_float(b);
}

// ---------------- K0: prep = init + all normalizations ----------------
__global__ void __launch_bounds__(256) k_prep(const float* __restrict__ sup,
                                              const float* __restrict__ unl,
                                              const float* __restrict__ qx,
                                              float* __restrict__ out, int out_size){
    int s = blockIdx.x;
    int tid = threadIdx.x;
    if (s >= 800){
        int i = (s-800)*256 + tid;
        const int stride = 16*256;
        for (int t=i;t<BB*MU;t+=stride) g_rowbest[t]=0ULL;
        for (int t=i;t<BB*COLS;t+=stride) g_colbest[t]=0ULL;
        for (int t=i;t<BB*QROWP*NWAY;t+=stride) g_rowq[t]=0ULL;
        for (int t=i;t<BB*CC*(COLP-COLS);t+=stride){
            int bc=t/(COLP-COLS), p=t%(COLP-COLS);
            g_sup_t[(size_t)bc*COLP+COLS+p]=0.f;
        }
        for (int t=i;t<BB*CC*(MUP-MU);t+=stride){
            int bc=t/(MUP-MU), p=t%(MUP-MU);
            g_unl_t[(size_t)bc*MUP+MU+p]=0.f;
        }
        // pad rows 1875..1919 of g_q_t
        for (int t=i;t<BB*CC*(QROWP-QROWS);t+=stride){
            int bc=t/(QROWP-QROWS), p=t%(QROWP-QROWS);
            g_q_t[(size_t)bc*QROWP+QROWS+p]=0.f;
        }
        if (i==0) g_L[0]=0;
        for (int t=i;t<out_size;t+=stride) out[t]=0.f;
        return;
    }
    __shared__ __align__(16) float tile[1600];
    __shared__ float inv[HWN];
    const float* in;
    if (s<100)      in = sup + (size_t)s*1600;
    else if (s<500) in = unl + (size_t)(s-100)*1600;
    else            in = qx  + (size_t)(s-500)*1600;
    {
        const float4* in4=(const float4*)in;
        float4* t4=(float4*)tile;
        for (int t=tid;t<400;t+=256) t4[t]=in4[t];
    }
    __syncthreads();
    if (tid<HWN){
        float a=0.f;
        for (int c=0;c<CC;++c){ float v=tile[c*HWN+tid]; a=fmaf(v,v,a); }
        inv[tid]=1.0f/fmaxf(sqrtf(a),1e-12f);
    }
    __syncthreads();
    if (s<100){
        int b=s/25, sk=s%25, w=sk/5, k=sk%5;
        int colbase=w*MS+k*25;
        float* outt=g_sup_t+(size_t)b*CC*COLP+colbase;
        float* outc=g_cat_t+(size_t)(b*NWAY+w)*CC*CATP + k*25;
        for (int o=tid;o<1600;o+=256){
            int c=o/HWN,hw=o%HWN;
            float v=tile[o]*inv[hw];
            outt[(size_t)c*COLP+hw]=v;
            outc[(size_t)c*CATP+hw]=v;
        }
    } else if (s<500){
        int t2=s-100; int b=t2/100,u=t2%100;
        float* outt=g_unl_t+(size_t)b*CC*MUP+u*25;
        float* outp=g_unl_n+(size_t)(b*MU+u*25)*CC;
        for (int o=tid;o<1600;o+=256){ int c=o/HWN,hw=o%HWN; outt[(size_t)c*MUP+hw]=tile[o]*inv[hw]; }
        for (int o=tid;o<1600;o+=256){ int hw=o>>6,c=o&63; outp[o]=tile[c*HWN+hw]*inv[hw]; }
    } else {
        int t2=s-500; int b=t2/QQ, q=t2%QQ;
        float* outt=g_q_t+(size_t)b*CC*QROWP + q*25;
        for (int o=tid;o<1600;o+=256){ int c=o/HWN,hw=o%HWN; outt[(size_t)c*QROWP+hw]=tile[o]*inv[hw]; }
    }
}

// ---------------- K1: u2s GEMM (f32x2) + packed row/col argmax ----------------
__global__ void __launch_bounds__(128,4) k_u2s(){
    __shared__ float4 s4[2048];                  // [c][32 f4] = 128 cols (32KB)
    __shared__ float4 u4[2048];                  // [c][32 f4] = 128 m   (32KB)
    __shared__ unsigned long long sm_col[128];
    int mt=blockIdx.x, cp=blockIdx.y, b=blockIdx.z;
    int tid=threadIdx.x, lane=tid&31;
    int ci=tid&7, mi=tid>>3;

    const float4* gs4=(const float4*)g_sup_t + (size_t)b*(CC*COLP/4) + cp*32;
    #pragma unroll
    for (int t=0;t<16;++t){
        int idx=tid+t*128; int c=idx>>5, x=idx&31;
        s4[idx]=gs4[(size_t)c*(COLP/4)+x];
    }
    const float4* gu4=(const float4*)g_unl_t + (size_t)b*(CC*MUP/4) + mt*32;
    #pragma unroll
    for (int t=0;t<16;++t){
        int idx=tid+t*128; int c=idx>>5, x=idx&31;
        u4[idx]=gu4[(size_t)c*(MUP/4)+x];
    }
    sm_col[tid]=0ULL;
    __syncthreads();

    unsigned long long rk[8];
    #pragma unroll
    for (int sdx=0;sdx<8;++sdx) rk[sdx]=0ULL;

    #pragma unroll 1
    for (int h=0; h<2; ++h){
        unsigned long long acc[8][4];
        #pragma unroll
        for (int j=0;j<8;++j)
            #pragma unroll
            for (int k2=0;k2<4;++k2) acc[j][k2]=0ULL;

        #pragma unroll 2
        for (int c=0;c<64;++c){
            float4 a0=s4[c*32+h*16+ci];
            float4 a1=s4[c*32+h*16+8+ci];
            ulonglong2 bb0=*(const ulonglong2*)&u4[c*32+mi];
            ulonglong2 bb1=*(const ulonglong2*)&u4[c*32+16+mi];
            unsigned long long pb0=bb0.x, pb1=bb0.y, pb2=bb1.x, pb3=bb1.y;
            float av[8]={a0.x,a0.y,a0.z,a0.w,a1.x,a1.y,a1.z,a1.w};
            #pragma unroll
            for (int j=0;j<8;++j){
                unsigned long long sa=splat2(av[j]);
                fma2(acc[j][0],sa,pb0);
                fma2(acc[j][1],sa,pb1);
                fma2(acc[j][2],sa,pb2);
                fma2(acc[j][3],sa,pb3);
            }
        }
        #pragma unroll
        for (int j=0;j<8;++j){
            int colj = cp*128 + h*64 + ((j<4)? ci*4+j : 32+ci*4+(j-4));
            bool vc = colj < COLS;
            unsigned long long ck=0ULL;
            #pragma unroll
            for (int k2=0;k2<4;++k2){
                float lo,hi; unpack2(acc[j][k2],lo,hi);
                int mloc = (k2<2)? mi*4+2*k2 : 64+mi*4+2*(k2-2);
                int mglo = mt*128+mloc, mghi = mglo+1;
                if (vc){
                    unsigned long long kl=packkey(lo,(unsigned)colj);
                    unsigned long long kh=packkey(hi,(unsigned)colj);
                    if (kl>rk[2*k2])   rk[2*k2]=kl;
                    if (kh>rk[2*k2+1]) rk[2*k2+1]=kh;
                    if (mglo<MU){ unsigned long long c1=packkey(lo,(unsigned)mglo); if (c1>ck) ck=c1; }
                    if (mghi<MU){ unsigned long long c2=packkey(hi,(unsigned)mghi); if (c2>ck) ck=c2; }
                }
            }
            #pragma unroll
            for (int off=8;off<=16;off<<=1){
                unsigned long long o=__shfl_xor_sync(0xffffffffu,ck,off);
                if (o>ck) ck=o;
            }
            if (lane<8 && ck){
                int local = h*64 + ((j<4)? lane*4+j : 32+lane*4+(j-4));
                atomicMax(&sm_col[local], ck);
            }
        }
    }
    #pragma unroll
    for (int sdx=0;sdx<8;++sdx){
        unsigned long long v=rk[sdx];
        #pragma unroll
        for (int off=1;off<=4;off<<=1){
            unsigned long long o=__shfl_xor_sync(0xffffffffu,v,off);
            if (o>v) v=o;
        }
        if ((lane&7)==0 && v){
            int mloc = (sdx<4)? mi*4+sdx : 64+mi*4+(sdx-4);
            int mg = mt*128+mloc;
            if (mg<MU) atomicMax(&g_rowbest[(size_t)b*MU+mg], v);
        }
    }
    __syncthreads();
    if ((cp*128+tid)<COLS && sm_col[tid])
        atomicMax(&g_colbest[(size_t)b*COLS+cp*128+tid], sm_col[tid]);
}

// ---------------- K2: fused compact + gather (per bw block) -----------------
__global__ void __launch_bounds__(512) k_cg(){
    int bw = blockIdx.x; int b = bw/NWAY, w = bw%NWAY;
    int tid = threadIdx.x, lane = tid&31, wid = tid>>5;   // 16 warps
    __shared__ int sel_s[640];                            // cw <= 625
    __shared__ int wsum[16], woff[16], sbase;
    __shared__ float tile[CC][65];
    if (tid==0) sbase=0;
    __syncthreads();
    for (int chunk=0; chunk<5; ++chunk){
        int m = chunk*512 + tid;
        bool flag = false;
        if (m < MU){
            unsigned long long rb = g_rowbest[b*MU+m];
            unsigned col = 0xFFFFFFFFu - (unsigned)(rb & 0xFFFFFFFFu);
            if ((int)(col/MS) == w){
                unsigned long long cb = g_colbest[b*COLS+col];
                unsigned mm = 0xFFFFFFFFu - (unsigned)(cb & 0xFFFFFFFFu);
                flag = (mm == (unsigned)m);
            }
        }
        unsigned bal = __ballot_sync(0xffffffffu, flag);
        if (lane==0) wsum[wid] = __popc(bal);
        __syncthreads();
        if (tid==0){
            int run=sbase;
            #pragma unroll
            for (int i=0;i<16;++i){ woff[i]=run; run+=wsum[i]; }
            sbase=run;
        }
        __syncthreads();
        if (flag){
            int pos = woff[wid] + __popc(bal & ((1u<<lane)-1u));
            sel_s[pos] = m;
        }
        __syncthreads();
    }
    int cw = sbase;
    if (tid==0){
        g_count[bw] = cw;
        atomicMax(&g_L[0], cw);
    }
    // Phase 2: gather
    const float* __restrict__ unl = g_unl_n + (size_t)b*MU*CC;
    float* __restrict__ cat = g_cat_t + (size_t)bw*CC*CATP + MS;
    for (int jb=0; jb<cw; jb+=64){
        int nj = min(64, cw-jb);
        for (int t=wid; t<nj; t+=16){
            int m = sel_s[jb+t];                             // broadcast per warp
            float2 v = ((const float2*)(unl + (size_t)m*CC))[lane];  // 256B coalesced
            tile[2*lane][t]   = v.x;
            tile[2*lane+1][t] = v.y;
        }
        __syncthreads();
        for (int o=tid; o<CC*64; o+=512){
            int c=o>>6, j=o&63;
            if (j<nj) cat[(size_t)c*CATP + jb + j] = tile[c][j];   // coalesced along j
        }
        __syncthreads();
    }
}

// ---------------- K3: query GEMM (f32x2), 128x128 tile, balanced 8x8 map ----
// Grid (15 qt, 20 bw), 256 threads, 2 blocks/SM. Thread tile: 8 cols x 8 rows
// -> 64B LDS per 32 fma2 (crossbar 16cyc == FMA 16cyc per warp per c).
// ci=tid&15 covers cols {ci*4..+3, 64+ci*4..+3}; mi=tid>>4 owns rows mi*8..+7.
__global__ void __launch_bounds__(256,2) k_qsim(){
    int qt=blockIdx.x, bw=blockIdx.y;
    int b=bw/NWAY, w=bw%NWAY;
    int cw=g_count[bw]; int wl=MS+cw;
    int nct=(wl+127)>>7;
    __shared__ float4 a4[2048];                 // q-rows: [c][32 f4] = 128 rows (32KB)
    __shared__ float4 v4[2048];                 // cols:   [c][32 f4] = 128 cols (32KB)
    int tid=threadIdx.x, lane=tid&31;
    int ci=tid&15, mi=tid>>4;

    const float4* ga=(const float4*)g_q_t + (size_t)b*(CC*QROWP/4) + qt*32;
    #pragma unroll
    for (int t=0;t<8;++t){
        int idx=tid+t*256; int c=idx>>5, x=idx&31;
        a4[idx]=ga[(size_t)c*(QROWP/4)+x];
    }

    unsigned long long rkl[4], rkh[4];
    #pragma unroll
    for (int t=0;t<4;++t){ rkl[t]=0ULL; rkh[t]=0ULL; }

    for (int ct=0; ct<nct; ++ct){
        if (ct) __syncthreads();            // drain previous tile's v4 readers
        const float4* gv=(const float4*)g_cat_t + (size_t)bw*(CC*CATP/4) + ct*32;
        #pragma unroll
        for (int t=0;t<8;++t){
            int idx=tid+t*256; int c=idx>>5, x=idx&31;
            v4[idx]=gv[(size_t)c*(CATP/4)+x];
        }
        __syncthreads();                    // also covers a4 on first iteration

        unsigned long long acc[8][4];
        #pragma unroll
        for (int j=0;j<8;++j)
            #pragma unroll
            for (int t=0;t<4;++t) acc[j][t]=0ULL;

        #pragma unroll 2
        for (int c=0;c<64;++c){
            ulonglong2 bb0=*(const ulonglong2*)&a4[c*32 + mi*2];      // rows mi*8..+3
            ulonglong2 bb1=*(const ulonglong2*)&a4[c*32 + mi*2 + 1];  // rows mi*8+4..+7
            unsigned long long pb[4]={bb0.x,bb0.y,bb1.x,bb1.y};
            float4 x0=v4[c*32 + ci];         // cols ci*4..+3
            float4 x1=v4[c*32 + 16 + ci];    // cols 64+ci*4..+3
            float av[8]={x0.x,x0.y,x0.z,x0.w,x1.x,x1.y,x1.z,x1.w};
            #pragma unroll
            for (int j=0;j<8;++j){
                unsigned long long sa=splat2(av[j]);
                #pragma unroll
                for (int t=0;t<4;++t) fma2(acc[j][t],sa,pb[t]);
            }
        }

        // accumulate per-thread col-max keys across tiles (no shfl here)
        #pragma unroll
        for (int j=0;j<8;++j){
            int coll = (j<4)? ci*4+j : 64+ci*4+(j-4);
            int jg = ct*128 + coll;
            if (jg < wl){
                unsigned gcol = (unsigned)(w*MTOT + jg);
                #pragma unroll
                for (int t=0;t<4;++t){
                    float lo,hi; unpack2(acc[j][t],lo,hi);
                    unsigned long long a1=packkey(lo,gcol);
                    unsigned long long a2=packkey(hi,gcol);
                    if (a1>rkl[t]) rkl[t]=a1;
                    if (a2>rkh[t]) rkh[t]=a2;
                }
            }
        }
    }

    // final reduce over the 16 lanes of each half-warp (covers all 128 cols)
    #pragma unroll
    for (int t=0;t<4;++t){
        unsigned long long kl=rkl[t], kh=rkh[t];
        #pragma unroll
        for (int off=8;off>=1;off>>=1){
            unsigned long long o1=__shfl_xor_sync(0xffffffffu,kl,off);
            unsigned long long o2=__shfl_xor_sync(0xffffffffu,kh,off);
            if (o1>kl) kl=o1;
            if (o2>kh) kh=o2;
        }
        if ((lane&15)==0){
            int r0 = qt*128 + mi*8 + 2*t;
            if (r0<QROWS && kl) atomicMax(&g_rowq[((size_t)b*QROWP + r0)*NWAY + w], kl);
            if (r0+1<QROWS && kh) atomicMax(&g_rowq[((size_t)b*QROWP + r0+1)*NWAY + w], kh);
        }
    }
}

// ---------------- K4: finish = recompute col-argmax + mutual mask + CE ------
__global__ void __launch_bounds__(256) k_fin(const int* __restrict__ qy,
                                             float* __restrict__ out){
    int q=blockIdx.x, b=blockIdx.y;
    int tid=threadIdx.x, lane=tid&31, wp=tid>>5;
    __shared__ float rmx_s[NWAY][32];
    __shared__ unsigned gcol_s[32];
    __shared__ float mask_s[32];
    __shared__ int cnt_s[NWAY+1];
    if (tid<NWAY) cnt_s[tid]=g_count[b*NWAY+tid];
    if (tid==NWAY) cnt_s[NWAY]=g_L[0];
    if (tid<32) mask_s[tid]=0.f;
    __syncthreads();
    // stage 1: per-row (mq) way-maxes and global best column
    if (wp==0 && lane<HWN){
        unsigned long long qb=0ULL;
        #pragma unroll
        for (int w=0;w<NWAY;++w){
            unsigned long long r = g_rowq[((size_t)b*QROWP + q*25 + lane)*NWAY + w];
            int cww=cnt_s[w];
            if (cww < cnt_s[NWAY]){
                // first all-zero pad column of this way: raw cos = 0.0, col id MS+cww
                unsigned long long pk = packkey(0.0f,(unsigned)(w*MTOT+MS+cww));
                if (pk>r) r=pk;
            }
            rmx_s[w][lane]=fmaf(funmap((unsigned)(r>>32)),0.5f,0.5f);
            if (r>qb) qb=r;
        }
        gcol_s[lane]=0xFFFFFFFFu - (unsigned)(qb & 0xFFFFFFFFu);
    }
    __syncthreads();
    // stage 2: per winning column, recompute argmax over mq (bitwise-identical chain)
    for (int t=wp; t<HWN; t+=8){
        unsigned gcol=gcol_s[t];
        int w_=(int)(gcol/MTOT), j_=(int)(gcol%MTOT);
        int amq=0;
        if (j_ < MS + cnt_s[w_]){
            float acc=0.f;
            const float* qp = g_q_t + (size_t)b*CC*QROWP + q*25 + lane;
            const float* cp = g_cat_t + (size_t)(b*NWAY+w_)*CC*CATP + j_;
            if (lane<HWN){
                #pragma unroll
                for (int c=0;c<CC;++c)
                    acc=fmaf(qp[(size_t)c*QROWP], cp[(size_t)c*CATP], acc);
            }
            unsigned long long k = (lane<HWN)? packkey(acc,(unsigned)lane) : 0ULL;
            #pragma unroll
            for (int off=16;off>=1;off>>=1){
                unsigned long long o=__shfl_xor_sync(0xffffffffu,k,off);
                if (o>k) k=o;
            }
            amq = (int)(0xFFFFFFFFu - (unsigned)(k & 0xFFFFFFFFu));
        }
        if (lane==0) mask_s[t] = (amq==t)?1.f:0.f;
    }
    __syncthreads();
    // stage 3: qv + cross-entropy
    if (wp==0){
        float qv[NWAY];
        #pragma unroll
        for (int w=0;w<NWAY;++w){
            float t = (lane<HWN) ? rmx_s[w][lane]*mask_s[lane] : 0.f;
            #pragma unroll
            for (int off=16;off>=1;off>>=1) t += __shfl_xor_sync(0xffffffffu,t,off);
            qv[w]=t;
        }
        if (lane==0){
            int y = qy[b*QQ+q];
            float mx=qv[0];
            #pragma unroll
            for (int w=1;w<NWAY;++w) mx=fmaxf(mx,qv[w]);
            float se=0.f;
            #pragma unroll
            for (int w=0;w<NWAY;++w) se += expf(qv[w]-mx);
            float li = mx + logf(se) - qv[y];
            atomicAdd(out, li*(1.0f/(float)(BB*QQ)));
        }
    }
}

// ---------------- launch ----------------
extern "C" void kernel_launch(void* const* d_in, const int* in_sizes, int n_in,
                              void* d_out, int out_size) {
    const float* sup = nullptr;
    const float* qx  = nullptr;
    const float* ux  = nullptr;
    const int*   qy  = nullptr;
    for (int i=0;i<n_in;++i){
        switch (in_sizes[i]){
            case 160000: sup = (const float*)d_in[i]; break; // support_xf
            case 480000: qx  = (const float*)d_in[i]; break; // query_xf
            case 640000: ux  = (const float*)d_in[i]; break; // unlabeled_xf
            case 300:    qy  = (const int*)d_in[i];   break; // query_y
            default: break;                                  // support_y unused
        }
    }
    float* out = (float*)d_out;
    k_prep<<<816,256>>>(sup, ux, qx, out, out_size);
    k_u2s<<<dim3(20,5,BB),128>>>();
    k_cg<<<BB*NWAY,512>>>();
    k_qsim<<<dim3(15,BB*NWAY),256>>>();
    k_fin<<<dim3(QQ,BB),256>>>(qy, out);
}

// round 14
// speedup vs baseline: 1.2156x; 1.0246x over previous
#include <cuda_runtime.h>
#include <math.h>

#define NWAY 5
#define BB 4
#define CC 64
#define HWN 25
#define MS 125      // K_SHOT * h * w
#define MU 2500     // u * h * w
#define QQ 75
#define COLS 625    // NWAY * MS
#define MTOT 2625   // MS + MU
#define COLP 640    // padded cols for transposed support
#define MUP 2560    // padded m for transposed unlabeled
#define QROWS 1875  // 75 q * 25 rows (packed)
#define QROWP 1920  // padded to 15*128
#define CATP 2688   // padded cat columns (21*128)

// ---------------- scratch (static device allocations only) ----------------
__device__ float g_sup_t[BB*CC*COLP];            // [b][c][col] transposed support (pad zeroed)
__device__ float g_unl_t[BB*CC*MUP];             // [b][c][m]   transposed unlabeled (pad zeroed)
__device__ float g_unl_n[BB*MU*CC];              // [b][m][c]   row-major normalized unlabeled
__device__ float g_q_t[BB*CC*QROWP];             // [b][c][q*25+mq] transposed query (pads zero)
__device__ float g_cat_t[BB*NWAY*CC*CATP];       // [bw][c][j] = [sup(125) | compacted unl(cw)]
__device__ unsigned long long g_rowbest[BB*MU];  // per (b,m): packed (val,col) argmax
__device__ unsigned long long g_colbest[BB*COLS];// per (b,col): packed (val,m) argmax
__device__ unsigned long long g_rowq[BB*QROWP*NWAY]; // per (b,row,w): packed best over cols
__device__ int g_count[BB*NWAY];
__device__ int g_L[1];

// monotone float ordering map (handles negatives exactly)
__device__ __forceinline__ unsigned fmap(float f){
    unsigned b=__float_as_uint(f);
    return (b&0x80000000u)? ~b : (b|0x80000000u);
}
__device__ __forceinline__ float funmap(unsigned u){
    return (u&0x80000000u)? __uint_as_float(u^0x80000000u) : __uint_as_float(~u);
}
// max-value, min-index-on-tie key (matches jnp first-occurrence argmax)
__device__ __forceinline__ unsigned long long packkey(float v, unsigned idx){
    return (((unsigned long long)fmap(v))<<32) | (unsigned long long)(0xFFFFFFFFu - idx);
}
// packed 2xFP32 FMA (Blackwell f32x2)
__device__ __forceinline__ void fma2(unsigned long long& acc, unsigned long long a, unsigned long long b){
    asm("fma.rn.f32x2 %0, %1, %2, %0;" : "+l"(acc) : "l"(a), "l"(b));
}
__device__ __forceinline__ unsigned long long splat2(float x){
    unsigned long long r;
    asm("mov.b64 %0, {%1, %1};" : "=l"(r) : "r"(__float_as_uint(x)));
    return r;
}
__device__ __forceinline__ void unpack2(unsigned long long v, float& lo, float& hi){
    unsigned a,b;
    asm("mov.b64 {%0, %1}, %2;" : "=r"(a), "=r"(b) : "l"(v));
    lo=__uint_as_float(a); hi=__uint_as_float(b);
}

// ---------------- K0: prep = init + all normalizations ----------------
__global__ void __launch_bounds__(256) k_prep(const float* __restrict__ sup,
                                              const float* __restrict__ unl,
                                              const float* __restrict__ qx,
                                              float* __restrict__ out, int out_size){
    int s = blockIdx.x;
    int tid = threadIdx.x;
    if (s >= 800){
        int i = (s-800)*256 + tid;
        const int stride = 16*256;
        for (int t=i;t<BB*MU;t+=stride) g_rowbest[t]=0ULL;
        for (int t=i;t<BB*COLS;t+=stride) g_colbest[t]=0ULL;
        for (int t=i;t<BB*QROWP*NWAY;t+=stride) g_rowq[t]=0ULL;
        for (int t=i;t<BB*CC*(COLP-COLS);t+=stride){
            int bc=t/(COLP-COLS), p=t%(COLP-COLS);
            g_sup_t[(size_t)bc*COLP+COLS+p]=0.f;
        }
        for (int t=i;t<BB*CC*(MUP-MU);t+=stride){
            int bc=t/(MUP-MU), p=t%(MUP-MU);
            g_unl_t[(size_t)bc*MUP+MU+p]=0.f;
        }
        // pad rows 1875..1919 of g_q_t
        for (int t=i;t<BB*CC*(QROWP-QROWS);t+=stride){
            int bc=t/(QROWP-QROWS), p=t%(QROWP-QROWS);
            g_q_t[(size_t)bc*QROWP+QROWS+p]=0.f;
        }
        if (i==0) g_L[0]=0;
        for (int t=i;t<out_size;t+=stride) out[t]=0.f;
        return;
    }
    __shared__ __align__(16) float tile[1664];   // 1600 used; tail pad for safe OOB reads
    __shared__ float inv[HWN];
    const float* in;
    if (s<100)      in = sup + (size_t)s*1600;
    else if (s<500) in = unl + (size_t)(s-100)*1600;
    else            in = qx  + (size_t)(s-500)*1600;
    {
        const float4* in4=(const float4*)in;
        float4* t4=(float4*)tile;
        for (int t=tid;t<400;t+=256) t4[t]=in4[t];
    }
    __syncthreads();
    {
        // parallel norm: 8 threads per hw (all 256 threads participate; hw>=25 discarded)
        int hw=tid>>3, k=tid&7;
        float a=0.f;
        #pragma unroll
        for (int c=k;c<CC;c+=8){ float v=tile[c*HWN+hw]; a=fmaf(v,v,a); }
        a += __shfl_xor_sync(0xffffffffu,a,4);
        a += __shfl_xor_sync(0xffffffffu,a,2);
        a += __shfl_xor_sync(0xffffffffu,a,1);
        if (k==0 && hw<HWN) inv[hw]=1.0f/fmaxf(sqrtf(a),1e-12f);
    }
    __syncthreads();
    if (s<100){
        int b=s/25, sk=s%25, w=sk/5, k=sk%5;
        int colbase=w*MS+k*25;
        float* outt=g_sup_t+(size_t)b*CC*COLP+colbase;
        float* outc=g_cat_t+(size_t)(b*NWAY+w)*CC*CATP + k*25;
        for (int o=tid;o<1600;o+=256){
            int c=o/HWN,hw=o%HWN;
            float v=tile[o]*inv[hw];
            outt[(size_t)c*COLP+hw]=v;
            outc[(size_t)c*CATP+hw]=v;
        }
    } else if (s<500){
        int t2=s-100; int b=t2/100,u=t2%100;
        float* outt=g_unl_t+(size_t)b*CC*MUP+u*25;
        float* outp=g_unl_n+(size_t)(b*MU+u*25)*CC;
        for (int o=tid;o<1600;o+=256){ int c=o/HWN,hw=o%HWN; outt[(size_t)c*MUP+hw]=tile[o]*inv[hw]; }
        for (int o=tid;o<1600;o+=256){ int hw=o>>6,c=o&63; outp[o]=tile[c*HWN+hw]*inv[hw]; }
    } else {
        int t2=s-500; int b=t2/QQ, q=t2%QQ;
        float* outt=g_q_t+(size_t)b*CC*QROWP + q*25;
        for (int o=tid;o<1600;o+=256){ int c=o/HWN,hw=o%HWN; outt[(size_t)c*QROWP+hw]=tile[o]*inv[hw]; }
    }
}

// ---------------- K1: u2s GEMM (f32x2), balanced 8x8 thread tile ------------
// Block = 128 cols (cp) x 128 m (mt). 256 threads: ci=tid&15 -> cols
// {ci*4..+3, 64+ci*4..+3}; mi=tid>>4 -> m rows mi*8..+7.
// Per c per warp: 4 LDS.128 + 32 fma2 (the ceiling-reaching mix from k_qsim).
__global__ void __launch_bounds__(256,2) k_u2s(){
    __shared__ float4 s4[2048];                  // [c][32 f4] = 128 cols (32KB)
    __shared__ float4 u4[2048];                  // [c][32 f4] = 128 m   (32KB)
    __shared__ unsigned long long sm_col[128];
    int mt=blockIdx.x, cp=blockIdx.y, b=blockIdx.z;
    int tid=threadIdx.x, lane=tid&31;
    int ci=tid&15, mi=tid>>4;

    const float4* gs4=(const float4*)g_sup_t + (size_t)b*(CC*COLP/4) + cp*32;
    #pragma unroll
    for (int t=0;t<8;++t){
        int idx=tid+t*256; int c=idx>>5, x=idx&31;
        s4[idx]=gs4[(size_t)c*(COLP/4)+x];
    }
    const float4* gu4=(const float4*)g_unl_t + (size_t)b*(CC*MUP/4) + mt*32;
    #pragma unroll
    for (int t=0;t<8;++t){
        int idx=tid+t*256; int c=idx>>5, x=idx&31;
        u4[idx]=gu4[(size_t)c*(MUP/4)+x];
    }
    if (tid<128) sm_col[tid]=0ULL;
    __syncthreads();

    unsigned long long acc[8][4];                // [col j][row pair t]
    #pragma unroll
    for (int j=0;j<8;++j)
        #pragma unroll
        for (int t=0;t<4;++t) acc[j][t]=0ULL;

    #pragma unroll 2
    for (int c=0;c<64;++c){
        ulonglong2 bb0=*(const ulonglong2*)&u4[c*32 + mi*2];      // m mi*8..+3
        ulonglong2 bb1=*(const ulonglong2*)&u4[c*32 + mi*2 + 1];  // m mi*8+4..+7
        unsigned long long pb[4]={bb0.x,bb0.y,bb1.x,bb1.y};
        float4 x0=s4[c*32 + ci];         // cols ci*4..+3
        float4 x1=s4[c*32 + 16 + ci];    // cols 64+ci*4..+3
        float av[8]={x0.x,x0.y,x0.z,x0.w,x1.x,x1.y,x1.z,x1.w};
        #pragma unroll
        for (int j=0;j<8;++j){
            unsigned long long sa=splat2(av[j]);
            #pragma unroll
            for (int t=0;t<4;++t) fma2(acc[j][t],sa,pb[t]);
        }
    }

    // epilogue: per-col keys (over m) via smem atomics; per-m keys (over cols) in regs
    unsigned long long rkl[4], rkh[4];
    #pragma unroll
    for (int t=0;t<4;++t){ rkl[t]=0ULL; rkh[t]=0ULL; }

    #pragma unroll
    for (int j=0;j<8;++j){
        int coll = (j<4)? ci*4+j : 64+ci*4+(j-4);
        int colj = cp*128 + coll;
        bool vc = colj < COLS;
        unsigned long long ck=0ULL;
        if (vc){
            #pragma unroll
            for (int t=0;t<4;++t){
                float lo,hi; unpack2(acc[j][t],lo,hi);
                unsigned long long kl=packkey(lo,(unsigned)colj);
                unsigned long long kh=packkey(hi,(unsigned)colj);
                if (kl>rkl[t]) rkl[t]=kl;
                if (kh>rkh[t]) rkh[t]=kh;
                int mglo = mt*128 + mi*8 + 2*t;
                if (mglo<MU){ unsigned long long c1=packkey(lo,(unsigned)mglo); if (c1>ck) ck=c1; }
                if (mglo+1<MU){ unsigned long long c2=packkey(hi,(unsigned)(mglo+1)); if (c2>ck) ck=c2; }
            }
        }
        // combine the two mi halves of this warp (lane ^ 16 has same ci)
        unsigned long long o=__shfl_xor_sync(0xffffffffu,ck,16);
        if (o>ck) ck=o;
        if (lane<16 && ck)
            atomicMax(&sm_col[(j<4)? lane*4+j : 64+lane*4+(j-4)], ck);
    }
    // row (per-m) reduce over the 16 ci lanes (xor <16 keeps mi fixed)
    #pragma unroll
    for (int t=0;t<4;++t){
        unsigned long long kl=rkl[t], kh=rkh[t];
        #pragma unroll
        for (int off=8;off>=1;off>>=1){
            unsigned long long o1=__shfl_xor_sync(0xffffffffu,kl,off);
            unsigned long long o2=__shfl_xor_sync(0xffffffffu,kh,off);
            if (o1>kl) kl=o1;
            if (o2>kh) kh=o2;
        }
        if ((lane&15)==0){
            int r0 = mt*128 + mi*8 + 2*t;
            if (r0<MU && kl) atomicMax(&g_rowbest[(size_t)b*MU+r0], kl);
            if (r0+1<MU && kh) atomicMax(&g_rowbest[(size_t)b*MU+r0+1], kh);
        }
    }
    __syncthreads();
    if (tid<128 && (cp*128+tid)<COLS && sm_col[tid])
        atomicMax(&g_colbest[(size_t)b*COLS+cp*128+tid], sm_col[tid]);
}

// ---------------- K2: fused compact + gather (per bw block) -----------------
__global__ void __launch_bounds__(512) k_cg(){
    int bw = blockIdx.x; int b = bw/NWAY, w = bw%NWAY;
    int tid = threadIdx.x, lane = tid&31, wid = tid>>5;   // 16 warps
    __shared__ int sel_s[640];                            // cw <= 625
    __shared__ int wsum[16], woff[16], sbase;
    __shared__ float tile[CC][65];
    if (tid==0) sbase=0;
    __syncthreads();
    for (int chunk=0; chunk<5; ++chunk){
        int m = chunk*512 + tid;
        bool flag = false;
        if (m < MU){
            unsigned long long rb = g_rowbest[b*MU+m];
            unsigned col = 0xFFFFFFFFu - (unsigned)(rb & 0xFFFFFFFFu);
            if ((int)(col/MS) == w){
                unsigned long long cb = g_colbest[b*COLS+col];
                unsigned mm = 0xFFFFFFFFu - (unsigned)(cb & 0xFFFFFFFFu);
                flag = (mm == (unsigned)m);
            }
        }
        unsigned bal = __ballot_sync(0xffffffffu, flag);
        if (lane==0) wsum[wid] = __popc(bal);
        __syncthreads();
        if (tid==0){
            int run=sbase;
            #pragma unroll
            for (int i=0;i<16;++i){ woff[i]=run; run+=wsum[i]; }
            sbase=run;
        }
        __syncthreads();
        if (flag){
            int pos = woff[wid] + __popc(bal & ((1u<<lane)-1u));
            sel_s[pos] = m;
        }
        __syncthreads();
    }
    int cw = sbase;
    if (tid==0){
        g_count[bw] = cw;
        atomicMax(&g_L[0], cw);
    }
    // Phase 2: gather
    const float* __restrict__ unl = g_unl_n + (size_t)b*MU*CC;
    float* __restrict__ cat = g_cat_t + (size_t)bw*CC*CATP + MS;
    for (int jb=0; jb<cw; jb+=64){
        int nj = min(64, cw-jb);
        for (int t=wid; t<nj; t+=16){
            int m = sel_s[jb+t];                             // broadcast per warp
            float2 v = ((const float2*)(unl + (size_t)m*CC))[lane];  // 256B coalesced
            tile[2*lane][t]   = v.x;
            tile[2*lane+1][t] = v.y;
        }
        __syncthreads();
        for (int o=tid; o<CC*64; o+=512){
            int c=o>>6, j=o&63;
            if (j<nj) cat[(size_t)c*CATP + jb + j] = tile[c][j];   // coalesced along j
        }
        __syncthreads();
    }
}

// ---------------- K3: query GEMM (f32x2), 128x128 tile, balanced 8x8 map ----
__global__ void __launch_bounds__(256,2) k_qsim(){
    int qt=blockIdx.x, bw=blockIdx.y;
    int b=bw/NWAY, w=bw%NWAY;
    int cw=g_count[bw]; int wl=MS+cw;
    int nct=(wl+127)>>7;
    __shared__ float4 a4[2048];                 // q-rows: [c][32 f4] = 128 rows (32KB)
    __shared__ float4 v4[2048];                 // cols:   [c][32 f4] = 128 cols (32KB)
    int tid=threadIdx.x, lane=tid&31;
    int ci=tid&15, mi=tid>>4;

    const float4* ga=(const float4*)g_q_t + (size_t)b*(CC*QROWP/4) + qt*32;
    #pragma unroll
    for (int t=0;t<8;++t){
        int idx=tid+t*256; int c=idx>>5, x=idx&31;
        a4[idx]=ga[(size_t)c*(QROWP/4)+x];
    }

    unsigned long long rkl[4], rkh[4];
    #pragma unroll
    for (int t=0;t<4;++t){ rkl[t]=0ULL; rkh[t]=0ULL; }

    for (int ct=0; ct<nct; ++ct){
        if (ct) __syncthreads();            // drain previous tile's v4 readers
        const float4* gv=(const float4*)g_cat_t + (size_t)bw*(CC*CATP/4) + ct*32;
        #pragma unroll
        for (int t=0;t<8;++t){
            int idx=tid+t*256; int c=idx>>5, x=idx&31;
            v4[idx]=gv[(size_t)c*(CATP/4)+x];
        }
        __syncthreads();                    // also covers a4 on first iteration

        unsigned long long acc[8][4];
        #pragma unroll
        for (int j=0;j<8;++j)
            #pragma unroll
            for (int t=0;t<4;++t) acc[j][t]=0ULL;

        #pragma unroll 2
        for (int c=0;c<64;++c){
            ulonglong2 bb0=*(const ulonglong2*)&a4[c*32 + mi*2];      // rows mi*8..+3
            ulonglong2 bb1=*(const ulonglong2*)&a4[c*32 + mi*2 + 1];  // rows mi*8+4..+7
            unsigned long long pb[4]={bb0.x,bb0.y,bb1.x,bb1.y};
            float4 x0=v4[c*32 + ci];         // cols ci*4..+3
            float4 x1=v4[c*32 + 16 + ci];    // cols 64+ci*4..+3
            float av[8]={x0.x,x0.y,x0.z,x0.w,x1.x,x1.y,x1.z,x1.w};
            #pragma unroll
            for (int j=0;j<8;++j){
                unsigned long long sa=splat2(av[j]);
                #pragma unroll
                for (int t=0;t<4;++t) fma2(acc[j][t],sa,pb[t]);
            }
        }

        // accumulate per-thread col-max keys across tiles (no shfl here)
        #pragma unroll
        for (int j=0;j<8;++j){
            int coll = (j<4)? ci*4+j : 64+ci*4+(j-4);
            int jg = ct*128 + coll;
            if (jg < wl){
                unsigned gcol = (unsigned)(w*MTOT + jg);
                #pragma unroll
                for (int t=0;t<4;++t){
                    float lo,hi; unpack2(acc[j][t],lo,hi);
                    unsigned long long a1=packkey(lo,gcol);
                    unsigned long long a2=packkey(hi,gcol);
                    if (a1>rkl[t]) rkl[t]=a1;
                    if (a2>rkh[t]) rkh[t]=a2;
                }
            }
        }
    }

    // final reduce over the 16 lanes of each half-warp (covers all 128 cols)
    #pragma unroll
    for (int t=0;t<4;++t){
        unsigned long long kl=rkl[t], kh=rkh[t];
        #pragma unroll
        for (int off=8;off>=1;off>>=1){
            unsigned long long o1=__shfl_xor_sync(0xffffffffu,kl,off);
            unsigned long long o2=__shfl_xor_sync(0xffffffffu,kh,off);
            if (o1>kl) kl=o1;
            if (o2>kh) kh=o2;
        }
        if ((lane&15)==0){
            int r0 = qt*128 + mi*8 + 2*t;
            if (r0<QROWS && kl) atomicMax(&g_rowq[((size_t)b*QROWP + r0)*NWAY + w], kl);
            if (r0+1<QROWS && kh) atomicMax(&g_rowq[((size_t)b*QROWP + r0+1)*NWAY + w], kh);
        }
    }
}

// ---------------- K4: finish = recompute col-argmax + mutual mask + CE ------
__global__ void __launch_bounds__(256) k_fin(const int* __restrict__ qy,
                                             float* __restrict__ out){
    int q=blockIdx.x, b=blockIdx.y;
    int tid=threadIdx.x, lane=tid&31, wp=tid>>5;
    __shared__ float rmx_s[NWAY][32];
    __shared__ unsigned gcol_s[32];
    __shared__ float mask_s[32];
    __shared__ int cnt_s[NWAY+1];
    if (tid<NWAY) cnt_s[tid]=g_count[b*NWAY+tid];
    if (tid==NWAY) cnt_s[NWAY]=g_L[0];
    if (tid<32) mask_s[tid]=0.f;
    __syncthreads();
    // stage 1: per-row (mq) way-maxes and global best column
    if (wp==0 && lane<HWN){
        unsigned long long qb=0ULL;
        #pragma unroll
        for (int w=0;w<NWAY;++w){
            unsigned long long r = g_rowq[((size_t)b*QROWP + q*25 + lane)*NWAY + w];
            int cww=cnt_s[w];
            if (cww < cnt_s[NWAY]){
                // first all-zero pad column of this way: raw cos = 0.0, col id MS+cww
                unsigned long long pk = packkey(0.0f,(unsigned)(w*MTOT+MS+cww));
                if (pk>r) r=pk;
            }
            rmx_s[w][lane]=fmaf(funmap((unsigned)(r>>32)),0.5f,0.5f);
            if (r>qb) qb=r;
        }
        gcol_s[lane]=0xFFFFFFFFu - (unsigned)(qb & 0xFFFFFFFFu);
    }
    __syncthreads();
    // stage 2: per winning column, recompute argmax over mq (bitwise-identical chain)
    for (int t=wp; t<HWN; t+=8){
        unsigned gcol=gcol_s[t];
        int w_=(int)(gcol/MTOT), j_=(int)(gcol%MTOT);
        int amq=0;
        if (j_ < MS + cnt_s[w_]){
            float acc=0.f;
            const float* qp = g_q_t + (size_t)b*CC*QROWP + q*25 + lane;
            const float* cp = g_cat_t + (size_t)(b*NWAY+w_)*CC*CATP + j_;
            if (lane<HWN){
                #pragma unroll
                for (int c=0;c<CC;++c)
                    acc=fmaf(qp[(size_t)c*QROWP], cp[(size_t)c*CATP], acc);
            }
            unsigned long long k = (lane<HWN)? packkey(acc,(unsigned)lane) : 0ULL;
            #pragma unroll
            for (int off=16;off>=1;off>>=1){
                unsigned long long o=__shfl_xor_sync(0xffffffffu,k,off);
                if (o>k) k=o;
            }
            amq = (int)(0xFFFFFFFFu - (unsigned)(k & 0xFFFFFFFFu));
        }
        if (lane==0) mask_s[t] = (amq==t)?1.f:0.f;
    }
    __syncthreads();
    // stage 3: qv + cross-entropy
    if (wp==0){
        float qv[NWAY];
        #pragma unroll
        for (int w=0;w<NWAY;++w){
            float t = (lane<HWN) ? rmx_s[w][lane]*mask_s[lane] : 0.f;
            #pragma unroll
            for (int off=16;off>=1;off>>=1) t += __shfl_xor_sync(0xffffffffu,t,off);
            qv[w]=t;
        }
        if (lane==0){
            int y = qy[b*QQ+q];
            float mx=qv[0];
            #pragma unroll
            for (int w=1;w<NWAY;++w) mx=fmaxf(mx,qv[w]);
            float se=0.f;
            #pragma unroll
            for (int w=0;w<NWAY;++w) se += expf(qv[w]-mx);
            float li = mx + logf(se) - qv[y];
            atomicAdd(out, li*(1.0f/(float)(BB*QQ)));
        }
    }
}

// ---------------- launch ----------------
extern "C" void kernel_launch(void* const* d_in, const int* in_sizes, int n_in,
                              void* d_out, int out_size) {
    const float* sup = nullptr;
    const float* qx  = nullptr;
    const float* ux  = nullptr;
    const int*   qy  = nullptr;
    for (int i=0;i<n_in;++i){
        switch (in_sizes[i]){
            case 160000: sup = (const float*)d_in[i]; break; // support_xf
            case 480000: qx  = (const float*)d_in[i]; break; // query_xf
            case 640000: ux  = (const float*)d_in[i]; break; // unlabeled_xf
            case 300:    qy  = (const int*)d_in[i];   break; // query_y
            default: break;                                  // support_y unused
        }
    }
    float* out = (float*)d_out;
    k_prep<<<816,256>>>(sup, ux, qx, out, out_size);
    k_u2s<<<dim3(20,5,BB),256>>>();
    k_cg<<<BB*NWAY,512>>>();
    k_qsim<<<dim3(15,BB*NWAY),256>>>();
    k_fin<<<dim3(QQ,BB),256>>>(qy, out);
}

// round 15
// speedup vs baseline: 1.2420x; 1.0217x over previous
#include <cuda_runtime.h>
#include <math.h>

#define NWAY 5
#define BB 4
#define CC 64
#define HWN 25
#define MS 125      // K_SHOT * h * w
#define MU 2500     // u * h * w
#define QQ 75
#define COLS 625    // NWAY * MS
#define MTOT 2625   // MS + MU
#define MUP 2560    // padded m for transposed unlabeled
#define QROWS 1875  // 75 q * 25 rows (packed)
#define QROWP 1920  // padded to 15*128
#define CATP 2688   // padded cat columns (21*128)

// ---------------- scratch (static device allocations only) ----------------
__device__ float g_unl_t[BB*CC*MUP];             // [b][c][m]   transposed unlabeled (pad zeroed)
__device__ float g_unl_n[BB*MU*CC];              // [b][m][c]   row-major normalized unlabeled
__device__ float g_q_t[BB*CC*QROWP];             // [b][c][q*25+mq] transposed query (pads zero)
__device__ float g_cat_t[BB*NWAY*CC*CATP];       // [bw][c][j] = [sup(125) | compacted unl(cw)]
__device__ unsigned long long g_rowbest[BB*MU];  // per (b,m): packed (val,col) argmax
__device__ unsigned long long g_colbest[BB*COLS];// per (b,col): packed (val,m) argmax
__device__ unsigned long long g_rowq[BB*QROWP*NWAY]; // per (b,row,w): packed best over cols
__device__ int g_count[BB*NWAY];
__device__ int g_L[1];

// monotone float ordering map (handles negatives exactly)
__device__ __forceinline__ unsigned fmap(float f){
    unsigned b=__float_as_uint(f);
    return (b&0x80000000u)? ~b : (b|0x80000000u);
}
__device__ __forceinline__ float funmap(unsigned u){
    return (u&0x80000000u)? __uint_as_float(u^0x80000000u) : __uint_as_float(~u);
}
// max-value, min-index-on-tie key (matches jnp first-occurrence argmax)
__device__ __forceinline__ unsigned long long packkey(float v, unsigned idx){
    return (((unsigned long long)fmap(v))<<32) | (unsigned long long)(0xFFFFFFFFu - idx);
}
// packed 2xFP32 FMA (Blackwell f32x2)
__device__ __forceinline__ void fma2(unsigned long long& acc, unsigned long long a, unsigned long long b){
    asm("fma.rn.f32x2 %0, %1, %2, %0;" : "+l"(acc) : "l"(a), "l"(b));
}
__device__ __forceinline__ unsigned long long splat2(float x){
    unsigned long long r;
    asm("mov.b64 %0, {%1, %1};" : "=l"(r) : "r"(__float_as_uint(x)));
    return r;
}
__device__ __forceinline__ void unpack2(unsigned long long v, float& lo, float& hi){
    unsigned a,b;
    asm("mov.b64 {%0, %1}, %2;" : "=r"(a), "=r"(b) : "l"(v));
    lo=__uint_as_float(a); hi=__uint_as_float(b);
}

// ---------------- K0: prep = init + all normalizations ----------------
__global__ void __launch_bounds__(256) k_prep(const float* __restrict__ sup,
                                              const float* __restrict__ unl,
                                              const float* __restrict__ qx,
                                              float* __restrict__ out, int out_size){
    int s = blockIdx.x;
    int tid = threadIdx.x;
    if (s >= 800){
        int i = (s-800)*256 + tid;
        const int stride = 16*256;
        for (int t=i;t<BB*MU;t+=stride) g_rowbest[t]=0ULL;
        for (int t=i;t<BB*COLS;t+=stride) g_colbest[t]=0ULL;
        for (int t=i;t<BB*QROWP*NWAY;t+=stride) g_rowq[t]=0ULL;
        for (int t=i;t<BB*CC*(MUP-MU);t+=stride){
            int bc=t/(MUP-MU), p=t%(MUP-MU);
            g_unl_t[(size_t)bc*MUP+MU+p]=0.f;
        }
        // pad rows 1875..1919 of g_q_t
        for (int t=i;t<BB*CC*(QROWP-QROWS);t+=stride){
            int bc=t/(QROWP-QROWS), p=t%(QROWP-QROWS);
            g_q_t[(size_t)bc*QROWP+QROWS+p]=0.f;
        }
        if (i==0) g_L[0]=0;
        for (int t=i;t<out_size;t+=stride) out[t]=0.f;
        return;
    }
    __shared__ __align__(16) float tile[1664];   // 1600 used; tail pad for safe OOB reads
    __shared__ float inv[HWN];
    const float* in;
    if (s<100)      in = sup + (size_t)s*1600;
    else if (s<500) in = unl + (size_t)(s-100)*1600;
    else            in = qx  + (size_t)(s-500)*1600;
    {
        const float4* in4=(const float4*)in;
        float4* t4=(float4*)tile;
        for (int t=tid;t<400;t+=256) t4[t]=in4[t];
    }
    __syncthreads();
    {
        // parallel norm: 8 threads per hw (all 256 threads participate; hw>=25 discarded)
        int hw=tid>>3, k=tid&7;
        float a=0.f;
        #pragma unroll
        for (int c=k;c<CC;c+=8){ float v=tile[c*HWN+hw]; a=fmaf(v,v,a); }
        a += __shfl_xor_sync(0xffffffffu,a,4);
        a += __shfl_xor_sync(0xffffffffu,a,2);
        a += __shfl_xor_sync(0xffffffffu,a,1);
        if (k==0 && hw<HWN) inv[hw]=1.0f/fmaxf(sqrtf(a),1e-12f);
    }
    __syncthreads();
    if (s<100){
        int b=s/25, sk=s%25, w=sk/5, k=sk%5;
        // support columns live ONLY in g_cat_t now (cols k*25..k*25+24 of way w)
        float* outc=g_cat_t+(size_t)(b*NWAY+w)*CC*CATP + k*25;
        for (int o=tid;o<1600;o+=256){
            int c=o/HWN,hw=o%HWN;
            outc[(size_t)c*CATP+hw]=tile[o]*inv[hw];
        }
    } else if (s<500){
        int t2=s-100; int b=t2/100,u=t2%100;
        float* outt=g_unl_t+(size_t)b*CC*MUP+u*25;
        float* outp=g_unl_n+(size_t)(b*MU+u*25)*CC;
        for (int o=tid;o<1600;o+=256){ int c=o/HWN,hw=o%HWN; outt[(size_t)c*MUP+hw]=tile[o]*inv[hw]; }
        for (int o=tid;o<1600;o+=256){ int hw=o>>6,c=o&63; outp[o]=tile[c*HWN+hw]*inv[hw]; }
    } else {
        int t2=s-500; int b=t2/QQ, q=t2%QQ;
        float* outt=g_q_t+(size_t)b*CC*QROWP + q*25;
        for (int o=tid;o<1600;o+=256){ int c=o/HWN,hw=o%HWN; outt[(size_t)c*QROWP+hw]=tile[o]*inv[hw]; }
    }
}

// ---------------- K1: u2s GEMM (f32x2), per-way column tiles ----------------
// Block = way w (125 cols, padded reads to 128) x 128 m (mt). 256 threads:
// ci=tid&15 -> cols {ci*4..+3, 64+ci*4..+3}; mi=tid>>4 -> m rows mi*8..+7.
// Support tile read directly from g_cat_t (cols 125..127 are garbage, guarded).
__global__ void __launch_bounds__(256,2) k_u2s(){
    __shared__ float4 s4[2048];                  // [c][32 f4] = 128 cols (32KB)
    __shared__ float4 u4[2048];                  // [c][32 f4] = 128 m   (32KB)
    __shared__ unsigned long long sm_col[128];
    int mt=blockIdx.x, w=blockIdx.y, b=blockIdx.z;
    int bw=b*NWAY+w;
    int tid=threadIdx.x, lane=tid&31;
    int ci=tid&15, mi=tid>>4;

    const float4* gs4=(const float4*)g_cat_t + (size_t)bw*(CC*CATP/4);
    #pragma unroll
    for (int t=0;t<8;++t){
        int idx=tid+t*256; int c=idx>>5, x=idx&31;
        s4[idx]=gs4[(size_t)c*(CATP/4)+x];
    }
    const float4* gu4=(const float4*)g_unl_t + (size_t)b*(CC*MUP/4) + mt*32;
    #pragma unroll
    for (int t=0;t<8;++t){
        int idx=tid+t*256; int c=idx>>5, x=idx&31;
        u4[idx]=gu4[(size_t)c*(MUP/4)+x];
    }
    if (tid<128) sm_col[tid]=0ULL;
    __syncthreads();

    unsigned long long acc[8][4];                // [col j][row pair t]
    #pragma unroll
    for (int j=0;j<8;++j)
        #pragma unroll
        for (int t=0;t<4;++t) acc[j][t]=0ULL;

    #pragma unroll 2
    for (int c=0;c<64;++c){
        ulonglong2 bb0=*(const ulonglong2*)&u4[c*32 + mi*2];      // m mi*8..+3
        ulonglong2 bb1=*(const ulonglong2*)&u4[c*32 + mi*2 + 1];  // m mi*8+4..+7
        unsigned long long pb[4]={bb0.x,bb0.y,bb1.x,bb1.y};
        float4 x0=s4[c*32 + ci];         // cols ci*4..+3
        float4 x1=s4[c*32 + 16 + ci];    // cols 64+ci*4..+3
        float av[8]={x0.x,x0.y,x0.z,x0.w,x1.x,x1.y,x1.z,x1.w};
        #pragma unroll
        for (int j=0;j<8;++j){
            unsigned long long sa=splat2(av[j]);
            #pragma unroll
            for (int t=0;t<4;++t) fma2(acc[j][t],sa,pb[t]);
        }
    }

    // epilogue: per-col keys (over m) via smem atomics; per-m keys (over cols) in regs
    unsigned long long rkl[4], rkh[4];
    #pragma unroll
    for (int t=0;t<4;++t){ rkl[t]=0ULL; rkh[t]=0ULL; }

    #pragma unroll
    for (int j=0;j<8;++j){
        int coll = (j<4)? ci*4+j : 64+ci*4+(j-4);
        bool vc = coll < MS;                      // cols 125..127 are garbage
        int colj = w*MS + coll;                   // global column id 0..624
        unsigned long long ck=0ULL;
        if (vc){
            #pragma unroll
            for (int t=0;t<4;++t){
                float lo,hi; unpack2(acc[j][t],lo,hi);
                unsigned long long kl=packkey(lo,(unsigned)colj);
                unsigned long long kh=packkey(hi,(unsigned)colj);
                if (kl>rkl[t]) rkl[t]=kl;
                if (kh>rkh[t]) rkh[t]=kh;
                int mglo = mt*128 + mi*8 + 2*t;
                if (mglo<MU){ unsigned long long c1=packkey(lo,(unsigned)mglo); if (c1>ck) ck=c1; }
                if (mglo+1<MU){ unsigned long long c2=packkey(hi,(unsigned)(mglo+1)); if (c2>ck) ck=c2; }
            }
        }
        // combine the two mi halves of this warp (lane ^ 16 has same ci)
        unsigned long long o=__shfl_xor_sync(0xffffffffu,ck,16);
        if (o>ck) ck=o;
        if (lane<16 && ck)
            atomicMax(&sm_col[(j<4)? lane*4+j : 64+lane*4+(j-4)], ck);
    }
    // row (per-m) reduce over the 16 ci lanes (xor <16 keeps mi fixed)
    #pragma unroll
    for (int t=0;t<4;++t){
        unsigned long long kl=rkl[t], kh=rkh[t];
        #pragma unroll
        for (int off=8;off>=1;off>>=1){
            unsigned long long o1=__shfl_xor_sync(0xffffffffu,kl,off);
            unsigned long long o2=__shfl_xor_sync(0xffffffffu,kh,off);
            if (o1>kl) kl=o1;
            if (o2>kh) kh=o2;
        }
        if ((lane&15)==0){
            int r0 = mt*128 + mi*8 + 2*t;
            if (r0<MU && kl) atomicMax(&g_rowbest[(size_t)b*MU+r0], kl);
            if (r0+1<MU && kh) atomicMax(&g_rowbest[(size_t)b*MU+r0+1], kh);
        }
    }
    __syncthreads();
    if (tid<MS && sm_col[tid])
        atomicMax(&g_colbest[(size_t)b*COLS + w*MS + tid], sm_col[tid]);
}

// ---------------- K2: fused compact + gather (per bw block) -----------------
__global__ void __launch_bounds__(512) k_cg(){
    int bw = blockIdx.x; int b = bw/NWAY, w = bw%NWAY;
    int tid = threadIdx.x, lane = tid&31, wid = tid>>5;   // 16 warps
    __shared__ int sel_s[640];                            // cw <= 625
    __shared__ int wsum[16], woff[16], sbase;
    __shared__ float tile[CC][65];
    if (tid==0) sbase=0;
    __syncthreads();
    for (int chunk=0; chunk<5; ++chunk){
        int m = chunk*512 + tid;
        bool flag = false;
        if (m < MU){
            unsigned long long rb = g_rowbest[b*MU+m];
            unsigned col = 0xFFFFFFFFu - (unsigned)(rb & 0xFFFFFFFFu);
            if ((int)(col/MS) == w){
                unsigned long long cb = g_colbest[b*COLS+col];
                unsigned mm = 0xFFFFFFFFu - (unsigned)(cb & 0xFFFFFFFFu);
                flag = (mm == (unsigned)m);
            }
        }
        unsigned bal = __ballot_sync(0xffffffffu, flag);
        if (lane==0) wsum[wid] = __popc(bal);
        __syncthreads();
        if (tid==0){
            int run=sbase;
            #pragma unroll
            for (int i=0;i<16;++i){ woff[i]=run; run+=wsum[i]; }
            sbase=run;
        }
        __syncthreads();
        if (flag){
            int pos = woff[wid] + __popc(bal & ((1u<<lane)-1u));
            sel_s[pos] = m;
        }
        __syncthreads();
    }
    int cw = sbase;
    if (tid==0){
        g_count[bw] = cw;
        atomicMax(&g_L[0], cw);
    }
    // Phase 2: gather
    const float* __restrict__ unl = g_unl_n + (size_t)b*MU*CC;
    float* __restrict__ cat = g_cat_t + (size_t)bw*CC*CATP + MS;
    for (int jb=0; jb<cw; jb+=64){
        int nj = min(64, cw-jb);
        for (int t=wid; t<nj; t+=16){
            int m = sel_s[jb+t];                             // broadcast per warp
            float2 v = ((const float2*)(unl + (size_t)m*CC))[lane];  // 256B coalesced
            tile[2*lane][t]   = v.x;
            tile[2*lane+1][t] = v.y;
        }
        __syncthreads();
        for (int o=tid; o<CC*64; o+=512){
            int c=o>>6, j=o&63;
            if (j<nj) cat[(size_t)c*CATP + jb + j] = tile[c][j];   // coalesced along j
        }
        __syncthreads();
    }
}

// ---------------- K3: query GEMM (f32x2), 128x128 tile, balanced 8x8 map ----
__global__ void __launch_bounds__(256,2) k_qsim(){
    int qt=blockIdx.x, bw=blockIdx.y;
    int b=bw/NWAY, w=bw%NWAY;
    int cw=g_count[bw]; int wl=MS+cw;
    int nct=(wl+127)>>7;
    __shared__ float4 a4[2048];                 // q-rows: [c][32 f4] = 128 rows (32KB)
    __shared__ float4 v4[2048];                 // cols:   [c][32 f4] = 128 cols (32KB)
    int tid=threadIdx.x, lane=tid&31;
    int ci=tid&15, mi=tid>>4;

    const float4* ga=(const float4*)g_q_t + (size_t)b*(CC*QROWP/4) + qt*32;
    #pragma unroll
    for (int t=0;t<8;++t){
        int idx=tid+t*256; int c=idx>>5, x=idx&31;
        a4[idx]=ga[(size_t)c*(QROWP/4)+x];
    }

    unsigned long long rkl[4], rkh[4];
    #pragma unroll
    for (int t=0;t<4;++t){ rkl[t]=0ULL; rkh[t]=0ULL; }

    for (int ct=0; ct<nct; ++ct){
        if (ct) __syncthreads();            // drain previous tile's v4 readers
        const float4* gv=(const float4*)g_cat_t + (size_t)bw*(CC*CATP/4) + ct*32;
        #pragma unroll
        for (int t=0;t<8;++t){
            int idx=tid+t*256; int c=idx>>5, x=idx&31;
            v4[idx]=gv[(size_t)c*(CATP/4)+x];
        }
        __syncthreads();                    // also covers a4 on first iteration

        unsigned long long acc[8][4];
        #pragma unroll
        for (int j=0;j<8;++j)
            #pragma unroll
            for (int t=0;t<4;++t) acc[j][t]=0ULL;

        #pragma unroll 2
        for (int c=0;c<64;++c){
            ulonglong2 bb0=*(const ulonglong2*)&a4[c*32 + mi*2];      // rows mi*8..+3
            ulonglong2 bb1=*(const ulonglong2*)&a4[c*32 + mi*2 + 1];  // rows mi*8+4..+7
            unsigned long long pb[4]={bb0.x,bb0.y,bb1.x,bb1.y};
            float4 x0=v4[c*32 + ci];         // cols ci*4..+3
            float4 x1=v4[c*32 + 16 + ci];    // cols 64+ci*4..+3
            float av[8]={x0.x,x0.y,x0.z,x0.w,x1.x,x1.y,x1.z,x1.w};
            #pragma unroll
            for (int j=0;j<8;++j){
                unsigned long long sa=splat2(av[j]);
                #pragma unroll
                for (int t=0;t<4;++t) fma2(acc[j][t],sa,pb[t]);
            }
        }

        // accumulate per-thread col-max keys across tiles (no shfl here)
        #pragma unroll
        for (int j=0;j<8;++j){
            int coll = (j<4)? ci*4+j : 64+ci*4+(j-4);
            int jg = ct*128 + coll;
            if (jg < wl){
                unsigned gcol = (unsigned)(w*MTOT + jg);
                #pragma unroll
                for (int t=0;t<4;++t){
                    float lo,hi; unpack2(acc[j][t],lo,hi);
                    unsigned long long a1=packkey(lo,gcol);
                    unsigned long long a2=packkey(hi,gcol);
                    if (a1>rkl[t]) rkl[t]=a1;
                    if (a2>rkh[t]) rkh[t]=a2;
                }
            }
        }
    }

    // final reduce over the 16 lanes of each half-warp (covers all 128 cols)
    #pragma unroll
    for (int t=0;t<4;++t){
        unsigned long long kl=rkl[t], kh=rkh[t];
        #pragma unroll
        for (int off=8;off>=1;off>>=1){
            unsigned long long o1=__shfl_xor_sync(0xffffffffu,kl,off);
            unsigned long long o2=__shfl_xor_sync(0xffffffffu,kh,off);
            if (o1>kl) kl=o1;
            if (o2>kh) kh=o2;
        }
        if ((lane&15)==0){
            int r0 = qt*128 + mi*8 + 2*t;
            if (r0<QROWS && kl) atomicMax(&g_rowq[((size_t)b*QROWP + r0)*NWAY + w], kl);
            if (r0+1<QROWS && kh) atomicMax(&g_rowq[((size_t)b*QROWP + r0+1)*NWAY + w], kh);
        }
    }
}

// ---------------- K4: finish = recompute col-argmax + mutual mask + CE ------
__global__ void __launch_bounds__(256) k_fin(const int* __restrict__ qy,
                                             float* __restrict__ out){
    int q=blockIdx.x, b=blockIdx.y;
    int tid=threadIdx.x, lane=tid&31, wp=tid>>5;
    __shared__ float rmx_s[NWAY][32];
    __shared__ unsigned gcol_s[32];
    __shared__ float mask_s[32];
    __shared__ int cnt_s[NWAY+1];
    if (tid<NWAY) cnt_s[tid]=g_count[b*NWAY+tid];
    if (tid==NWAY) cnt_s[NWAY]=g_L[0];
    if (tid<32) mask_s[tid]=0.f;
    __syncthreads();
    // stage 1: per-row (mq) way-maxes and global best column
    if (wp==0 && lane<HWN){
        unsigned long long qb=0ULL;
        #pragma unroll
        for (int w=0;w<NWAY;++w){
            unsigned long long r = g_rowq[((size_t)b*QROWP + q*25 + lane)*NWAY + w];
            int cww=cnt_s[w];
            if (cww < cnt_s[NWAY]){
                // first all-zero pad column of this way: raw cos = 0.0, col id MS+cww
                unsigned long long pk = packkey(0.0f,(unsigned)(w*MTOT+MS+cww));
                if (pk>r) r=pk;
            }
            rmx_s[w][lane]=fmaf(funmap((unsigned)(r>>32)),0.5f,0.5f);
            if (r>qb) qb=r;
        }
        gcol_s[lane]=0xFFFFFFFFu - (unsigned)(qb & 0xFFFFFFFFu);
    }
    __syncthreads();
    // stage 2: per winning column, recompute argmax over mq (bitwise-identical chain)
    for (int t=wp; t<HWN; t+=8){
        unsigned gcol=gcol_s[t];
        int w_=(int)(gcol/MTOT), j_=(int)(gcol%MTOT);
        int amq=0;
        if (j_ < MS + cnt_s[w_]){
            float acc=0.f;
            const float* qp = g_q_t + (size_t)b*CC*QROWP + q*25 + lane;
            const float* cp = g_cat_t + (size_t)(b*NWAY+w_)*CC*CATP + j_;
            if (lane<HWN){
                #pragma unroll
                for (int c=0;c<CC;++c)
                    acc=fmaf(qp[(size_t)c*QROWP], cp[(size_t)c*CATP], acc);
            }
            unsigned long long k = (lane<HWN)? packkey(acc,(unsigned)lane) : 0ULL;
            #pragma unroll
            for (int off=16;off>=1;off>>=1){
                unsigned long long o=__shfl_xor_sync(0xffffffffu,k,off);
                if (o>k) k=o;
            }
            amq = (int)(0xFFFFFFFFu - (unsigned)(k & 0xFFFFFFFFu));
        }
        if (lane==0) mask_s[t] = (amq==t)?1.f:0.f;
    }
    __syncthreads();
    // stage 3: qv + cross-entropy
    if (wp==0){
        float qv[NWAY];
        #pragma unroll
        for (int w=0;w<NWAY;++w){
            float t = (lane<HWN) ? rmx_s[w][lane]*mask_s[lane] : 0.f;
            #pragma unroll
            for (int off=16;off>=1;off>>=1) t += __shfl_xor_sync(0xffffffffu,t,off);
            qv[w]=t;
        }
        if (lane==0){
            int y = qy[b*QQ+q];
            float mx=qv[0];
            #pragma unroll
            for (int w=1;w<NWAY;++w) mx=fmaxf(mx,qv[w]);
            float se=0.f;
            #pragma unroll
            for (int w=0;w<NWAY;++w) se += expf(qv[w]-mx);
            float li = mx + logf(se) - qv[y];
            atomicAdd(out, li*(1.0f/(float)(BB*QQ)));
        }
    }
}

// ---------------- launch ----------------
extern "C" void kernel_launch(void* const* d_in, const int* in_sizes, int n_in,
                              void* d_out, int out_size) {
    const float* sup = nullptr;
    const float* qx  = nullptr;
    const float* ux  = nullptr;
    const int*   qy  = nullptr;
    for (int i=0;i<n_in;++i){
        switch (in_sizes[i]){
            case 160000: sup = (const float*)d_in[i]; break; // support_xf
            case 480000: qx  = (const float*)d_in[i]; break; // query_xf
            case 640000: ux  = (const float*)d_in[i]; break; // unlabeled_xf
            case 300:    qy  = (const int*)d_in[i];   break; // query_y
            default: break;                                  // support_y unused
        }
    }
    float* out = (float*)d_out;
    k_prep<<<816,256>>>(sup, ux, qx, out, out_size);
    k_u2s<<<dim3(20,NWAY,BB),256>>>();
    k_cg<<<BB*NWAY,512>>>();
    k_qsim<<<dim3(15,BB*NWAY),256>>>();
    k_fin<<<dim3(QQ,BB),256>>>(qy, out);
}

// round 16
// speedup vs baseline: 1.2449x; 1.0023x over previous
#include <cuda_runtime.h>
#include <math.h>

#define NWAY 5
#define BB 4
#define CC 64
#define HWN 25
#define MS 125      // K_SHOT * h * w
#define MU 2500     // u * h * w
#define QQ 75
#define COLS 625    // NWAY * MS
#define MTOT 2625   // MS + MU
#define QROWS 1875  // 75 q * 25 rows (packed)
#define QROWP 1920  // padded to 15*128
#define CATP 2688   // padded cat columns (21*128)

// ---------------- scratch (static device allocations only) ----------------
__device__ float g_unl_n[BB*MU*CC];              // [b][m][c]   row-major normalized unlabeled
__device__ float g_q_t[BB*CC*QROWP];             // [b][c][q*25+mq] transposed query (pads zero)
__device__ float g_cat_t[BB*NWAY*CC*CATP];       // [bw][c][j] = [sup(125) | compacted unl(cw)]
__device__ unsigned long long g_rowbest[BB*MU];  // per (b,m): packed (val,col) argmax
__device__ unsigned long long g_colbest[BB*COLS];// per (b,col): packed (val,m) argmax
__device__ unsigned long long g_rowq[BB*QROWP*NWAY]; // per (b,row,w): packed best over cols
__device__ int g_count[BB*NWAY];
__device__ int g_L[1];

// monotone float ordering map (handles negatives exactly)
__device__ __forceinline__ unsigned fmap(float f){
    unsigned b=__float_as_uint(f);
    return (b&0x80000000u)? ~b : (b|0x80000000u);
}
__device__ __forceinline__ float funmap(unsigned u){
    return (u&0x80000000u)? __uint_as_float(u^0x80000000u) : __uint_as_float(~u);
}
// max-value, min-index-on-tie key (matches jnp first-occurrence argmax)
__device__ __forceinline__ unsigned long long packkey(float v, unsigned idx){
    return (((unsigned long long)fmap(v))<<32) | (unsigned long long)(0xFFFFFFFFu - idx);
}
// packed 2xFP32 FMA (Blackwell f32x2)
__device__ __forceinline__ void fma2(unsigned long long& acc, unsigned long long a, unsigned long long b){
    asm("fma.rn.f32x2 %0, %1, %2, %0;" : "+l"(acc) : "l"(a), "l"(b));
}
__device__ __forceinline__ unsigned long long splat2(float x){
    unsigned long long r;
    asm("mov.b64 %0, {%1, %1};" : "=l"(r) : "r"(__float_as_uint(x)));
    return r;
}
__device__ __forceinline__ void unpack2(unsigned long long v, float& lo, float& hi){
    unsigned a,b;
    asm("mov.b64 {%0, %1}, %2;" : "=r"(a), "=r"(b) : "l"(v));
    lo=__uint_as_float(a); hi=__uint_as_float(b);
}

// ---------------- K0: prep = init + all normalizations ----------------
__global__ void __launch_bounds__(256) k_prep(const float* __restrict__ sup,
                                              const float* __restrict__ unl,
                                              const float* __restrict__ qx,
                                              float* __restrict__ out, int out_size){
    int s = blockIdx.x;
    int tid = threadIdx.x;
    if (s >= 800){
        int i = (s-800)*256 + tid;
        const int stride = 16*256;
        for (int t=i;t<BB*MU;t+=stride) g_rowbest[t]=0ULL;
        for (int t=i;t<BB*COLS;t+=stride) g_colbest[t]=0ULL;
        for (int t=i;t<BB*QROWP*NWAY;t+=stride) g_rowq[t]=0ULL;
        // pad rows 1875..1919 of g_q_t
        for (int t=i;t<BB*CC*(QROWP-QROWS);t+=stride){
            int bc=t/(QROWP-QROWS), p=t%(QROWP-QROWS);
            g_q_t[(size_t)bc*QROWP+QROWS+p]=0.f;
        }
        if (i==0) g_L[0]=0;
        for (int t=i;t<out_size;t+=stride) out[t]=0.f;
        return;
    }
    __shared__ __align__(16) float tile[1664];   // 1600 used; tail pad for safe OOB reads
    __shared__ float inv[HWN];
    const float* in;
    if (s<100)      in = sup + (size_t)s*1600;
    else if (s<500) in = unl + (size_t)(s-100)*1600;
    else            in = qx  + (size_t)(s-500)*1600;
    {
        const float4* in4=(const float4*)in;
        float4* t4=(float4*)tile;
        for (int t=tid;t<400;t+=256) t4[t]=in4[t];
    }
    __syncthreads();
    {
        // parallel norm: 8 threads per hw (all 256 threads participate; hw>=25 discarded)
        int hw=tid>>3, k=tid&7;
        float a=0.f;
        #pragma unroll
        for (int c=k;c<CC;c+=8){ float v=tile[c*HWN+hw]; a=fmaf(v,v,a); }
        a += __shfl_xor_sync(0xffffffffu,a,4);
        a += __shfl_xor_sync(0xffffffffu,a,2);
        a += __shfl_xor_sync(0xffffffffu,a,1);
        if (k==0 && hw<HWN) inv[hw]=1.0f/fmaxf(sqrtf(a),1e-12f);
    }
    __syncthreads();
    if (s<100){
        int b=s/25, sk=s%25, w=sk/5, k=sk%5;
        // support columns live ONLY in g_cat_t (cols k*25..k*25+24 of way w)
        float* outc=g_cat_t+(size_t)(b*NWAY+w)*CC*CATP + k*25;
        for (int o=tid;o<1600;o+=256){
            int c=o/HWN,hw=o%HWN;
            outc[(size_t)c*CATP+hw]=tile[o]*inv[hw];
        }
    } else if (s<500){
        int t2=s-100; int b=t2/100,u=t2%100;
        float* outp=g_unl_n+(size_t)(b*MU+u*25)*CC;
        for (int o=tid;o<1600;o+=256){ int hw=o>>6,c=o&63; outp[o]=tile[c*HWN+hw]*inv[hw]; }
    } else {
        int t2=s-500; int b=t2/QQ, q=t2%QQ;
        float* outt=g_q_t+(size_t)b*CC*QROWP + q*25;
        for (int o=tid;o<1600;o+=256){ int c=o/HWN,hw=o%HWN; outt[(size_t)c*QROWP+hw]=tile[o]*inv[hw]; }
    }
}

// ---------------- K1: u2s GEMM (f32x2), per-way column tiles ----------------
// Block = way w (125 cols, padded reads to 128) x 128 m (mt). 256 threads:
// ci=tid&15 -> cols {ci*4..+3, 64+ci*4..+3}; mi=tid>>4 -> m rows mi*8..+7.
// Support tile read from g_cat_t (cols 125..127 garbage, guarded).
// Unlabeled tile staged from row-major g_unl_n via in-kernel transpose
// (rows >= MU zero-filled, reproducing the old zero padding exactly).
__global__ void __launch_bounds__(256,2) k_u2s(){
    __shared__ float4 s4[2048];                  // [c][32 f4] = 128 cols (32KB)
    __shared__ float4 u4[2048];                  // [c][32 f4] = 128 m   (32KB)
    __shared__ unsigned long long sm_col[128];
    int mt=blockIdx.x, w=blockIdx.y, b=blockIdx.z;
    int bw=b*NWAY+w;
    int tid=threadIdx.x, lane=tid&31;
    int ci=tid&15, mi=tid>>4;

    const float4* gs4=(const float4*)g_cat_t + (size_t)bw*(CC*CATP/4);
    #pragma unroll
    for (int t=0;t<8;++t){
        int idx=tid+t*256; int c=idx>>5, x=idx&31;
        s4[idx]=gs4[(size_t)c*(CATP/4)+x];
    }
    // stage u-tile transposed from g_unl_n: 2 threads per m-row
    {
        float* uf=(float*)u4;
        int m=tid>>1, half=tid&1;
        int mg=mt*128+m;
        const float4* src=(const float4*)(g_unl_n + (size_t)(b*MU + (mg<MU?mg:0))*CC) + half*8;
        #pragma unroll
        for (int i=0;i<8;++i){
            float4 v = src[i];
            if (mg>=MU) v=make_float4(0.f,0.f,0.f,0.f);
            int c=half*32+i*4;
            uf[(c+0)*128+m]=v.x;
            uf[(c+1)*128+m]=v.y;
            uf[(c+2)*128+m]=v.z;
            uf[(c+3)*128+m]=v.w;
        }
    }
    if (tid<128) sm_col[tid]=0ULL;
    __syncthreads();

    unsigned long long acc[8][4];                // [col j][row pair t]
    #pragma unroll
    for (int j=0;j<8;++j)
        #pragma unroll
        for (int t=0;t<4;++t) acc[j][t]=0ULL;

    #pragma unroll 2
    for (int c=0;c<64;++c){
        ulonglong2 bb0=*(const ulonglong2*)&u4[c*32 + mi*2];      // m mi*8..+3
        ulonglong2 bb1=*(const ulonglong2*)&u4[c*32 + mi*2 + 1];  // m mi*8+4..+7
        unsigned long long pb[4]={bb0.x,bb0.y,bb1.x,bb1.y};
        float4 x0=s4[c*32 + ci];         // cols ci*4..+3
        float4 x1=s4[c*32 + 16 + ci];    // cols 64+ci*4..+3
        float av[8]={x0.x,x0.y,x0.z,x0.w,x1.x,x1.y,x1.z,x1.w};
        #pragma unroll
        for (int j=0;j<8;++j){
            unsigned long long sa=splat2(av[j]);
            #pragma unroll
            for (int t=0;t<4;++t) fma2(acc[j][t],sa,pb[t]);
        }
    }

    // epilogue: per-col keys (over m) via smem atomics; per-m keys (over cols) in regs
    unsigned long long rkl[4], rkh[4];
    #pragma unroll
    for (int t=0;t<4;++t){ rkl[t]=0ULL; rkh[t]=0ULL; }

    #pragma unroll
    for (int j=0;j<8;++j){
        int coll = (j<4)? ci*4+j : 64+ci*4+(j-4);
        bool vc = coll < MS;                      // cols 125..127 are garbage
        int colj = w*MS + coll;                   // global column id 0..624
        unsigned long long ck=0ULL;
        if (vc){
            #pragma unroll
            for (int t=0;t<4;++t){
                float lo,hi; unpack2(acc[j][t],lo,hi);
                unsigned long long kl=packkey(lo,(unsigned)colj);
                unsigned long long kh=packkey(hi,(unsigned)colj);
                if (kl>rkl[t]) rkl[t]=kl;
                if (kh>rkh[t]) rkh[t]=kh;
                int mglo = mt*128 + mi*8 + 2*t;
                if (mglo<MU){ unsigned long long c1=packkey(lo,(unsigned)mglo); if (c1>ck) ck=c1; }
                if (mglo+1<MU){ unsigned long long c2=packkey(hi,(unsigned)(mglo+1)); if (c2>ck) ck=c2; }
            }
        }
        // combine the two mi halves of this warp (lane ^ 16 has same ci)
        unsigned long long o=__shfl_xor_sync(0xffffffffu,ck,16);
        if (o>ck) ck=o;
        if (lane<16 && ck)
            atomicMax(&sm_col[(j<4)? lane*4+j : 64+lane*4+(j-4)], ck);
    }
    // row (per-m) reduce over the 16 ci lanes (xor <16 keeps mi fixed)
    #pragma unroll
    for (int t=0;t<4;++t){
        unsigned long long kl=rkl[t], kh=rkh[t];
        #pragma unroll
        for (int off=8;off>=1;off>>=1){
            unsigned long long o1=__shfl_xor_sync(0xffffffffu,kl,off);
            unsigned long long o2=__shfl_xor_sync(0xffffffffu,kh,off);
            if (o1>kl) kl=o1;
            if (o2>kh) kh=o2;
        }
        if ((lane&15)==0){
            int r0 = mt*128 + mi*8 + 2*t;
            if (r0<MU && kl) atomicMax(&g_rowbest[(size_t)b*MU+r0], kl);
            if (r0+1<MU && kh) atomicMax(&g_rowbest[(size_t)b*MU+r0+1], kh);
        }
    }
    __syncthreads();
    if (tid<MS && sm_col[tid])
        atomicMax(&g_colbest[(size_t)b*COLS + w*MS + tid], sm_col[tid]);
}

// ---------------- K2: fused compact + gather (per bw block) -----------------
__global__ void __launch_bounds__(512) k_cg(){
    int bw = blockIdx.x; int b = bw/NWAY, w = bw%NWAY;
    int tid = threadIdx.x, lane = tid&31, wid = tid>>5;   // 16 warps
    __shared__ int sel_s[640];                            // cw <= 625
    __shared__ int wsum[16], woff[16], sbase;
    __shared__ float tile[CC][65];
    if (tid==0) sbase=0;
    __syncthreads();
    for (int chunk=0; chunk<5; ++chunk){
        int m = chunk*512 + tid;
        bool flag = false;
        if (m < MU){
            unsigned long long rb = g_rowbest[b*MU+m];
            unsigned col = 0xFFFFFFFFu - (unsigned)(rb & 0xFFFFFFFFu);
            if ((int)(col/MS) == w){
                unsigned long long cb = g_colbest[b*COLS+col];
                unsigned mm = 0xFFFFFFFFu - (unsigned)(cb & 0xFFFFFFFFu);
                flag = (mm == (unsigned)m);
            }
        }
        unsigned bal = __ballot_sync(0xffffffffu, flag);
        if (lane==0) wsum[wid] = __popc(bal);
        __syncthreads();
        if (tid==0){
            int run=sbase;
            #pragma unroll
            for (int i=0;i<16;++i){ woff[i]=run; run+=wsum[i]; }
            sbase=run;
        }
        __syncthreads();
        if (flag){
            int pos = woff[wid] + __popc(bal & ((1u<<lane)-1u));
            sel_s[pos] = m;
        }
        __syncthreads();
    }
    int cw = sbase;
    if (tid==0){
        g_count[bw] = cw;
        atomicMax(&g_L[0], cw);
    }
    // Phase 2: gather
    const float* __restrict__ unl = g_unl_n + (size_t)b*MU*CC;
    float* __restrict__ cat = g_cat_t + (size_t)bw*CC*CATP + MS;
    for (int jb=0; jb<cw; jb+=64){
        int nj = min(64, cw-jb);
        for (int t=wid; t<nj; t+=16){
            int m = sel_s[jb+t];                             // broadcast per warp
            float2 v = ((const float2*)(unl + (size_t)m*CC))[lane];  // 256B coalesced
            tile[2*lane][t]   = v.x;
            tile[2*lane+1][t] = v.y;
        }
        __syncthreads();
        for (int o=tid; o<CC*64; o+=512){
            int c=o>>6, j=o&63;
            if (j<nj) cat[(size_t)c*CATP + jb + j] = tile[c][j];   // coalesced along j
        }
        __syncthreads();
    }
}

// ---------------- K3: query GEMM (f32x2), 128x128 tile, balanced 8x8 map ----
__global__ void __launch_bounds__(256,2) k_qsim(){
    int qt=blockIdx.x, bw=blockIdx.y;
    int b=bw/NWAY, w=bw%NWAY;
    int cw=g_count[bw]; int wl=MS+cw;
    int nct=(wl+127)>>7;
    __shared__ float4 a4[2048];                 // q-rows: [c][32 f4] = 128 rows (32KB)
    __shared__ float4 v4[2048];                 // cols:   [c][32 f4] = 128 cols (32KB)
    int tid=threadIdx.x, lane=tid&31;
    int ci=tid&15, mi=tid>>4;

    const float4* ga=(const float4*)g_q_t + (size_t)b*(CC*QROWP/4) + qt*32;
    #pragma unroll
    for (int t=0;t<8;++t){
        int idx=tid+t*256; int c=idx>>5, x=idx&31;
        a4[idx]=ga[(size_t)c*(QROWP/4)+x];
    }

    unsigned long long rkl[4], rkh[4];
    #pragma unroll
    for (int t=0;t<4;++t){ rkl[t]=0ULL; rkh[t]=0ULL; }

    for (int ct=0; ct<nct; ++ct){
        if (ct) __syncthreads();            // drain previous tile's v4 readers
        const float4* gv=(const float4*)g_cat_t + (size_t)bw*(CC*CATP/4) + ct*32;
        #pragma unroll
        for (int t=0;t<8;++t){
            int idx=tid+t*256; int c=idx>>5, x=idx&31;
            v4[idx]=gv[(size_t)c*(CATP/4)+x];
        }
        __syncthreads();                    // also covers a4 on first iteration

        unsigned long long acc[8][4];
        #pragma unroll
        for (int j=0;j<8;++j)
            #pragma unroll
            for (int t=0;t<4;++t) acc[j][t]=0ULL;

        #pragma unroll 2
        for (int c=0;c<64;++c){
            ulonglong2 bb0=*(const ulonglong2*)&a4[c*32 + mi*2];      // rows mi*8..+3
            ulonglong2 bb1=*(const ulonglong2*)&a4[c*32 + mi*2 + 1];  // rows mi*8+4..+7
            unsigned long long pb[4]={bb0.x,bb0.y,bb1.x,bb1.y};
            float4 x0=v4[c*32 + ci];         // cols ci*4..+3
            float4 x1=v4[c*32 + 16 + ci];    // cols 64+ci*4..+3
            float av[8]={x0.x,x0.y,x0.z,x0.w,x1.x,x1.y,x1.z,x1.w};
            #pragma unroll
            for (int j=0;j<8;++j){
                unsigned long long sa=splat2(av[j]);
                #pragma unroll
                for (int t=0;t<4;++t) fma2(acc[j][t],sa,pb[t]);
            }
        }

        // accumulate per-thread col-max keys across tiles (no shfl here)
        #pragma unroll
        for (int j=0;j<8;++j){
            int coll = (j<4)? ci*4+j : 64+ci*4+(j-4);
            int jg = ct*128 + coll;
            if (jg < wl){
                unsigned gcol = (unsigned)(w*MTOT + jg);
                #pragma unroll
                for (int t=0;t<4;++t){
                    float lo,hi; unpack2(acc[j][t],lo,hi);
                    unsigned long long a1=packkey(lo,gcol);
                    unsigned long long a2=packkey(hi,gcol);
                    if (a1>rkl[t]) rkl[t]=a1;
                    if (a2>rkh[t]) rkh[t]=a2;
                }
            }
        }
    }

    // final reduce over the 16 lanes of each half-warp (covers all 128 cols)
    #pragma unroll
    for (int t=0;t<4;++t){
        unsigned long long kl=rkl[t], kh=rkh[t];
        #pragma unroll
        for (int off=8;off>=1;off>>=1){
            unsigned long long o1=__shfl_xor_sync(0xffffffffu,kl,off);
            unsigned long long o2=__shfl_xor_sync(0xffffffffu,kh,off);
            if (o1>kl) kl=o1;
            if (o2>kh) kh=o2;
        }
        if ((lane&15)==0){
            int r0 = qt*128 + mi*8 + 2*t;
            if (r0<QROWS && kl) atomicMax(&g_rowq[((size_t)b*QROWP + r0)*NWAY + w], kl);
            if (r0+1<QROWS && kh) atomicMax(&g_rowq[((size_t)b*QROWP + r0+1)*NWAY + w], kh);
        }
    }
}

// ---------------- K4: finish = recompute col-argmax + mutual mask + CE ------
__global__ void __launch_bounds__(256) k_fin(const int* __restrict__ qy,
                                             float* __restrict__ out){
    int q=blockIdx.x, b=blockIdx.y;
    int tid=threadIdx.x, lane=tid&31, wp=tid>>5;
    __shared__ float rmx_s[NWAY][32];
    __shared__ unsigned gcol_s[32];
    __shared__ float mask_s[32];
    __shared__ int cnt_s[NWAY+1];
    if (tid<NWAY) cnt_s[tid]=g_count[b*NWAY+tid];
    if (tid==NWAY) cnt_s[NWAY]=g_L[0];
    if (tid<32) mask_s[tid]=0.f;
    __syncthreads();
    // stage 1: per-row (mq) way-maxes and global best column
    if (wp==0 && lane<HWN){
        unsigned long long qb=0ULL;
        #pragma unroll
        for (int w=0;w<NWAY;++w){
            unsigned long long r = g_rowq[((size_t)b*QROWP + q*25 + lane)*NWAY + w];
            int cww=cnt_s[w];
            if (cww < cnt_s[NWAY]){
                // first all-zero pad column of this way: raw cos = 0.0, col id MS+cww
                unsigned long long pk = packkey(0.0f,(unsigned)(w*MTOT+MS+cww));
                if (pk>r) r=pk;
            }
            rmx_s[w][lane]=fmaf(funmap((unsigned)(r>>32)),0.5f,0.5f);
            if (r>qb) qb=r;
        }
        gcol_s[lane]=0xFFFFFFFFu - (unsigned)(qb & 0xFFFFFFFFu);
    }
    __syncthreads();
    // stage 2: per winning column, recompute argmax over mq (bitwise-identical chain)
    for (int t=wp; t<HWN; t+=8){
        unsigned gcol=gcol_s[t];
        int w_=(int)(gcol/MTOT), j_=(int)(gcol%MTOT);
        int amq=0;
        if (j_ < MS + cnt_s[w_]){
            float acc=0.f;
            const float* qp = g_q_t + (size_t)b*CC*QROWP + q*25 + lane;
            const float* cp = g_cat_t + (size_t)(b*NWAY+w_)*CC*CATP + j_;
            if (lane<HWN){
                #pragma unroll
                for (int c=0;c<CC;++c)
                    acc=fmaf(qp[(size_t)c*QROWP], cp[(size_t)c*CATP], acc);
            }
            unsigned long long k = (lane<HWN)? packkey(acc,(unsigned)lane) : 0ULL;
            #pragma unroll
            for (int off=16;off>=1;off>>=1){
                unsigned long long o=__shfl_xor_sync(0xffffffffu,k,off);
                if (o>k) k=o;
            }
            amq = (int)(0xFFFFFFFFu - (unsigned)(k & 0xFFFFFFFFu));
        }
        if (lane==0) mask_s[t] = (amq==t)?1.f:0.f;
    }
    __syncthreads();
    // stage 3: qv + cross-entropy
    if (wp==0){
        float qv[NWAY];
        #pragma unroll
        for (int w=0;w<NWAY;++w){
            float t = (lane<HWN) ? rmx_s[w][lane]*mask_s[lane] : 0.f;
            #pragma unroll
            for (int off=16;off>=1;off>>=1) t += __shfl_xor_sync(0xffffffffu,t,off);
            qv[w]=t;
        }
        if (lane==0){
            int y = qy[b*QQ+q];
            float mx=qv[0];
            #pragma unroll
            for (int w=1;w<NWAY;++w) mx=fmaxf(mx,qv[w]);
            float se=0.f;
            #pragma unroll
            for (int w=0;w<NWAY;++w) se += expf(qv[w]-mx);
            float li = mx + logf(se) - qv[y];
            atomicAdd(out, li*(1.0f/(float)(BB*QQ)));
        }
    }
}

// ---------------- launch ----------------
extern "C" void kernel_launch(void* const* d_in, const int* in_sizes, int n_in,
                              void* d_out, int out_size) {
    const float* sup = nullptr;
    const float* qx  = nullptr;
    const float* ux  = nullptr;
    const int*   qy  = nullptr;
    for (int i=0;i<n_in;++i){
        switch (in_sizes[i]){
            case 160000: sup = (const float*)d_in[i]; break; // support_xf
            case 480000: qx  = (const float*)d_in[i]; break; // query_xf
            case 640000: ux  = (const float*)d_in[i]; break; // unlabeled_xf
            case 300:    qy  = (const int*)d_in[i];   break; // query_y
            default: break;                                  // support_y unused
        }
    }
    float* out = (float*)d_out;
    k_prep<<<816,256>>>(sup, ux, qx, out, out_size);
    k_u2s<<<dim3(20,NWAY,BB),256>>>();
    k_cg<<<BB*NWAY,512>>>();
    k_qsim<<<dim3(15,BB*NWAY),256>>>();
    k_fin<<<dim3(QQ,BB),256>>>(qy, out);
}